// round 4
// baseline (speedup 1.0000x reference)
#include <cuda_runtime.h>
#include <cstdint>

#define EE 8
#define TT 2048
#define DD 1024
#define HH 4096

// ---------------- device scratch ----------------------------------------------
__device__ float g_w1t[(size_t)EE * HH * DD]; // w_c_fc^T  [E][H][D], tf32-rounded
__device__ float g_wgt[(size_t)EE * HH * DD]; // w_gate^T  [E][H][D]
__device__ float g_w2t[(size_t)EE * DD * HH]; // w_c_proj^T[E][D][H]
__device__ float g_xr [(size_t)EE * TT * DD]; // x tf32-rounded
__device__ float g_og [(size_t)EE * TT * HH]; // gated hidden, tf32-rounded

// ---------------- helpers ------------------------------------------------------
__device__ __forceinline__ uint32_t smem_u32(const void* p) {
    uint32_t a;
    asm("{ .reg .u64 t; cvta.to.shared.u64 t, %1; cvt.u32.u64 %0, t; }" : "=r"(a) : "l"(p));
    return a;
}
__device__ __forceinline__ uint32_t swz128(uint32_t o) { return o ^ ((o >> 3) & 0x70); }

__device__ __forceinline__ float tf32f(float x) {
    uint32_t r; asm("cvt.rna.tf32.f32 %0, %1;" : "=r"(r) : "f"(x));
    return __uint_as_float(r);
}
__device__ __forceinline__ void cp_async16(uint32_t dst, const float* src) {
    asm volatile("cp.async.cg.shared.global [%0], [%1], 16;" :: "r"(dst), "l"(src));
}
#define CP_COMMIT() asm volatile("cp.async.commit_group;" ::: "memory")
#define CP_WAIT2()  asm volatile("cp.async.wait_group 2;" ::: "memory")

// tf32 m16n8k8: D = A@B + D  (A row-major 16x8, B col-major 8x8)
__device__ __forceinline__ void mma8(float* c, uint32_t a0, uint32_t a1, uint32_t a2,
                                     uint32_t a3, uint32_t b0, uint32_t b1) {
    asm volatile(
        "mma.sync.aligned.m16n8k8.row.col.f32.tf32.tf32.f32 "
        "{%0,%1,%2,%3}, {%4,%5,%6,%7}, {%8,%9}, {%0,%1,%2,%3};"
        : "+f"(c[0]), "+f"(c[1]), "+f"(c[2]), "+f"(c[3])
        : "r"(a0), "r"(a1), "r"(a2), "r"(a3), "r"(b0), "r"(b1));
}
__device__ __forceinline__ float my_silu(float g) {
    return g / (1.0f + __expf(-g));
}

// ---------------- prep kernels --------------------------------------------------
__global__ void round_x_kernel(const float* __restrict__ x) {
    size_t i = ((size_t)blockIdx.x * blockDim.x + threadIdx.x) * 4;
    float4 v = *reinterpret_cast<const float4*>(x + i);
    v.x = tf32f(v.x); v.y = tf32f(v.y); v.z = tf32f(v.z); v.w = tf32f(v.w);
    *reinterpret_cast<float4*>(g_xr + i) = v;
}

// out[e][c][r] = tf32(in[e][r][c]);  which: 0=w1t, 1=wgt, 2=w2t
__global__ void transpose_round_kernel(const float* __restrict__ in, int which, int R, int C) {
    __shared__ float t[32][33];
    float* out = (which == 0) ? g_w1t : (which == 1) ? g_wgt : g_w2t;
    const int e = blockIdx.z;
    const float* ip = in + (size_t)e * R * C;
    float* op = out + (size_t)e * R * C;
    const int c0 = blockIdx.x * 32, r0 = blockIdx.y * 32;
    const int tx = threadIdx.x, ty = threadIdx.y;
#pragma unroll
    for (int i = 0; i < 4; i++)
        t[ty + 8 * i][tx] = ip[(size_t)(r0 + ty + 8 * i) * C + c0 + tx];
    __syncthreads();
#pragma unroll
    for (int i = 0; i < 4; i++)
        op[(size_t)(c0 + ty + 8 * i) * R + r0 + tx] = tf32f(t[tx][ty + 8 * i]);
}

// =================================================================================
// GEMM1 fused: h = x@w1+b1 ; g = silu(x@wg+bg) ; og = tf32(h*g)
// Tile 128x128 (dual output), Kc=32, 512 threads (16 warps, 4x4), 3-stage cp.async.
// Stage smem = A 16KB + B1 16KB + B2 16KB = 48KB; total 144KB.
// =================================================================================
#define G1_STGF 12288          // floats per stage
#define G1_SMEM (3 * 48 * 1024)

__global__ void __launch_bounds__(512, 1)
gemm1_kernel(const float* __restrict__ bias1, const float* __restrict__ biasg) {
    extern __shared__ float sm[];
    const uint32_t sb = smem_u32(sm);
    const int tid = threadIdx.x, wid = tid >> 5, lane = tid & 31;
    const int gid = lane >> 2, tig = lane & 3;
    const int wr = wid >> 2, wc = wid & 3;          // 4x4 warp grid
    const int bid = blockIdx.x;
    const int e = bid >> 9, mt = (bid >> 5) & 15, nt = bid & 31;

    const float* aB  = g_xr  + ((size_t)e * TT + (size_t)mt * 128) * DD;
    const float* b1B = g_w1t + ((size_t)e * HH + (size_t)nt * 128) * DD;
    const float* b2B = g_wgt + ((size_t)e * HH + (size_t)nt * 128) * DD;

    float ah[2][4][4] = {}, ag[2][4][4] = {};

    auto fill = [&](int s) {
        const int buf = s - (s / 3) * 3;
        const uint32_t base = sb + (uint32_t)buf * (G1_STGF * 4);
        const float* a  = aB  + s * 32;
        const float* b1 = b1B + s * 32;
        const float* b2 = b2B + s * 32;
#pragma unroll
        for (int c = 0; c < 2; c++) {
            int idx = c * 512 + tid;                 // 1024 x 16B per sub-tile
            uint32_t d = swz128((uint32_t)idx * 16);
            size_t off = (size_t)(idx >> 3) * DD + (idx & 7) * 4;
            cp_async16(base + d,                a  + off);
            cp_async16(base + 16384 + d,        b1 + off);
            cp_async16(base + 32768 + d,        b2 + off);
        }
    };

    fill(0); CP_COMMIT();
    fill(1); CP_COMMIT();

#pragma unroll 1
    for (int s = 0; s < 32; s++) {                   // K = 1024 / 32
        __syncthreads();
        if (s + 2 < 32) fill(s + 2);
        CP_COMMIT();
        CP_WAIT2();
        __syncthreads();

        const int buf = s - (s / 3) * 3;
        const float* As  = sm + buf * G1_STGF;
        const float* B1s = As + 4096;
        const float* B2s = As + 8192;

#pragma unroll
        for (int ks = 0; ks < 4; ks++) {
            uint32_t af[2][4], bf1[4][2], bf2[4][2];
#pragma unroll
            for (int i = 0; i < 2; i++) {
                int r = wr * 32 + i * 16 + gid;
                af[i][0] = __float_as_uint(As[swz128((uint32_t)(r * 128 + (ks * 8 + tig) * 4)) >> 2]);
                af[i][1] = __float_as_uint(As[swz128((uint32_t)((r + 8) * 128 + (ks * 8 + tig) * 4)) >> 2]);
                af[i][2] = __float_as_uint(As[swz128((uint32_t)(r * 128 + (ks * 8 + tig + 4) * 4)) >> 2]);
                af[i][3] = __float_as_uint(As[swz128((uint32_t)((r + 8) * 128 + (ks * 8 + tig + 4) * 4)) >> 2]);
            }
#pragma unroll
            for (int j = 0; j < 4; j++) {
                int n = wc * 32 + j * 8 + gid;
                uint32_t o0 = swz128((uint32_t)(n * 128 + (ks * 8 + tig) * 4)) >> 2;
                uint32_t o1 = swz128((uint32_t)(n * 128 + (ks * 8 + tig + 4) * 4)) >> 2;
                bf1[j][0] = __float_as_uint(B1s[o0]);
                bf1[j][1] = __float_as_uint(B1s[o1]);
                bf2[j][0] = __float_as_uint(B2s[o0]);
                bf2[j][1] = __float_as_uint(B2s[o1]);
            }
#pragma unroll
            for (int i = 0; i < 2; i++)
#pragma unroll
                for (int j = 0; j < 4; j++) {
                    mma8(ah[i][j], af[i][0], af[i][1], af[i][2], af[i][3], bf1[j][0], bf1[j][1]);
                    mma8(ag[i][j], af[i][0], af[i][1], af[i][2], af[i][3], bf2[j][0], bf2[j][1]);
                }
        }
    }

    // epilogue: og = tf32( (h + b1) * silu(g + bg) )
    const int m0 = mt * 128 + wr * 32;
    const int n0 = nt * 128 + wc * 32;
    const float* bp1 = bias1 + (size_t)e * HH;
    const float* bpg = biasg + (size_t)e * HH;
#pragma unroll
    for (int i = 0; i < 2; i++)
#pragma unroll
        for (int j = 0; j < 4; j++) {
            int col = n0 + j * 8 + 2 * tig;
            float bh0 = bp1[col], bh1 = bp1[col + 1];
            float bg0 = bpg[col], bg1 = bpg[col + 1];
#pragma unroll
            for (int half = 0; half < 2; half++) {
                int row = m0 + i * 16 + gid + half * 8;
                float h0 = ah[i][j][2 * half]     + bh0;
                float h1 = ah[i][j][2 * half + 1] + bh1;
                float g0 = ag[i][j][2 * half]     + bg0;
                float g1 = ag[i][j][2 * half + 1] + bg1;
                float2 v = make_float2(tf32f(h0 * my_silu(g0)), tf32f(h1 * my_silu(g1)));
                *reinterpret_cast<float2*>(g_og + ((size_t)e * TT + row) * HH + col) = v;
            }
        }
}

// =================================================================================
// GEMM2: out = og @ w2 + b2.  Tile 128x128, Kc=32, 256 threads (8 warps, 4x2),
// 3-stage cp.async.  Stage smem = A 16KB + B 16KB = 32KB; total 96KB (occ 2).
// =================================================================================
#define G2_STGF 8192
#define G2_SMEM (3 * 32 * 1024)

__global__ void __launch_bounds__(256)
gemm2_kernel(const float* __restrict__ bias2, float* __restrict__ out) {
    extern __shared__ float sm[];
    const uint32_t sb = smem_u32(sm);
    const int tid = threadIdx.x, wid = tid >> 5, lane = tid & 31;
    const int gid = lane >> 2, tig = lane & 3;
    const int wr = wid >> 1, wc = wid & 1;           // 4x2 warp grid, warp tile 32x64
    const int bid = blockIdx.x;
    const int e = bid >> 7, mt = (bid >> 3) & 15, nt = bid & 7;

    const float* aB = g_og  + ((size_t)e * TT + (size_t)mt * 128) * HH;
    const float* bB = g_w2t + ((size_t)e * DD + (size_t)nt * 128) * HH;

    float acc[2][8][4] = {};

    auto fill = [&](int s) {
        const int buf = s - (s / 3) * 3;
        const uint32_t base = sb + (uint32_t)buf * (G2_STGF * 4);
        const float* a = aB + s * 32;
        const float* b = bB + s * 32;
#pragma unroll
        for (int c = 0; c < 4; c++) {
            int idx = c * 256 + tid;
            uint32_t d = swz128((uint32_t)idx * 16);
            size_t off = (size_t)(idx >> 3) * HH + (idx & 7) * 4;
            cp_async16(base + d,         a + off);
            cp_async16(base + 16384 + d, b + off);
        }
    };

    fill(0); CP_COMMIT();
    fill(1); CP_COMMIT();

#pragma unroll 1
    for (int s = 0; s < 128; s++) {                  // K = 4096 / 32
        __syncthreads();
        if (s + 2 < 128) fill(s + 2);
        CP_COMMIT();
        CP_WAIT2();
        __syncthreads();

        const int buf = s - (s / 3) * 3;
        const float* As = sm + buf * G2_STGF;
        const float* Bs = As + 4096;

#pragma unroll
        for (int ks = 0; ks < 4; ks++) {
            uint32_t af[2][4], bf[8][2];
#pragma unroll
            for (int i = 0; i < 2; i++) {
                int r = wr * 32 + i * 16 + gid;
                af[i][0] = __float_as_uint(As[swz128((uint32_t)(r * 128 + (ks * 8 + tig) * 4)) >> 2]);
                af[i][1] = __float_as_uint(As[swz128((uint32_t)((r + 8) * 128 + (ks * 8 + tig) * 4)) >> 2]);
                af[i][2] = __float_as_uint(As[swz128((uint32_t)(r * 128 + (ks * 8 + tig + 4) * 4)) >> 2]);
                af[i][3] = __float_as_uint(As[swz128((uint32_t)((r + 8) * 128 + (ks * 8 + tig + 4) * 4)) >> 2]);
            }
#pragma unroll
            for (int j = 0; j < 8; j++) {
                int n = wc * 64 + j * 8 + gid;
                bf[j][0] = __float_as_uint(Bs[swz128((uint32_t)(n * 128 + (ks * 8 + tig) * 4)) >> 2]);
                bf[j][1] = __float_as_uint(Bs[swz128((uint32_t)(n * 128 + (ks * 8 + tig + 4) * 4)) >> 2]);
            }
#pragma unroll
            for (int i = 0; i < 2; i++)
#pragma unroll
                for (int j = 0; j < 8; j++)
                    mma8(acc[i][j], af[i][0], af[i][1], af[i][2], af[i][3], bf[j][0], bf[j][1]);
        }
    }

    const int m0 = mt * 128 + wr * 32;
    const int n0 = nt * 128 + wc * 64;
    const float* bp2 = bias2 + (size_t)e * DD;
#pragma unroll
    for (int i = 0; i < 2; i++)
#pragma unroll
        for (int j = 0; j < 8; j++) {
            int col = n0 + j * 8 + 2 * tig;
            float b0 = bp2[col], b1 = bp2[col + 1];
#pragma unroll
            for (int half = 0; half < 2; half++) {
                int row = m0 + i * 16 + gid + half * 8;
                float2 v = make_float2(acc[i][j][2 * half] + b0, acc[i][j][2 * half + 1] + b1);
                *reinterpret_cast<float2*>(out + ((size_t)e * TT + row) * DD + col) = v;
            }
        }
}

// ---------------- launch ---------------------------------------------------------
extern "C" void kernel_launch(void* const* d_in, const int* in_sizes, int n_in,
                              void* d_out, int out_size) {
    const float* x  = (const float*)d_in[0];
    const float* w1 = (const float*)d_in[1];
    const float* b1 = (const float*)d_in[2];
    const float* wg = (const float*)d_in[3];
    const float* bg = (const float*)d_in[4];
    const float* w2 = (const float*)d_in[5];
    const float* b2 = (const float*)d_in[6];
    float* out = (float*)d_out;

    cudaFuncSetAttribute(gemm1_kernel, cudaFuncAttributeMaxDynamicSharedMemorySize, G1_SMEM);
    cudaFuncSetAttribute(gemm2_kernel, cudaFuncAttributeMaxDynamicSharedMemorySize, G2_SMEM);

    round_x_kernel<<<(EE * TT * DD) / (256 * 4), 256>>>(x);
    dim3 tpb(32, 8);
    transpose_round_kernel<<<dim3(HH / 32, DD / 32, EE), tpb>>>(w1, 0, DD, HH);
    transpose_round_kernel<<<dim3(HH / 32, DD / 32, EE), tpb>>>(wg, 1, DD, HH);
    transpose_round_kernel<<<dim3(DD / 32, HH / 32, EE), tpb>>>(w2, 2, HH, DD);

    gemm1_kernel<<<EE * 16 * 32, 512, G1_SMEM>>>(b1, bg);   // 4096 CTAs
    gemm2_kernel<<<EE * 16 * 8, 256, G2_SMEM>>>(b2, out);   // 1024 CTAs
}

// round 5
// speedup vs baseline: 1.0813x; 1.0813x over previous
#include <cuda_runtime.h>
#include <cstdint>

#define EE 8
#define TT 2048
#define DD 1024
#define HH 4096

// ---------------- device scratch ----------------------------------------------
__device__ float g_w1t[(size_t)EE * HH * DD]; // w_c_fc^T  [E][H][D], tf32-rounded
__device__ float g_wgt[(size_t)EE * HH * DD]; // w_gate^T  [E][H][D]
__device__ float g_w2t[(size_t)EE * DD * HH]; // w_c_proj^T[E][D][H]
__device__ float g_xr [(size_t)EE * TT * DD]; // x tf32-rounded
__device__ float g_og [(size_t)EE * TT * HH]; // gated hidden, tf32-rounded

// ---------------- helpers ------------------------------------------------------
__device__ __forceinline__ uint32_t smem_u32(const void* p) {
    uint32_t a;
    asm("{ .reg .u64 t; cvta.to.shared.u64 t, %1; cvt.u32.u64 %0, t; }" : "=r"(a) : "l"(p));
    return a;
}
__device__ __forceinline__ uint32_t swz128(uint32_t o) { return o ^ ((o >> 3) & 0x70); }

__device__ __forceinline__ float tf32f(float x) {
    uint32_t r; asm("cvt.rna.tf32.f32 %0, %1;" : "=r"(r) : "f"(x));
    return __uint_as_float(r);
}
__device__ __forceinline__ void cp_async16(uint32_t dst, const float* src) {
    asm volatile("cp.async.cg.shared.global [%0], [%1], 16;" :: "r"(dst), "l"(src));
}
#define CP_COMMIT() asm volatile("cp.async.commit_group;" ::: "memory")

__device__ __forceinline__ void cp_wait_tail(int s, int ns) {
    if (s + 2 < ns)      asm volatile("cp.async.wait_group 2;" ::: "memory");
    else if (s + 1 < ns) asm volatile("cp.async.wait_group 1;" ::: "memory");
    else                 asm volatile("cp.async.wait_group 0;" ::: "memory");
}

// tf32 m16n8k8: D = A@B + D  (A row-major 16x8, B col-major 8x8)
__device__ __forceinline__ void mma8(float* c, const uint32_t* a, const uint32_t* b) {
    asm volatile(
        "mma.sync.aligned.m16n8k8.row.col.f32.tf32.tf32.f32 "
        "{%0,%1,%2,%3}, {%4,%5,%6,%7}, {%8,%9}, {%0,%1,%2,%3};"
        : "+f"(c[0]), "+f"(c[1]), "+f"(c[2]), "+f"(c[3])
        : "r"(a[0]), "r"(a[1]), "r"(a[2]), "r"(a[3]), "r"(b[0]), "r"(b[1]));
}
__device__ __forceinline__ float my_silu(float g) { return g / (1.0f + __expf(-g)); }

// ---------------- prep kernels --------------------------------------------------
__global__ void round_x_kernel(const float* __restrict__ x) {
    size_t i = ((size_t)blockIdx.x * blockDim.x + threadIdx.x) * 4;
    float4 v = *reinterpret_cast<const float4*>(x + i);
    v.x = tf32f(v.x); v.y = tf32f(v.y); v.z = tf32f(v.z); v.w = tf32f(v.w);
    *reinterpret_cast<float4*>(g_xr + i) = v;
}

// out[e][c][r] = tf32(in[e][r][c]);  which: 0=w1t, 1=wgt, 2=w2t
__global__ void transpose_round_kernel(const float* __restrict__ in, int which, int R, int C) {
    __shared__ float t[32][33];
    float* out = (which == 0) ? g_w1t : (which == 1) ? g_wgt : g_w2t;
    const int e = blockIdx.z;
    const float* ip = in + (size_t)e * R * C;
    float* op = out + (size_t)e * R * C;
    const int c0 = blockIdx.x * 32, r0 = blockIdx.y * 32;
    const int tx = threadIdx.x, ty = threadIdx.y;
#pragma unroll
    for (int i = 0; i < 4; i++)
        t[ty + 8 * i][tx] = ip[(size_t)(r0 + ty + 8 * i) * C + c0 + tx];
    __syncthreads();
#pragma unroll
    for (int i = 0; i < 4; i++)
        op[(size_t)(c0 + ty + 8 * i) * R + r0 + tx] = tf32f(t[tx][ty + 8 * i]);
}

// =================================================================================
// GEMM1 fused: h = x@w1+b1 ; g = silu(x@wg+bg) ; og = tf32(h*g)
// CTA tile 128x128, dual output plane. 256 threads = 8 warps (2x4), warp 64x32.
// Kc=32, 4-stage cp.async (48KB/stage, 192KB total), 1 sync per stage.
// Regs/thread ~220 (acc 128 + dbl frags 64) — fits 255 @ 256thr, NO SPILLS.
// =================================================================================
#define STGF 12288            // floats per 48KB stage
#define G_SMEM (4 * 48 * 1024)

__global__ void __launch_bounds__(256, 1)
gemm1_kernel(const float* __restrict__ bias1, const float* __restrict__ biasg) {
    extern __shared__ float sm[];
    const uint32_t sb = smem_u32(sm);
    const int tid = threadIdx.x, wid = tid >> 5, lane = tid & 31;
    const int gid = lane >> 2, tig = lane & 3;
    const int wr = wid >> 2, wc = wid & 3;          // 2x4 warp grid, warp tile 64x32
    const int bid = blockIdx.x;
    const int e = bid >> 9, mt = (bid >> 5) & 15, nt = bid & 31;

    const float* aB  = g_xr  + ((size_t)e * TT + (size_t)mt * 128) * DD;
    const float* b1B = g_w1t + ((size_t)e * HH + (size_t)nt * 128) * DD;
    const float* b2B = g_wgt + ((size_t)e * HH + (size_t)nt * 128) * DD;

    float ah[4][4][4] = {}, ag[4][4][4] = {};       // 128 acc regs

    auto fill = [&](int s) {
        const uint32_t base = sb + (uint32_t)(s & 3) * (STGF * 4);
        const float* a  = aB  + s * 32;
        const float* b1 = b1B + s * 32;
        const float* b2 = b2B + s * 32;
#pragma unroll
        for (int c = 0; c < 4; c++) {               // 1024 chunks per 16KB sub-tile
            int idx = c * 256 + tid;
            uint32_t d = swz128((uint32_t)idx * 16);
            size_t off = (size_t)(idx >> 3) * DD + (idx & 7) * 4;
            cp_async16(base + d,         a  + off);
            cp_async16(base + 16384 + d, b1 + off);
            cp_async16(base + 32768 + d, b2 + off);
        }
        CP_COMMIT();
    };

    fill(0); fill(1); fill(2);

#pragma unroll 1
    for (int s = 0; s < 32; s++) {                  // K = 1024 / 32
        cp_wait_tail(s, 32);
        __syncthreads();                            // all warps done with stage s-1
        if (s + 3 < 32) fill(s + 3);

        const float* As  = sm + (s & 3) * STGF;
        const float* B1s = As + 4096;
        const float* B2s = As + 8192;

        uint32_t af[2][4][4], bf1[2][4][2], bf2[2][4][2];

        auto ldfr = [&](int ks, int pb) {
#pragma unroll
            for (int i = 0; i < 4; i++) {
                int r = wr * 64 + i * 16 + gid;
                af[pb][i][0] = __float_as_uint(As[swz128((uint32_t)(r * 128 + (ks * 8 + tig) * 4)) >> 2]);
                af[pb][i][1] = __float_as_uint(As[swz128((uint32_t)((r + 8) * 128 + (ks * 8 + tig) * 4)) >> 2]);
                af[pb][i][2] = __float_as_uint(As[swz128((uint32_t)(r * 128 + (ks * 8 + tig + 4) * 4)) >> 2]);
                af[pb][i][3] = __float_as_uint(As[swz128((uint32_t)((r + 8) * 128 + (ks * 8 + tig + 4) * 4)) >> 2]);
            }
#pragma unroll
            for (int j = 0; j < 4; j++) {
                int n = wc * 32 + j * 8 + gid;
                uint32_t o0 = swz128((uint32_t)(n * 128 + (ks * 8 + tig) * 4)) >> 2;
                uint32_t o1 = swz128((uint32_t)(n * 128 + (ks * 8 + tig + 4) * 4)) >> 2;
                bf1[pb][j][0] = __float_as_uint(B1s[o0]);
                bf1[pb][j][1] = __float_as_uint(B1s[o1]);
                bf2[pb][j][0] = __float_as_uint(B2s[o0]);
                bf2[pb][j][1] = __float_as_uint(B2s[o1]);
            }
        };

        ldfr(0, 0);
#pragma unroll
        for (int ks = 0; ks < 4; ks++) {
            const int cur = ks & 1;
            if (ks < 3) ldfr(ks + 1, cur ^ 1);
#pragma unroll
            for (int i = 0; i < 4; i++)
#pragma unroll
                for (int j = 0; j < 4; j++) {
                    mma8(ah[i][j], af[cur][i], bf1[cur][j]);
                    mma8(ag[i][j], af[cur][i], bf2[cur][j]);
                }
        }
    }

    // epilogue: og = tf32( (h + b1) * silu(g + bg) )
    const int m0 = mt * 128 + wr * 64;
    const int n0 = nt * 128 + wc * 32;
    const float* bp1 = bias1 + (size_t)e * HH;
    const float* bpg = biasg + (size_t)e * HH;
#pragma unroll
    for (int i = 0; i < 4; i++)
#pragma unroll
        for (int j = 0; j < 4; j++) {
            int col = n0 + j * 8 + 2 * tig;
            float bh0 = bp1[col], bh1 = bp1[col + 1];
            float bg0 = bpg[col], bg1 = bpg[col + 1];
#pragma unroll
            for (int half = 0; half < 2; half++) {
                int row = m0 + i * 16 + gid + half * 8;
                float h0 = ah[i][j][2 * half]     + bh0;
                float h1 = ah[i][j][2 * half + 1] + bh1;
                float g0 = ag[i][j][2 * half]     + bg0;
                float g1 = ag[i][j][2 * half + 1] + bg1;
                float2 v = make_float2(tf32f(h0 * my_silu(g0)), tf32f(h1 * my_silu(g1)));
                *reinterpret_cast<float2*>(g_og + ((size_t)e * TT + row) * HH + col) = v;
            }
        }
}

// =================================================================================
// GEMM2: out = og @ w2 + b2.  CTA tile 128x256, 256 threads = 8 warps (2x4),
// warp tile 64x64.  Kc=32, 4-stage (48KB/stage), 1 sync per stage. ~200 regs.
// =================================================================================
__global__ void __launch_bounds__(256, 1)
gemm2_kernel(const float* __restrict__ bias2, float* __restrict__ out) {
    extern __shared__ float sm[];
    const uint32_t sb = smem_u32(sm);
    const int tid = threadIdx.x, wid = tid >> 5, lane = tid & 31;
    const int gid = lane >> 2, tig = lane & 3;
    const int wr = wid >> 2, wc = wid & 3;          // 2x4 warp grid, warp tile 64x64
    const int bid = blockIdx.x;
    const int e = bid >> 6, mt = (bid >> 2) & 15, nt = bid & 3;

    const float* aB = g_og  + ((size_t)e * TT + (size_t)mt * 128) * HH;
    const float* bB = g_w2t + ((size_t)e * DD + (size_t)nt * 256) * HH;

    float acc[4][8][4] = {};                         // 128 acc regs

    auto fill = [&](int s) {
        const uint32_t base = sb + (uint32_t)(s & 3) * (STGF * 4);
        const float* a = aB + s * 32;
        const float* b = bB + s * 32;
#pragma unroll
        for (int c = 0; c < 4; c++) {                // A: 1024 chunks (16KB)
            int idx = c * 256 + tid;
            cp_async16(base + swz128((uint32_t)idx * 16),
                       a + (size_t)(idx >> 3) * HH + (idx & 7) * 4);
        }
#pragma unroll
        for (int c = 0; c < 8; c++) {                // B: 2048 chunks (32KB)
            int idx = c * 256 + tid;
            cp_async16(base + 16384 + swz128((uint32_t)idx * 16),
                       b + (size_t)(idx >> 3) * HH + (idx & 7) * 4);
        }
        CP_COMMIT();
    };

    fill(0); fill(1); fill(2);

#pragma unroll 1
    for (int s = 0; s < 128; s++) {                  // K = 4096 / 32
        cp_wait_tail(s, 128);
        __syncthreads();
        if (s + 3 < 128) fill(s + 3);

        const float* As = sm + (s & 3) * STGF;
        const float* Bs = As + 4096;

        uint32_t af[2][4][4], bf[2][8][2];

        auto ldfr = [&](int ks, int pb) {
#pragma unroll
            for (int i = 0; i < 4; i++) {
                int r = wr * 64 + i * 16 + gid;
                af[pb][i][0] = __float_as_uint(As[swz128((uint32_t)(r * 128 + (ks * 8 + tig) * 4)) >> 2]);
                af[pb][i][1] = __float_as_uint(As[swz128((uint32_t)((r + 8) * 128 + (ks * 8 + tig) * 4)) >> 2]);
                af[pb][i][2] = __float_as_uint(As[swz128((uint32_t)(r * 128 + (ks * 8 + tig + 4) * 4)) >> 2]);
                af[pb][i][3] = __float_as_uint(As[swz128((uint32_t)((r + 8) * 128 + (ks * 8 + tig + 4) * 4)) >> 2]);
            }
#pragma unroll
            for (int j = 0; j < 8; j++) {
                int n = wc * 64 + j * 8 + gid;
                bf[pb][j][0] = __float_as_uint(Bs[swz128((uint32_t)(n * 128 + (ks * 8 + tig) * 4)) >> 2]);
                bf[pb][j][1] = __float_as_uint(Bs[swz128((uint32_t)(n * 128 + (ks * 8 + tig + 4) * 4)) >> 2]);
            }
        };

        ldfr(0, 0);
#pragma unroll
        for (int ks = 0; ks < 4; ks++) {
            const int cur = ks & 1;
            if (ks < 3) ldfr(ks + 1, cur ^ 1);
#pragma unroll
            for (int i = 0; i < 4; i++)
#pragma unroll
                for (int j = 0; j < 8; j++)
                    mma8(acc[i][j], af[cur][i], bf[cur][j]);
        }
    }

    const int m0 = mt * 128 + wr * 64;
    const int n0 = nt * 256 + wc * 64;
    const float* bp2 = bias2 + (size_t)e * DD;
#pragma unroll
    for (int i = 0; i < 4; i++)
#pragma unroll
        for (int j = 0; j < 8; j++) {
            int col = n0 + j * 8 + 2 * tig;
            float b0 = bp2[col], b1 = bp2[col + 1];
#pragma unroll
            for (int half = 0; half < 2; half++) {
                int row = m0 + i * 16 + gid + half * 8;
                float2 v = make_float2(acc[i][j][2 * half] + b0, acc[i][j][2 * half + 1] + b1);
                *reinterpret_cast<float2*>(out + ((size_t)e * TT + row) * DD + col) = v;
            }
        }
}

// ---------------- launch ---------------------------------------------------------
extern "C" void kernel_launch(void* const* d_in, const int* in_sizes, int n_in,
                              void* d_out, int out_size) {
    const float* x  = (const float*)d_in[0];
    const float* w1 = (const float*)d_in[1];
    const float* b1 = (const float*)d_in[2];
    const float* wg = (const float*)d_in[3];
    const float* bg = (const float*)d_in[4];
    const float* w2 = (const float*)d_in[5];
    const float* b2 = (const float*)d_in[6];
    float* out = (float*)d_out;

    cudaFuncSetAttribute(gemm1_kernel, cudaFuncAttributeMaxDynamicSharedMemorySize, G_SMEM);
    cudaFuncSetAttribute(gemm2_kernel, cudaFuncAttributeMaxDynamicSharedMemorySize, G_SMEM);

    round_x_kernel<<<(EE * TT * DD) / (256 * 4), 256>>>(x);
    dim3 tpb(32, 8);
    transpose_round_kernel<<<dim3(HH / 32, DD / 32, EE), tpb>>>(w1, 0, DD, HH);
    transpose_round_kernel<<<dim3(HH / 32, DD / 32, EE), tpb>>>(wg, 1, DD, HH);
    transpose_round_kernel<<<dim3(DD / 32, HH / 32, EE), tpb>>>(w2, 2, HH, DD);

    gemm1_kernel<<<EE * 16 * 32, 256, G_SMEM>>>(b1, bg);   // 4096 CTAs
    gemm2_kernel<<<EE * 16 * 4, 256, G_SMEM>>>(b2, out);   // 512 CTAs
}

// round 6
// speedup vs baseline: 1.1282x; 1.0434x over previous
#include <cuda_runtime.h>
#include <cstdint>

#define EE 8
#define TT 2048
#define DD 1024
#define HH 4096

// ---------------- packed device scratch (pre-swizzled 16KB stage tiles) --------
// A1p: x packed     [e][mt(16)][s(32)]   [128 rows x 32 K, swizzled]   64MB
// B1p: w_c_fc^T     [e][nt(32)][s(32)]   [128 n   x 32 K, swizzled]   128MB
// Bgp: w_gate^T     [e][nt(32)][s(32)]                                 128MB
// B2p: w_c_proj^T   [e][nt(8)] [s(128)]                                128MB
// A2p: og packed    [e][mt(16)][s(128)]                                256MB
__device__ __align__(1024) float g_A1p[(size_t)EE * TT * DD];
__device__ __align__(1024) float g_B1p[(size_t)EE * HH * DD];
__device__ __align__(1024) float g_Bgp[(size_t)EE * HH * DD];
__device__ __align__(1024) float g_B2p[(size_t)EE * DD * HH];
__device__ __align__(1024) float g_A2p[(size_t)EE * TT * HH];

// ---------------- helpers ------------------------------------------------------
__device__ __forceinline__ uint32_t smem_u32(const void* p) {
    uint32_t a;
    asm("{ .reg .u64 t; cvta.to.shared.u64 t, %1; cvt.u32.u64 %0, t; }" : "=r"(a) : "l"(p));
    return a;
}
__device__ __forceinline__ uint32_t swz128(uint32_t o) { return o ^ ((o >> 3) & 0x70); }

__device__ __forceinline__ float tf32f(float x) {
    uint32_t r; asm("cvt.rna.tf32.f32 %0, %1;" : "=r"(r) : "f"(x));
    return __uint_as_float(r);
}
__device__ __forceinline__ void mbar_init(uint32_t m, uint32_t c) {
    asm volatile("mbarrier.init.shared.b64 [%0], %1;" :: "r"(m), "r"(c) : "memory");
}
__device__ __forceinline__ void mbar_expect_tx(uint32_t m, uint32_t bytes) {
    asm volatile("mbarrier.arrive.expect_tx.shared.b64 _, [%0], %1;"
                 :: "r"(m), "r"(bytes) : "memory");
}
__device__ __forceinline__ void mbar_wait(uint32_t m, uint32_t parity) {
    asm volatile(
        "{\n\t.reg .pred P;\n"
        "LW_%=:\n\t"
        "mbarrier.try_wait.parity.acquire.cta.shared::cta.b64 P, [%0], %1, 0x989680;\n\t"
        "@P bra.uni LD_%=;\n\t"
        "bra.uni LW_%=;\n"
        "LD_%=:\n\t}"
        :: "r"(m), "r"(parity) : "memory");
}
// one-instruction bulk copy gmem->smem (TMA-bulk, sm_90 baseline)
__device__ __forceinline__ void bulk_g2s(uint32_t dst, const float* src,
                                         uint32_t bytes, uint32_t mbar) {
    asm volatile(
        "cp.async.bulk.shared::cluster.global.mbarrier::complete_tx::bytes "
        "[%0], [%1], %2, [%3];"
        :: "r"(dst), "l"(src), "r"(bytes), "r"(mbar) : "memory");
}
#define FENCE_ASYNC() asm volatile("fence.proxy.async.shared::cta;" ::: "memory")

// tf32 m16n8k8: D = A@B + D
__device__ __forceinline__ void mma8(float* c, const uint32_t* a, const uint32_t* b) {
    asm volatile(
        "mma.sync.aligned.m16n8k8.row.col.f32.tf32.tf32.f32 "
        "{%0,%1,%2,%3}, {%4,%5,%6,%7}, {%8,%9}, {%0,%1,%2,%3};"
        : "+f"(c[0]), "+f"(c[1]), "+f"(c[2]), "+f"(c[3])
        : "r"(a[0]), "r"(a[1]), "r"(a[2]), "r"(a[3]), "r"(b[0]), "r"(b[1]));
}
__device__ __forceinline__ float my_silu(float g) { return g / (1.0f + __expf(-g)); }

// ---------------- prep: pack x -------------------------------------------------
__global__ void pack_x_kernel(const float* __restrict__ x) {
    size_t idx = ((size_t)blockIdx.x * blockDim.x + threadIdx.x) * 4;
    float4 v = *reinterpret_cast<const float4*>(x + idx);
    v.x = tf32f(v.x); v.y = tf32f(v.y); v.z = tf32f(v.z); v.w = tf32f(v.w);
    int d = (int)(idx & (DD - 1));
    int t = (int)((idx / DD) & (TT - 1));
    int e = (int)(idx / ((size_t)TT * DD));
    int mt = t >> 7, r = t & 127, s = d >> 5, c = d & 31;
    float* dst = g_A1p + (((size_t)(e * 16 + mt) * 32 + s) << 12)
               + (swz128((uint32_t)(r * 128 + c * 4)) >> 2);
    *reinterpret_cast<float4*>(dst) = v;
}

// ---------------- prep: transpose + round + pack weights -----------------------
// in [e][R][C] row-major -> out tiles [e][C/128][R/32][4096 floats swizzled]
// output element (n=col-of-in, k=row-of-in)
__global__ void transpose_pack_kernel(const float* __restrict__ in, float* __restrict__ out,
                                      int R, int C) {
    __shared__ float tsm[32][33];
    const int e = blockIdx.z;
    const float* ip = in + (size_t)e * R * C;
    const int c0 = blockIdx.x * 32, r0 = blockIdx.y * 32;
    const int tx = threadIdx.x, ty = threadIdx.y;
#pragma unroll
    for (int i = 0; i < 4; i++)
        tsm[ty + 8 * i][tx] = ip[(size_t)(r0 + ty + 8 * i) * C + c0 + tx];
    __syncthreads();
    const int NT = C >> 7, NSt = R >> 5;
    const int s = r0 >> 5;
#pragma unroll
    for (int i = 0; i < 4; i++) {
        int n = c0 + ty + 8 * i;
        int nt = n >> 7, nl = n & 127;
        float* bp = out + (((size_t)(e * NT + nt) * NSt + s) << 12);
        bp[swz128((uint32_t)(nl * 128 + tx * 4)) >> 2] = tf32f(tsm[tx][ty + 8 * i]);
    }
}

// =================================================================================
// GEMM1 fused: h = x@w1+b1 ; g = silu(x@wg+bg) ; og_packed = tf32(h*g)
// CTA 128x128 dual-plane, 256 thr (8 warps 2x4, warp 64x32), Kc=32.
// 4-stage ring, fills via cp.async.bulk (3 x 16KB per stage) + mbarrier.
// =================================================================================
#define G1_STG_B 49152
#define G1_STG_F 12288
#define G1_SMEM (1024 + 4 * G1_STG_B)

__global__ void __launch_bounds__(256, 1)
gemm1_kernel(const float* __restrict__ bias1, const float* __restrict__ biasg) {
    extern __shared__ float sm[];
    const uint32_t sb = smem_u32(sm);
    const int tid = threadIdx.x, wid = tid >> 5, lane = tid & 31;
    const int gid = lane >> 2, tig = lane & 3;
    const int wr = wid >> 2, wc = wid & 3;          // 2x4 grid, warp tile 64x32
    const int bid = blockIdx.x;
    const int e = bid >> 9, mt = (bid >> 5) & 15, nt = bid & 31;

    const float* aS  = g_A1p + (((size_t)(e * 16 + mt) * 32) << 12);
    const float* b1S = g_B1p + (((size_t)(e * 32 + nt) * 32) << 12);
    const float* bgS = g_Bgp + (((size_t)(e * 32 + nt) * 32) << 12);

    float ah[4][4][4] = {}, ag[4][4][4] = {};       // 128 acc regs

    auto fillb = [&](int s) {
        const int b = s & 3;
        const uint32_t mb = sb + (uint32_t)b * 8;
        const uint32_t dst = sb + 1024 + (uint32_t)b * G1_STG_B;
        mbar_expect_tx(mb, G1_STG_B);
        bulk_g2s(dst,          aS  + ((size_t)s << 12), 16384, mb);
        bulk_g2s(dst + 16384,  b1S + ((size_t)s << 12), 16384, mb);
        bulk_g2s(dst + 32768,  bgS + ((size_t)s << 12), 16384, mb);
    };

    if (tid == 0) {
#pragma unroll
        for (int b = 0; b < 4; b++) mbar_init(sb + b * 8, 1);
        FENCE_ASYNC();
        fillb(0); fillb(1); fillb(2);
    }

#pragma unroll 1
    for (int s = 0; s < 32; s++) {
        __syncthreads();                             // stage s-1 fully consumed
        if (tid == 0 && s + 3 < 32) { FENCE_ASYNC(); fillb(s + 3); }
        mbar_wait(sb + (uint32_t)(s & 3) * 8, (uint32_t)((s >> 2) & 1));

        const float* As  = sm + 256 + (s & 3) * G1_STG_F;
        const float* B1s = As + 4096;
        const float* B2s = As + 8192;

        uint32_t af[2][4][4], bf1[2][4][2], bf2[2][4][2];

        auto ldfr = [&](int ks, int pb) {
#pragma unroll
            for (int i = 0; i < 4; i++) {
                int r = wr * 64 + i * 16 + gid;
                af[pb][i][0] = __float_as_uint(As[swz128((uint32_t)(r * 128 + (ks * 8 + tig) * 4)) >> 2]);
                af[pb][i][1] = __float_as_uint(As[swz128((uint32_t)((r + 8) * 128 + (ks * 8 + tig) * 4)) >> 2]);
                af[pb][i][2] = __float_as_uint(As[swz128((uint32_t)(r * 128 + (ks * 8 + tig + 4) * 4)) >> 2]);
                af[pb][i][3] = __float_as_uint(As[swz128((uint32_t)((r + 8) * 128 + (ks * 8 + tig + 4) * 4)) >> 2]);
            }
#pragma unroll
            for (int j = 0; j < 4; j++) {
                int n = wc * 32 + j * 8 + gid;
                uint32_t o0 = swz128((uint32_t)(n * 128 + (ks * 8 + tig) * 4)) >> 2;
                uint32_t o1 = swz128((uint32_t)(n * 128 + (ks * 8 + tig + 4) * 4)) >> 2;
                bf1[pb][j][0] = __float_as_uint(B1s[o0]);
                bf1[pb][j][1] = __float_as_uint(B1s[o1]);
                bf2[pb][j][0] = __float_as_uint(B2s[o0]);
                bf2[pb][j][1] = __float_as_uint(B2s[o1]);
            }
        };

        ldfr(0, 0);
#pragma unroll
        for (int ks = 0; ks < 4; ks++) {
            const int cur = ks & 1;
            if (ks < 3) ldfr(ks + 1, cur ^ 1);
#pragma unroll
            for (int i = 0; i < 4; i++)
#pragma unroll
                for (int j = 0; j < 4; j++) {
                    mma8(ah[i][j], af[cur][i], bf1[cur][j]);
                    mma8(ag[i][j], af[cur][i], bf2[cur][j]);
                }
        }
    }

    // epilogue: og = tf32((h+b1)*silu(g+bg)) written PACKED for GEMM2
    const float* bp1 = bias1 + (size_t)e * HH + nt * 128;
    const float* bpg = biasg + (size_t)e * HH + nt * 128;
    const int s2 = nt * 4 + wc;                      // GEMM2 stage block
    float* blk = g_A2p + (((size_t)(e * 16 + mt) * 128 + s2) << 12);
#pragma unroll
    for (int i = 0; i < 4; i++)
#pragma unroll
        for (int j = 0; j < 4; j++) {
            int cl = wc * 32 + j * 8 + 2 * tig;      // col within 128-tile
            float bh0 = bp1[cl], bh1 = bp1[cl + 1];
            float bg0 = bpg[cl], bg1 = bpg[cl + 1];
            int c2 = j * 8 + 2 * tig;                // col within 32-wide stage
#pragma unroll
            for (int half = 0; half < 2; half++) {
                int rl = wr * 64 + i * 16 + gid + half * 8;
                float h0 = ah[i][j][2 * half]     + bh0;
                float h1 = ah[i][j][2 * half + 1] + bh1;
                float g0 = ag[i][j][2 * half]     + bg0;
                float g1 = ag[i][j][2 * half + 1] + bg1;
                float2 v = make_float2(tf32f(h0 * my_silu(g0)), tf32f(h1 * my_silu(g1)));
                *reinterpret_cast<float2*>(blk + (swz128((uint32_t)(rl * 128 + c2 * 4)) >> 2)) = v;
            }
        }
}

// =================================================================================
// GEMM2: out = og @ w2 + b2.  CTA 128x128, 256 thr (8 warps 2x4, warp 64x32),
// Kc=32, 128 stages, 3-stage ring (32KB/stage, 97KB total) -> occupancy 2.
// =================================================================================
#define G2_STG_B 32768
#define G2_STG_F 8192
#define G2_SMEM (1024 + 3 * G2_STG_B)

__global__ void __launch_bounds__(256, 2)
gemm2_kernel(const float* __restrict__ bias2, float* __restrict__ out) {
    extern __shared__ float sm[];
    const uint32_t sb = smem_u32(sm);
    const int tid = threadIdx.x, wid = tid >> 5, lane = tid & 31;
    const int gid = lane >> 2, tig = lane & 3;
    const int wr = wid >> 2, wc = wid & 3;          // 2x4 grid, warp tile 64x32
    const int bid = blockIdx.x;
    const int e = bid >> 7, mt = (bid >> 3) & 15, nt = bid & 7;

    const float* aS = g_A2p + (((size_t)(e * 16 + mt) * 128) << 12);
    const float* bS = g_B2p + (((size_t)(e * 8  + nt) * 128) << 12);

    float acc[4][4][4] = {};                         // 64 acc regs

    auto fillb = [&](int s, int b) {
        const uint32_t mb = sb + (uint32_t)b * 8;
        const uint32_t dst = sb + 1024 + (uint32_t)b * G2_STG_B;
        mbar_expect_tx(mb, G2_STG_B);
        bulk_g2s(dst,         aS + ((size_t)s << 12), 16384, mb);
        bulk_g2s(dst + 16384, bS + ((size_t)s << 12), 16384, mb);
    };

    if (tid == 0) {
#pragma unroll
        for (int b = 0; b < 3; b++) mbar_init(sb + b * 8, 1);
        FENCE_ASYNC();
        fillb(0, 0); fillb(1, 1);
    }

    int cb = 0, cph = 0, pb = 2;
#pragma unroll 1
    for (int s = 0; s < 128; s++) {
        __syncthreads();
        if (tid == 0 && s + 2 < 128) { FENCE_ASYNC(); fillb(s + 2, pb); }
        if (++pb == 3) pb = 0;
        mbar_wait(sb + (uint32_t)cb * 8, (uint32_t)cph);

        const float* As = sm + 256 + cb * G2_STG_F;
        const float* Bs = As + 4096;
        if (++cb == 3) { cb = 0; cph ^= 1; }

#pragma unroll
        for (int ks = 0; ks < 4; ks++) {
            uint32_t af[4][4], bf[4][2];
#pragma unroll
            for (int i = 0; i < 4; i++) {
                int r = wr * 64 + i * 16 + gid;
                af[i][0] = __float_as_uint(As[swz128((uint32_t)(r * 128 + (ks * 8 + tig) * 4)) >> 2]);
                af[i][1] = __float_as_uint(As[swz128((uint32_t)((r + 8) * 128 + (ks * 8 + tig) * 4)) >> 2]);
                af[i][2] = __float_as_uint(As[swz128((uint32_t)(r * 128 + (ks * 8 + tig + 4) * 4)) >> 2]);
                af[i][3] = __float_as_uint(As[swz128((uint32_t)((r + 8) * 128 + (ks * 8 + tig + 4) * 4)) >> 2]);
            }
#pragma unroll
            for (int j = 0; j < 4; j++) {
                int n = wc * 32 + j * 8 + gid;
                bf[j][0] = __float_as_uint(Bs[swz128((uint32_t)(n * 128 + (ks * 8 + tig) * 4)) >> 2]);
                bf[j][1] = __float_as_uint(Bs[swz128((uint32_t)(n * 128 + (ks * 8 + tig + 4) * 4)) >> 2]);
            }
#pragma unroll
            for (int i = 0; i < 4; i++)
#pragma unroll
                for (int j = 0; j < 4; j++)
                    mma8(acc[i][j], af[i], bf[j]);
        }
    }

    const int m0 = mt * 128 + wr * 64;
    const int n0 = nt * 128 + wc * 32;
    const float* bp2 = bias2 + (size_t)e * DD;
#pragma unroll
    for (int i = 0; i < 4; i++)
#pragma unroll
        for (int j = 0; j < 4; j++) {
            int col = n0 + j * 8 + 2 * tig;
            float b0 = bp2[col], b1 = bp2[col + 1];
#pragma unroll
            for (int half = 0; half < 2; half++) {
                int row = m0 + i * 16 + gid + half * 8;
                float2 v = make_float2(acc[i][j][2 * half] + b0, acc[i][j][2 * half + 1] + b1);
                *reinterpret_cast<float2*>(out + ((size_t)e * TT + row) * DD + col) = v;
            }
        }
}

// ---------------- launch ---------------------------------------------------------
extern "C" void kernel_launch(void* const* d_in, const int* in_sizes, int n_in,
                              void* d_out, int out_size) {
    const float* x  = (const float*)d_in[0];
    const float* w1 = (const float*)d_in[1];
    const float* b1 = (const float*)d_in[2];
    const float* wg = (const float*)d_in[3];
    const float* bg = (const float*)d_in[4];
    const float* w2 = (const float*)d_in[5];
    const float* b2 = (const float*)d_in[6];
    float* out = (float*)d_out;

    cudaFuncSetAttribute(gemm1_kernel, cudaFuncAttributeMaxDynamicSharedMemorySize, G1_SMEM);
    cudaFuncSetAttribute(gemm2_kernel, cudaFuncAttributeMaxDynamicSharedMemorySize, G2_SMEM);

    float *dB1p, *dBgp, *dB2p;
    cudaGetSymbolAddress((void**)&dB1p, g_B1p);
    cudaGetSymbolAddress((void**)&dBgp, g_Bgp);
    cudaGetSymbolAddress((void**)&dB2p, g_B2p);

    pack_x_kernel<<<(EE * TT * DD) / (256 * 4), 256>>>(x);
    dim3 tpb(32, 8);
    transpose_pack_kernel<<<dim3(HH / 32, DD / 32, EE), tpb>>>(w1, dB1p, DD, HH);
    transpose_pack_kernel<<<dim3(HH / 32, DD / 32, EE), tpb>>>(wg, dBgp, DD, HH);
    transpose_pack_kernel<<<dim3(DD / 32, HH / 32, EE), tpb>>>(w2, dB2p, HH, DD);

    gemm1_kernel<<<EE * 16 * 32, 256, G1_SMEM>>>(b1, bg);   // 4096 CTAs
    gemm2_kernel<<<EE * 16 * 8, 256, G2_SMEM>>>(b2, out);   // 1024 CTAs
}

// round 7
// speedup vs baseline: 1.2001x; 1.0638x over previous
#include <cuda_runtime.h>
#include <cstdint>

#define EE 8
#define TT 2048
#define DD 1024
#define HH 4096

// ---------------- packed device scratch (pre-swizzled 16KB [128x32] tiles) -----
__device__ __align__(1024) float g_A1p[(size_t)EE * TT * DD];
__device__ __align__(1024) float g_B1p[(size_t)EE * HH * DD];
__device__ __align__(1024) float g_Bgp[(size_t)EE * HH * DD];
__device__ __align__(1024) float g_B2p[(size_t)EE * DD * HH];
__device__ __align__(1024) float g_A2p[(size_t)EE * TT * HH];

// ---------------- helpers ------------------------------------------------------
__device__ __forceinline__ uint32_t smem_u32(const void* p) {
    uint32_t a;
    asm("{ .reg .u64 t; cvta.to.shared.u64 t, %1; cvt.u32.u64 %0, t; }" : "=r"(a) : "l"(p));
    return a;
}
__device__ __forceinline__ uint32_t swz128(uint32_t o) { return o ^ ((o >> 3) & 0x70); }

__device__ __forceinline__ float tf32f(float x) {
    uint32_t r; asm("cvt.rna.tf32.f32 %0, %1;" : "=r"(r) : "f"(x));
    return __uint_as_float(r);
}
__device__ __forceinline__ void mbar_init(uint32_t m, uint32_t c) {
    asm volatile("mbarrier.init.shared.b64 [%0], %1;" :: "r"(m), "r"(c) : "memory");
}
__device__ __forceinline__ void mbar_expect_tx(uint32_t m, uint32_t bytes) {
    asm volatile("mbarrier.arrive.expect_tx.shared.b64 _, [%0], %1;"
                 :: "r"(m), "r"(bytes) : "memory");
}
__device__ __forceinline__ void mbar_wait(uint32_t m, uint32_t parity) {
    asm volatile(
        "{\n\t.reg .pred P;\n"
        "LW_%=:\n\t"
        "mbarrier.try_wait.parity.acquire.cta.shared::cta.b64 P, [%0], %1, 0x989680;\n\t"
        "@P bra.uni LD_%=;\n\t"
        "bra.uni LW_%=;\n"
        "LD_%=:\n\t}"
        :: "r"(m), "r"(parity) : "memory");
}
__device__ __forceinline__ void bulk_g2s(uint32_t dst, const float* src,
                                         uint32_t bytes, uint32_t mbar) {
    asm volatile(
        "cp.async.bulk.shared::cluster.global.mbarrier::complete_tx::bytes "
        "[%0], [%1], %2, [%3];"
        :: "r"(dst), "l"(src), "r"(bytes), "r"(mbar) : "memory");
}
#define FENCE_ASYNC() asm volatile("fence.proxy.async.shared::cta;" ::: "memory")

__device__ __forceinline__ void mma8(float* c, const uint32_t* a, const uint32_t* b) {
    asm volatile(
        "mma.sync.aligned.m16n8k8.row.col.f32.tf32.tf32.f32 "
        "{%0,%1,%2,%3}, {%4,%5,%6,%7}, {%8,%9}, {%0,%1,%2,%3};"
        : "+f"(c[0]), "+f"(c[1]), "+f"(c[2]), "+f"(c[3])
        : "r"(a[0]), "r"(a[1]), "r"(a[2]), "r"(a[3]), "r"(b[0]), "r"(b[1]));
}
__device__ __forceinline__ float my_silu(float g) { return g / (1.0f + __expf(-g)); }

// ---------------- prep: pack x -------------------------------------------------
__global__ void pack_x_kernel(const float* __restrict__ x) {
    size_t idx = ((size_t)blockIdx.x * blockDim.x + threadIdx.x) * 4;
    float4 v = *reinterpret_cast<const float4*>(x + idx);
    v.x = tf32f(v.x); v.y = tf32f(v.y); v.z = tf32f(v.z); v.w = tf32f(v.w);
    int d = (int)(idx & (DD - 1));
    int t = (int)((idx / DD) & (TT - 1));
    int e = (int)(idx / ((size_t)TT * DD));
    int mt = t >> 7, r = t & 127, s = d >> 5, c = d & 31;
    float* dst = g_A1p + (((size_t)(e * 16 + mt) * 32 + s) << 12)
               + (swz128((uint32_t)(r * 128 + c * 4)) >> 2);
    *reinterpret_cast<float4*>(dst) = v;
}

// ---------------- prep: transpose + round + pack weights -----------------------
__global__ void transpose_pack_kernel(const float* __restrict__ in, float* __restrict__ out,
                                      int R, int C) {
    __shared__ float tsm[32][33];
    const int e = blockIdx.z;
    const float* ip = in + (size_t)e * R * C;
    const int c0 = blockIdx.x * 32, r0 = blockIdx.y * 32;
    const int tx = threadIdx.x, ty = threadIdx.y;
#pragma unroll
    for (int i = 0; i < 4; i++)
        tsm[ty + 8 * i][tx] = ip[(size_t)(r0 + ty + 8 * i) * C + c0 + tx];
    __syncthreads();
    const int NT = C >> 7, NSt = R >> 5;
    const int s = r0 >> 5;
#pragma unroll
    for (int i = 0; i < 4; i++) {
        int n = c0 + ty + 8 * i;
        int nt = n >> 7, nl = n & 127;
        float* bp = out + (((size_t)(e * NT + nt) * NSt + s) << 12);
        bp[swz128((uint32_t)(nl * 128 + tx * 4)) >> 2] = tf32f(tsm[tx][ty + 8 * i]);
    }
}

// =================================================================================
// GEMM1 fused: h = x@w1+b1 ; g = silu(x@wg+bg) ; og_packed = tf32(h*g)
// CTA 128x128 dual-plane, 256 thr (8 warps 2x4, warp 64x32).
// Kc=64 -> 16 stages; 2-stage ring, 96KB/stage, depth-1 TMA-bulk prefetch.
// =================================================================================
#define G1_STG_B 98304
#define G1_STG_F 24576
#define G1_SMEM (1024 + 2 * G1_STG_B)

__global__ void __launch_bounds__(256, 1)
gemm1_kernel(const float* __restrict__ bias1, const float* __restrict__ biasg) {
    extern __shared__ float sm[];
    const uint32_t sb = smem_u32(sm);
    const int tid = threadIdx.x, wid = tid >> 5, lane = tid & 31;
    const int gid = lane >> 2, tig = lane & 3;
    const int wr = wid >> 2, wc = wid & 3;          // 2x4 grid, warp tile 64x32
    const int bid = blockIdx.x;
    const int e = bid >> 9, nt = (bid >> 4) & 31, mt = bid & 15;  // mt innermost: B reuse in L2

    const float* aS  = g_A1p + (((size_t)(e * 16 + mt) * 32) << 12);
    const float* b1S = g_B1p + (((size_t)(e * 32 + nt) * 32) << 12);
    const float* bgS = g_Bgp + (((size_t)(e * 32 + nt) * 32) << 12);

    float ah[4][4][4] = {}, ag[4][4][4] = {};       // 128 acc regs

    auto fillb = [&](int s) {                        // stage s: 2 packed 16KB blocks each
        const int b = s & 1;
        const uint32_t mb = sb + (uint32_t)b * 8;
        const uint32_t dst = sb + 1024 + (uint32_t)b * G1_STG_B;
        mbar_expect_tx(mb, G1_STG_B);
        bulk_g2s(dst,          aS  + ((size_t)(2 * s) << 12), 32768, mb);
        bulk_g2s(dst + 32768,  b1S + ((size_t)(2 * s) << 12), 32768, mb);
        bulk_g2s(dst + 65536,  bgS + ((size_t)(2 * s) << 12), 32768, mb);
    };

    if (tid == 0) {
        mbar_init(sb, 1); mbar_init(sb + 8, 1);
        FENCE_ASYNC();
        fillb(0);
    }

#pragma unroll 1
    for (int s = 0; s < 16; s++) {                   // K = 1024 / 64
        __syncthreads();                             // buf (s+1)&1 fully consumed
        if (tid == 0 && s + 1 < 16) { FENCE_ASYNC(); fillb(s + 1); }
        mbar_wait(sb + (uint32_t)(s & 1) * 8, (uint32_t)((s >> 1) & 1));

        const float* As  = sm + 256 + (s & 1) * G1_STG_F;  // [A0 A1 B10 B11 Bg0 Bg1]
        const float* B1s = As + 8192;
        const float* B2s = As + 16384;

        uint32_t af[2][4][4], bf1[2][4][2], bf2[2][4][2];

        auto ldfr = [&](int ks, int pb) {
            const int blk = (ks >> 2) * 4096, kk = ks & 3;
#pragma unroll
            for (int i = 0; i < 4; i++) {
                int r = wr * 64 + i * 16 + gid;
                af[pb][i][0] = __float_as_uint(As[blk + (swz128((uint32_t)(r * 128 + (kk * 8 + tig) * 4)) >> 2)]);
                af[pb][i][1] = __float_as_uint(As[blk + (swz128((uint32_t)((r + 8) * 128 + (kk * 8 + tig) * 4)) >> 2)]);
                af[pb][i][2] = __float_as_uint(As[blk + (swz128((uint32_t)(r * 128 + (kk * 8 + tig + 4) * 4)) >> 2)]);
                af[pb][i][3] = __float_as_uint(As[blk + (swz128((uint32_t)((r + 8) * 128 + (kk * 8 + tig + 4) * 4)) >> 2)]);
            }
#pragma unroll
            for (int j = 0; j < 4; j++) {
                int n = wc * 32 + j * 8 + gid;
                uint32_t o0 = swz128((uint32_t)(n * 128 + (kk * 8 + tig) * 4)) >> 2;
                uint32_t o1 = swz128((uint32_t)(n * 128 + (kk * 8 + tig + 4) * 4)) >> 2;
                bf1[pb][j][0] = __float_as_uint(B1s[blk + o0]);
                bf1[pb][j][1] = __float_as_uint(B1s[blk + o1]);
                bf2[pb][j][0] = __float_as_uint(B2s[blk + o0]);
                bf2[pb][j][1] = __float_as_uint(B2s[blk + o1]);
            }
        };

        ldfr(0, 0);
#pragma unroll
        for (int ks = 0; ks < 8; ks++) {
            const int cur = ks & 1;
            if (ks < 7) ldfr(ks + 1, cur ^ 1);
#pragma unroll
            for (int i = 0; i < 4; i++)
#pragma unroll
                for (int j = 0; j < 4; j++) {
                    mma8(ah[i][j], af[cur][i], bf1[cur][j]);
                    mma8(ag[i][j], af[cur][i], bf2[cur][j]);
                }
        }
    }

    // epilogue: og = tf32((h+b1)*silu(g+bg)) written PACKED for GEMM2
    const float* bp1 = bias1 + (size_t)e * HH + nt * 128;
    const float* bpg = biasg + (size_t)e * HH + nt * 128;
    const int s2 = nt * 4 + wc;
    float* blk = g_A2p + (((size_t)(e * 16 + mt) * 128 + s2) << 12);
#pragma unroll
    for (int i = 0; i < 4; i++)
#pragma unroll
        for (int j = 0; j < 4; j++) {
            int cl = wc * 32 + j * 8 + 2 * tig;
            float bh0 = bp1[cl], bh1 = bp1[cl + 1];
            float bg0 = bpg[cl], bg1 = bpg[cl + 1];
            int c2 = j * 8 + 2 * tig;
#pragma unroll
            for (int half = 0; half < 2; half++) {
                int rl = wr * 64 + i * 16 + gid + half * 8;
                float h0 = ah[i][j][2 * half]     + bh0;
                float h1 = ah[i][j][2 * half + 1] + bh1;
                float g0 = ag[i][j][2 * half]     + bg0;
                float g1 = ag[i][j][2 * half + 1] + bg1;
                float2 v = make_float2(tf32f(h0 * my_silu(g0)), tf32f(h1 * my_silu(g1)));
                *reinterpret_cast<float2*>(blk + (swz128((uint32_t)(rl * 128 + c2 * 4)) >> 2)) = v;
            }
        }
}

// =================================================================================
// GEMM2: out = og @ w2 + b2.  CTA 128x128, 256 thr, Kc=32, 3-stage ring, occ 2.
// =================================================================================
#define G2_STG_B 32768
#define G2_STG_F 8192
#define G2_SMEM (1024 + 3 * G2_STG_B)

__global__ void __launch_bounds__(256, 2)
gemm2_kernel(const float* __restrict__ bias2, float* __restrict__ out) {
    extern __shared__ float sm[];
    const uint32_t sb = smem_u32(sm);
    const int tid = threadIdx.x, wid = tid >> 5, lane = tid & 31;
    const int gid = lane >> 2, tig = lane & 3;
    const int wr = wid >> 2, wc = wid & 3;
    const int bid = blockIdx.x;
    const int e = bid >> 7, nt = (bid >> 4) & 7, mt = bid & 15;   // mt innermost

    const float* aS = g_A2p + (((size_t)(e * 16 + mt) * 128) << 12);
    const float* bS = g_B2p + (((size_t)(e * 8  + nt) * 128) << 12);

    float acc[4][4][4] = {};

    auto fillb = [&](int s, int b) {
        const uint32_t mb = sb + (uint32_t)b * 8;
        const uint32_t dst = sb + 1024 + (uint32_t)b * G2_STG_B;
        mbar_expect_tx(mb, G2_STG_B);
        bulk_g2s(dst,         aS + ((size_t)s << 12), 16384, mb);
        bulk_g2s(dst + 16384, bS + ((size_t)s << 12), 16384, mb);
    };

    if (tid == 0) {
#pragma unroll
        for (int b = 0; b < 3; b++) mbar_init(sb + b * 8, 1);
        FENCE_ASYNC();
        fillb(0, 0); fillb(1, 1);
    }

    int cb = 0, cph = 0, pb = 2;
#pragma unroll 1
    for (int s = 0; s < 128; s++) {
        __syncthreads();
        if (tid == 0 && s + 2 < 128) { FENCE_ASYNC(); fillb(s + 2, pb); }
        if (++pb == 3) pb = 0;
        mbar_wait(sb + (uint32_t)cb * 8, (uint32_t)cph);

        const float* As = sm + 256 + cb * G2_STG_F;
        const float* Bs = As + 4096;
        if (++cb == 3) { cb = 0; cph ^= 1; }

#pragma unroll
        for (int ks = 0; ks < 4; ks++) {
            uint32_t af[4][4], bf[4][2];
#pragma unroll
            for (int i = 0; i < 4; i++) {
                int r = wr * 64 + i * 16 + gid;
                af[i][0] = __float_as_uint(As[swz128((uint32_t)(r * 128 + (ks * 8 + tig) * 4)) >> 2]);
                af[i][1] = __float_as_uint(As[swz128((uint32_t)((r + 8) * 128 + (ks * 8 + tig) * 4)) >> 2]);
                af[i][2] = __float_as_uint(As[swz128((uint32_t)(r * 128 + (ks * 8 + tig + 4) * 4)) >> 2]);
                af[i][3] = __float_as_uint(As[swz128((uint32_t)((r + 8) * 128 + (ks * 8 + tig + 4) * 4)) >> 2]);
            }
#pragma unroll
            for (int j = 0; j < 4; j++) {
                int n = wc * 32 + j * 8 + gid;
                bf[j][0] = __float_as_uint(Bs[swz128((uint32_t)(n * 128 + (ks * 8 + tig) * 4)) >> 2]);
                bf[j][1] = __float_as_uint(Bs[swz128((uint32_t)(n * 128 + (ks * 8 + tig + 4) * 4)) >> 2]);
            }
#pragma unroll
            for (int i = 0; i < 4; i++)
#pragma unroll
                for (int j = 0; j < 4; j++)
                    mma8(acc[i][j], af[i], bf[j]);
        }
    }

    const int m0 = mt * 128 + wr * 64;
    const int n0 = nt * 128 + wc * 32;
    const float* bp2 = bias2 + (size_t)e * DD;
#pragma unroll
    for (int i = 0; i < 4; i++)
#pragma unroll
        for (int j = 0; j < 4; j++) {
            int col = n0 + j * 8 + 2 * tig;
            float b0 = bp2[col], b1 = bp2[col + 1];
#pragma unroll
            for (int half = 0; half < 2; half++) {
                int row = m0 + i * 16 + gid + half * 8;
                float2 v = make_float2(acc[i][j][2 * half] + b0, acc[i][j][2 * half + 1] + b1);
                *reinterpret_cast<float2*>(out + ((size_t)e * TT + row) * DD + col) = v;
            }
        }
}

// ---------------- launch ---------------------------------------------------------
extern "C" void kernel_launch(void* const* d_in, const int* in_sizes, int n_in,
                              void* d_out, int out_size) {
    const float* x  = (const float*)d_in[0];
    const float* w1 = (const float*)d_in[1];
    const float* b1 = (const float*)d_in[2];
    const float* wg = (const float*)d_in[3];
    const float* bg = (const float*)d_in[4];
    const float* w2 = (const float*)d_in[5];
    const float* b2 = (const float*)d_in[6];
    float* out = (float*)d_out;

    cudaFuncSetAttribute(gemm1_kernel, cudaFuncAttributeMaxDynamicSharedMemorySize, G1_SMEM);
    cudaFuncSetAttribute(gemm2_kernel, cudaFuncAttributeMaxDynamicSharedMemorySize, G2_SMEM);

    float *dB1p, *dBgp, *dB2p;
    cudaGetSymbolAddress((void**)&dB1p, g_B1p);
    cudaGetSymbolAddress((void**)&dBgp, g_Bgp);
    cudaGetSymbolAddress((void**)&dB2p, g_B2p);

    pack_x_kernel<<<(EE * TT * DD) / (256 * 4), 256>>>(x);
    dim3 tpb(32, 8);
    transpose_pack_kernel<<<dim3(HH / 32, DD / 32, EE), tpb>>>(w1, dB1p, DD, HH);
    transpose_pack_kernel<<<dim3(HH / 32, DD / 32, EE), tpb>>>(wg, dBgp, DD, HH);
    transpose_pack_kernel<<<dim3(DD / 32, HH / 32, EE), tpb>>>(w2, dB2p, HH, DD);

    gemm1_kernel<<<EE * 16 * 32, 256, G1_SMEM>>>(b1, bg);   // 4096 CTAs
    gemm2_kernel<<<EE * 16 * 8, 256, G2_SMEM>>>(b2, out);   // 1024 CTAs
}

// round 8
// speedup vs baseline: 1.3640x; 1.1365x over previous
#include <cuda_runtime.h>
#include <cstdint>

#define EE 8
#define TT 2048
#define DD 1024
#define HH 4096

// ---------------- packed device scratch (pre-swizzled 16KB [128x32] tiles) -----
__device__ __align__(1024) float g_A1p[(size_t)EE * TT * DD];
__device__ __align__(1024) float g_B1p[(size_t)EE * HH * DD];
__device__ __align__(1024) float g_Bgp[(size_t)EE * HH * DD];
__device__ __align__(1024) float g_B2p[(size_t)EE * DD * HH];
__device__ __align__(1024) float g_A2p[(size_t)EE * TT * HH];

// ---------------- helpers ------------------------------------------------------
__device__ __forceinline__ uint32_t smem_u32(const void* p) {
    uint32_t a;
    asm("{ .reg .u64 t; cvta.to.shared.u64 t, %1; cvt.u32.u64 %0, t; }" : "=r"(a) : "l"(p));
    return a;
}
__device__ __forceinline__ uint32_t swz128(uint32_t o) { return o ^ ((o >> 3) & 0x70); }

__device__ __forceinline__ float tf32f(float x) {
    uint32_t r; asm("cvt.rna.tf32.f32 %0, %1;" : "=r"(r) : "f"(x));
    return __uint_as_float(r);
}
__device__ __forceinline__ void mbar_init(uint32_t m, uint32_t c) {
    asm volatile("mbarrier.init.shared.b64 [%0], %1;" :: "r"(m), "r"(c) : "memory");
}
__device__ __forceinline__ void mbar_expect_tx(uint32_t m, uint32_t bytes) {
    asm volatile("mbarrier.arrive.expect_tx.shared.b64 _, [%0], %1;"
                 :: "r"(m), "r"(bytes) : "memory");
}
__device__ __forceinline__ void mbar_wait(uint32_t m, uint32_t parity) {
    asm volatile(
        "{\n\t.reg .pred P;\n"
        "LW_%=:\n\t"
        "mbarrier.try_wait.parity.acquire.cta.shared::cta.b64 P, [%0], %1, 0x989680;\n\t"
        "@P bra.uni LD_%=;\n\t"
        "bra.uni LW_%=;\n"
        "LD_%=:\n\t}"
        :: "r"(m), "r"(parity) : "memory");
}
__device__ __forceinline__ void bulk_g2s(uint32_t dst, const float* src,
                                         uint32_t bytes, uint32_t mbar) {
    asm volatile(
        "cp.async.bulk.shared::cluster.global.mbarrier::complete_tx::bytes "
        "[%0], [%1], %2, [%3];"
        :: "r"(dst), "l"(src), "r"(bytes), "r"(mbar) : "memory");
}
#define FENCE_ASYNC() asm volatile("fence.proxy.async.shared::cta;" ::: "memory")

// ldmatrix x4 (b16): loads 4 8x8 b16 matrices; fragment layout == tf32 b32 frags
__device__ __forceinline__ void ldm_x4(uint32_t* r, uint32_t addr) {
    asm volatile("ldmatrix.sync.aligned.m8n8.x4.shared.b16 {%0,%1,%2,%3}, [%4];"
                 : "=r"(r[0]), "=r"(r[1]), "=r"(r[2]), "=r"(r[3]) : "r"(addr));
}

__device__ __forceinline__ void mma8(float* c, const uint32_t* a, const uint32_t* b) {
    asm volatile(
        "mma.sync.aligned.m16n8k8.row.col.f32.tf32.tf32.f32 "
        "{%0,%1,%2,%3}, {%4,%5,%6,%7}, {%8,%9}, {%0,%1,%2,%3};"
        : "+f"(c[0]), "+f"(c[1]), "+f"(c[2]), "+f"(c[3])
        : "r"(a[0]), "r"(a[1]), "r"(a[2]), "r"(a[3]), "r"(b[0]), "r"(b[1]));
}
__device__ __forceinline__ float my_silu(float g) { return g / (1.0f + __expf(-g)); }

// ---------------- prep: pack x -------------------------------------------------
__global__ void pack_x_kernel(const float* __restrict__ x) {
    size_t idx = ((size_t)blockIdx.x * blockDim.x + threadIdx.x) * 4;
    float4 v = *reinterpret_cast<const float4*>(x + idx);
    v.x = tf32f(v.x); v.y = tf32f(v.y); v.z = tf32f(v.z); v.w = tf32f(v.w);
    int d = (int)(idx & (DD - 1));
    int t = (int)((idx / DD) & (TT - 1));
    int e = (int)(idx / ((size_t)TT * DD));
    int mt = t >> 7, r = t & 127, s = d >> 5, c = d & 31;
    float* dst = g_A1p + (((size_t)(e * 16 + mt) * 32 + s) << 12)
               + (swz128((uint32_t)(r * 128 + c * 4)) >> 2);
    *reinterpret_cast<float4*>(dst) = v;
}

// ---------------- prep: transpose + round + pack weights -----------------------
__global__ void transpose_pack_kernel(const float* __restrict__ in, float* __restrict__ out,
                                      int R, int C) {
    __shared__ float tsm[32][33];
    const int e = blockIdx.z;
    const float* ip = in + (size_t)e * R * C;
    const int c0 = blockIdx.x * 32, r0 = blockIdx.y * 32;
    const int tx = threadIdx.x, ty = threadIdx.y;
#pragma unroll
    for (int i = 0; i < 4; i++)
        tsm[ty + 8 * i][tx] = ip[(size_t)(r0 + ty + 8 * i) * C + c0 + tx];
    __syncthreads();
    const int NT = C >> 7, NSt = R >> 5;
    const int s = r0 >> 5;
#pragma unroll
    for (int i = 0; i < 4; i++) {
        int n = c0 + ty + 8 * i;
        int nt = n >> 7, nl = n & 127;
        float* bp = out + (((size_t)(e * NT + nt) * NSt + s) << 12);
        bp[swz128((uint32_t)(nl * 128 + tx * 4)) >> 2] = tf32f(tsm[tx][ty + 8 * i]);
    }
}

// =================================================================================
// GEMM1 fused: h = x@w1+b1 ; g = silu(x@wg+bg) ; og_packed = tf32(h*g)
// CTA 128x128 dual-plane, 256 thr (8 warps 2x4, warp 64x32).
// Kc=64 -> 16 stages; 2-stage ring, 96KB/stage, depth-1 TMA-bulk prefetch.
// Fragments via ldmatrix.x4.
// =================================================================================
#define G1_STG_B 98304
#define G1_SMEM (1024 + 2 * G1_STG_B)

__global__ void __launch_bounds__(256, 1)
gemm1_kernel(const float* __restrict__ bias1, const float* __restrict__ biasg) {
    extern __shared__ float sm[];
    const uint32_t sb = smem_u32(sm);
    const int tid = threadIdx.x, wid = tid >> 5, lane = tid & 31;
    const int gid = lane >> 2, tig = lane & 3;
    const int wr = wid >> 2, wc = wid & 3;          // 2x4 grid, warp tile 64x32
    const int bid = blockIdx.x;
    const int e = bid >> 9, nt = (bid >> 4) & 31, mt = bid & 15;  // mt innermost

    // ldmatrix per-lane address constants
    const int mq = lane >> 3, lr = lane & 7;
    const int rA = (mq & 1) * 8 + lr,  cA = (mq >> 1) * 16;  // A: row-block, col-block
    const int rB = (mq >> 1) * 8 + lr, cB = (mq & 1) * 16;   // B: n-block,  col-block

    const float* aS  = g_A1p + (((size_t)(e * 16 + mt) * 32) << 12);
    const float* b1S = g_B1p + (((size_t)(e * 32 + nt) * 32) << 12);
    const float* bgS = g_Bgp + (((size_t)(e * 32 + nt) * 32) << 12);

    float ah[4][4][4] = {}, ag[4][4][4] = {};       // 128 acc regs

    auto fillb = [&](int s) {
        const int b = s & 1;
        const uint32_t mb = sb + (uint32_t)b * 8;
        const uint32_t dst = sb + 1024 + (uint32_t)b * G1_STG_B;
        mbar_expect_tx(mb, G1_STG_B);
        bulk_g2s(dst,          aS  + ((size_t)(2 * s) << 12), 32768, mb);
        bulk_g2s(dst + 32768,  b1S + ((size_t)(2 * s) << 12), 32768, mb);
        bulk_g2s(dst + 65536,  bgS + ((size_t)(2 * s) << 12), 32768, mb);
    };

    if (tid == 0) {
        mbar_init(sb, 1); mbar_init(sb + 8, 1);
        FENCE_ASYNC();
        fillb(0);
    }

#pragma unroll 1
    for (int s = 0; s < 16; s++) {                   // K = 1024 / 64
        __syncthreads();
        if (tid == 0 && s + 1 < 16) { FENCE_ASYNC(); fillb(s + 1); }
        mbar_wait(sb + (uint32_t)(s & 1) * 8, (uint32_t)((s >> 1) & 1));

        const uint32_t dA  = sb + 1024 + (uint32_t)(s & 1) * G1_STG_B;
        const uint32_t dB1 = dA + 32768;
        const uint32_t dB2 = dA + 65536;

        uint32_t af[2][4][4], bf1[2][4][2], bf2[2][4][2];

        auto ldfr = [&](int ks, int pb) {
            const int kk = ks & 3;
            const uint32_t blk = (uint32_t)(ks >> 2) * 16384;
#pragma unroll
            for (int i = 0; i < 4; i++) {
                int row = wr * 64 + i * 16 + rA;
                uint32_t ad = dA + blk + (uint32_t)row * 128
                            + (uint32_t)((kk * 32 + cA) ^ ((row & 7) << 4));
                ldm_x4(af[pb][i], ad);
            }
#pragma unroll
            for (int jp = 0; jp < 2; jp++) {
                int n = wc * 32 + jp * 16 + rB;
                uint32_t off = blk + (uint32_t)n * 128
                             + (uint32_t)((kk * 32 + cB) ^ ((n & 7) << 4));
                ldm_x4(&bf1[pb][jp * 2][0], dB1 + off);
                ldm_x4(&bf2[pb][jp * 2][0], dB2 + off);
            }
        };

        ldfr(0, 0);
#pragma unroll
        for (int ks = 0; ks < 8; ks++) {
            const int cur = ks & 1;
            if (ks < 7) ldfr(ks + 1, cur ^ 1);
#pragma unroll
            for (int i = 0; i < 4; i++)
#pragma unroll
                for (int j = 0; j < 4; j++) {
                    mma8(ah[i][j], af[cur][i], bf1[cur][j]);
                    mma8(ag[i][j], af[cur][i], bf2[cur][j]);
                }
        }
    }

    // epilogue: og = tf32((h+b1)*silu(g+bg)) written PACKED for GEMM2
    const float* bp1 = bias1 + (size_t)e * HH + nt * 128;
    const float* bpg = biasg + (size_t)e * HH + nt * 128;
    const int s2 = nt * 4 + wc;
    float* blk = g_A2p + (((size_t)(e * 16 + mt) * 128 + s2) << 12);
#pragma unroll
    for (int i = 0; i < 4; i++)
#pragma unroll
        for (int j = 0; j < 4; j++) {
            int cl = wc * 32 + j * 8 + 2 * tig;
            float bh0 = bp1[cl], bh1 = bp1[cl + 1];
            float bg0 = bpg[cl], bg1 = bpg[cl + 1];
            int c2 = j * 8 + 2 * tig;
#pragma unroll
            for (int half = 0; half < 2; half++) {
                int rl = wr * 64 + i * 16 + gid + half * 8;
                float h0 = ah[i][j][2 * half]     + bh0;
                float h1 = ah[i][j][2 * half + 1] + bh1;
                float g0 = ag[i][j][2 * half]     + bg0;
                float g1 = ag[i][j][2 * half + 1] + bg1;
                float2 v = make_float2(tf32f(h0 * my_silu(g0)), tf32f(h1 * my_silu(g1)));
                *reinterpret_cast<float2*>(blk + (swz128((uint32_t)(rl * 128 + c2 * 4)) >> 2)) = v;
            }
        }
}

// =================================================================================
// GEMM2: out = og @ w2 + b2.  CTA 128x128, 256 thr, Kc=32, 3-stage ring, occ 2.
// Fragments via ldmatrix.x4.
// =================================================================================
#define G2_STG_B 32768
#define G2_SMEM (1024 + 3 * G2_STG_B)

__global__ void __launch_bounds__(256, 2)
gemm2_kernel(const float* __restrict__ bias2, float* __restrict__ out) {
    extern __shared__ float sm[];
    const uint32_t sb = smem_u32(sm);
    const int tid = threadIdx.x, wid = tid >> 5, lane = tid & 31;
    const int gid = lane >> 2, tig = lane & 3;
    const int wr = wid >> 2, wc = wid & 3;
    const int bid = blockIdx.x;
    const int e = bid >> 7, nt = (bid >> 4) & 7, mt = bid & 15;   // mt innermost

    const int mq = lane >> 3, lr = lane & 7;
    const int rA = (mq & 1) * 8 + lr,  cA = (mq >> 1) * 16;
    const int rB = (mq >> 1) * 8 + lr, cB = (mq & 1) * 16;

    const float* aS = g_A2p + (((size_t)(e * 16 + mt) * 128) << 12);
    const float* bS = g_B2p + (((size_t)(e * 8  + nt) * 128) << 12);

    float acc[4][4][4] = {};

    auto fillb = [&](int s, int b) {
        const uint32_t mb = sb + (uint32_t)b * 8;
        const uint32_t dst = sb + 1024 + (uint32_t)b * G2_STG_B;
        mbar_expect_tx(mb, G2_STG_B);
        bulk_g2s(dst,         aS + ((size_t)s << 12), 16384, mb);
        bulk_g2s(dst + 16384, bS + ((size_t)s << 12), 16384, mb);
    };

    if (tid == 0) {
#pragma unroll
        for (int b = 0; b < 3; b++) mbar_init(sb + b * 8, 1);
        FENCE_ASYNC();
        fillb(0, 0); fillb(1, 1);
    }

    int cb = 0, cph = 0, pb = 2;
#pragma unroll 1
    for (int s = 0; s < 128; s++) {
        __syncthreads();
        if (tid == 0 && s + 2 < 128) { FENCE_ASYNC(); fillb(s + 2, pb); }
        if (++pb == 3) pb = 0;
        mbar_wait(sb + (uint32_t)cb * 8, (uint32_t)cph);

        const uint32_t dA = sb + 1024 + (uint32_t)cb * G2_STG_B;
        const uint32_t dB = dA + 16384;
        if (++cb == 3) { cb = 0; cph ^= 1; }

#pragma unroll
        for (int ks = 0; ks < 4; ks++) {
            uint32_t af[4][4], bf[4][2];
#pragma unroll
            for (int i = 0; i < 4; i++) {
                int row = wr * 64 + i * 16 + rA;
                uint32_t ad = dA + (uint32_t)row * 128
                            + (uint32_t)((ks * 32 + cA) ^ ((row & 7) << 4));
                ldm_x4(af[i], ad);
            }
#pragma unroll
            for (int jp = 0; jp < 2; jp++) {
                int n = wc * 32 + jp * 16 + rB;
                uint32_t ad = dB + (uint32_t)n * 128
                            + (uint32_t)((ks * 32 + cB) ^ ((n & 7) << 4));
                ldm_x4(&bf[jp * 2][0], ad);
            }
#pragma unroll
            for (int i = 0; i < 4; i++)
#pragma unroll
                for (int j = 0; j < 4; j++)
                    mma8(acc[i][j], af[i], bf[j]);
        }
    }

    const int m0 = mt * 128 + wr * 64;
    const int n0 = nt * 128 + wc * 32;
    const float* bp2 = bias2 + (size_t)e * DD;
#pragma unroll
    for (int i = 0; i < 4; i++)
#pragma unroll
        for (int j = 0; j < 4; j++) {
            int col = n0 + j * 8 + 2 * tig;
            float b0 = bp2[col], b1 = bp2[col + 1];
#pragma unroll
            for (int half = 0; half < 2; half++) {
                int row = m0 + i * 16 + gid + half * 8;
                float2 v = make_float2(acc[i][j][2 * half] + b0, acc[i][j][2 * half + 1] + b1);
                *reinterpret_cast<float2*>(out + ((size_t)e * TT + row) * DD + col) = v;
            }
        }
}

// ---------------- launch ---------------------------------------------------------
extern "C" void kernel_launch(void* const* d_in, const int* in_sizes, int n_in,
                              void* d_out, int out_size) {
    const float* x  = (const float*)d_in[0];
    const float* w1 = (const float*)d_in[1];
    const float* b1 = (const float*)d_in[2];
    const float* wg = (const float*)d_in[3];
    const float* bg = (const float*)d_in[4];
    const float* w2 = (const float*)d_in[5];
    const float* b2 = (const float*)d_in[6];
    float* out = (float*)d_out;

    cudaFuncSetAttribute(gemm1_kernel, cudaFuncAttributeMaxDynamicSharedMemorySize, G1_SMEM);
    cudaFuncSetAttribute(gemm2_kernel, cudaFuncAttributeMaxDynamicSharedMemorySize, G2_SMEM);

    float *dB1p, *dBgp, *dB2p;
    cudaGetSymbolAddress((void**)&dB1p, g_B1p);
    cudaGetSymbolAddress((void**)&dBgp, g_Bgp);
    cudaGetSymbolAddress((void**)&dB2p, g_B2p);

    pack_x_kernel<<<(EE * TT * DD) / (256 * 4), 256>>>(x);
    dim3 tpb(32, 8);
    transpose_pack_kernel<<<dim3(HH / 32, DD / 32, EE), tpb>>>(w1, dB1p, DD, HH);
    transpose_pack_kernel<<<dim3(HH / 32, DD / 32, EE), tpb>>>(wg, dBgp, DD, HH);
    transpose_pack_kernel<<<dim3(DD / 32, HH / 32, EE), tpb>>>(w2, dB2p, HH, DD);

    gemm1_kernel<<<EE * 16 * 32, 256, G1_SMEM>>>(b1, bg);   // 4096 CTAs
    gemm2_kernel<<<EE * 16 * 8, 256, G2_SMEM>>>(b2, out);   // 1024 CTAs
}

// round 9
// speedup vs baseline: 1.4196x; 1.0408x over previous
#include <cuda_runtime.h>
#include <cstdint>

#define EE 8
#define TT 2048
#define DD 1024
#define HH 4096

// ---------------- packed device scratch (pre-swizzled 16KB [128x32] tiles) -----
__device__ __align__(1024) float g_A1p[(size_t)EE * TT * DD];
__device__ __align__(1024) float g_B1p[(size_t)EE * HH * DD];
__device__ __align__(1024) float g_Bgp[(size_t)EE * HH * DD];
__device__ __align__(1024) float g_B2p[(size_t)EE * DD * HH];
__device__ __align__(1024) float g_A2p[(size_t)EE * TT * HH];

// ---------------- helpers ------------------------------------------------------
__device__ __forceinline__ uint32_t smem_u32(const void* p) {
    uint32_t a;
    asm("{ .reg .u64 t; cvta.to.shared.u64 t, %1; cvt.u32.u64 %0, t; }" : "=r"(a) : "l"(p));
    return a;
}
__device__ __forceinline__ uint32_t swz128(uint32_t o) { return o ^ ((o >> 3) & 0x70); }

__device__ __forceinline__ float tf32f(float x) {
    uint32_t r; asm("cvt.rna.tf32.f32 %0, %1;" : "=r"(r) : "f"(x));
    return __uint_as_float(r);
}
__device__ __forceinline__ void mbar_init(uint32_t m, uint32_t c) {
    asm volatile("mbarrier.init.shared.b64 [%0], %1;" :: "r"(m), "r"(c) : "memory");
}
__device__ __forceinline__ void mbar_expect_tx(uint32_t m, uint32_t bytes) {
    asm volatile("mbarrier.arrive.expect_tx.shared.b64 _, [%0], %1;"
                 :: "r"(m), "r"(bytes) : "memory");
}
__device__ __forceinline__ void mbar_wait(uint32_t m, uint32_t parity) {
    asm volatile(
        "{\n\t.reg .pred P;\n"
        "LW_%=:\n\t"
        "mbarrier.try_wait.parity.acquire.cta.shared::cta.b64 P, [%0], %1, 0x989680;\n\t"
        "@P bra.uni LD_%=;\n\t"
        "bra.uni LW_%=;\n"
        "LD_%=:\n\t}"
        :: "r"(m), "r"(parity) : "memory");
}
__device__ __forceinline__ void bulk_g2s(uint32_t dst, const float* src,
                                         uint32_t bytes, uint32_t mbar) {
    asm volatile(
        "cp.async.bulk.shared::cluster.global.mbarrier::complete_tx::bytes "
        "[%0], [%1], %2, [%3];"
        :: "r"(dst), "l"(src), "r"(bytes), "r"(mbar) : "memory");
}
#define FENCE_ASYNC() asm volatile("fence.proxy.async.shared::cta;" ::: "memory")

__device__ __forceinline__ void ldm_x4(uint32_t* r, uint32_t addr) {
    asm volatile("ldmatrix.sync.aligned.m8n8.x4.shared.b16 {%0,%1,%2,%3}, [%4];"
                 : "=r"(r[0]), "=r"(r[1]), "=r"(r[2]), "=r"(r[3]) : "r"(addr));
}
__device__ __forceinline__ void mma8(float* c, const uint32_t* a, const uint32_t* b) {
    asm volatile(
        "mma.sync.aligned.m16n8k8.row.col.f32.tf32.tf32.f32 "
        "{%0,%1,%2,%3}, {%4,%5,%6,%7}, {%8,%9}, {%0,%1,%2,%3};"
        : "+f"(c[0]), "+f"(c[1]), "+f"(c[2]), "+f"(c[3])
        : "r"(a[0]), "r"(a[1]), "r"(a[2]), "r"(a[3]), "r"(b[0]), "r"(b[1]));
}
__device__ __forceinline__ float my_silu(float g) { return g / (1.0f + __expf(-g)); }

// ---------------- prep: pack x -------------------------------------------------
__global__ void pack_x_kernel(const float* __restrict__ x) {
    size_t idx = ((size_t)blockIdx.x * blockDim.x + threadIdx.x) * 4;
    float4 v = *reinterpret_cast<const float4*>(x + idx);
    v.x = tf32f(v.x); v.y = tf32f(v.y); v.z = tf32f(v.z); v.w = tf32f(v.w);
    int d = (int)(idx & (DD - 1));
    int t = (int)((idx / DD) & (TT - 1));
    int e = (int)(idx / ((size_t)TT * DD));
    int mt = t >> 7, r = t & 127, s = d >> 5, c = d & 31;
    float* dst = g_A1p + (((size_t)(e * 16 + mt) * 32 + s) << 12)
               + (swz128((uint32_t)(r * 128 + c * 4)) >> 2);
    *reinterpret_cast<float4*>(dst) = v;
}

// ---------------- prep: vectorized transpose + round + pack --------------------
// 32(k-rows) x 128(n-cols) tile per block == exactly one packed 16KB output block.
__global__ void transpose_pack_kernel(const float* __restrict__ in, float* __restrict__ out,
                                      int R, int C) {
    __shared__ float tsm[32][133];
    const int e = blockIdx.z;
    const float* ip = in + (size_t)e * R * C;
    const int c0 = blockIdx.x * 128, r0 = blockIdx.y * 32;
    const int tid = threadIdx.x;
    const int lrow = tid >> 5, lc4 = tid & 31;          // load: row, float4-col
#pragma unroll
    for (int it = 0; it < 4; it++) {
        int r = lrow + 8 * it;
        float4 v = *reinterpret_cast<const float4*>(ip + (size_t)(r0 + r) * C + c0 + lc4 * 4);
        tsm[r][lc4 * 4 + 0] = tf32f(v.x);
        tsm[r][lc4 * 4 + 1] = tf32f(v.y);
        tsm[r][lc4 * 4 + 2] = tf32f(v.z);
        tsm[r][lc4 * 4 + 3] = tf32f(v.w);
    }
    __syncthreads();
    const int NT = C >> 7, NSt = R >> 5;
    const int s = r0 >> 5, nt = c0 >> 7;
    float* bp = out + (((size_t)(e * NT + nt) * NSt + s) << 12);
    const int kkc = tid & 7, nlb = tid >> 3;            // store: k-chunk, n-row base
#pragma unroll
    for (int it = 0; it < 4; it++) {
        int nl = nlb + 32 * it;
        float4 v;
        v.x = tsm[kkc * 4 + 0][nl];
        v.y = tsm[kkc * 4 + 1][nl];
        v.z = tsm[kkc * 4 + 2][nl];
        v.w = tsm[kkc * 4 + 3][nl];
        *reinterpret_cast<float4*>(bp + (swz128((uint32_t)(nl * 128 + kkc * 16)) >> 2)) = v;
    }
}

// =================================================================================
// GEMM1 fused (PERSISTENT): h = x@w1+b1 ; g = silu(x@wg+bg) ; og_packed = tf32(h*g)
// CTA 128x128 dual-plane, 256 thr (8 warps 2x4, warp 64x32). Kc=64, 16 stages/tile,
// 2-stage ring (96KB/stage) that NEVER drains across tiles.
// =================================================================================
#define G1_STG_B 98304
#define G1_SMEM (1024 + 2 * G1_STG_B)
#define NT1 (EE * 16 * 32)      // 4096 tiles

__global__ void __launch_bounds__(256, 1)
gemm1_kernel(const float* __restrict__ bias1, const float* __restrict__ biasg) {
    extern __shared__ float sm[];
    const uint32_t sb = smem_u32(sm);
    const int tid = threadIdx.x, wid = tid >> 5, lane = tid & 31;
    const int gid = lane >> 2, tig = lane & 3;
    const int wr = wid >> 2, wc = wid & 3;
    const int t0 = blockIdx.x, gstride = gridDim.x;

    const int mq = lane >> 3, lr = lane & 7;
    const int rA = (mq & 1) * 8 + lr,  cA = (mq >> 1) * 16;
    const int rB = (mq >> 1) * 8 + lr, cB = (mq & 1) * 16;

    float ah[4][4][4] = {}, ag[4][4][4] = {};

    // fill global-stage gsx (= local tile index * 16 + stage)
    auto fillb = [&](int gsx) {
        const int lt = gsx >> 4, s = gsx & 15;
        const int tile = t0 + lt * gstride;
        const int e = tile >> 9, nt = (tile >> 4) & 31, mtt = tile & 15;
        const float* aS  = g_A1p + (((size_t)(e * 16 + mtt) * 32) << 12);
        const float* b1S = g_B1p + (((size_t)(e * 32 + nt) * 32) << 12);
        const float* bgS = g_Bgp + (((size_t)(e * 32 + nt) * 32) << 12);
        const int b = gsx & 1;
        const uint32_t mb = sb + (uint32_t)b * 8;
        const uint32_t dst = sb + 1024 + (uint32_t)b * G1_STG_B;
        mbar_expect_tx(mb, G1_STG_B);
        bulk_g2s(dst,          aS  + ((size_t)(2 * s) << 12), 32768, mb);
        bulk_g2s(dst + 32768,  b1S + ((size_t)(2 * s) << 12), 32768, mb);
        bulk_g2s(dst + 65536,  bgS + ((size_t)(2 * s) << 12), 32768, mb);
    };

    if (tid == 0) {
        mbar_init(sb, 1); mbar_init(sb + 8, 1);
        FENCE_ASYNC();
        fillb(0);
    }

    int gs = 0;
#pragma unroll 1
    for (int tile = t0; tile < NT1; tile += gstride) {
#pragma unroll 1
        for (int s = 0; s < 16; s++, gs++) {
            __syncthreads();
            if (tid == 0) {
                int ngs = gs + 1;
                if (t0 + (ngs >> 4) * gstride < NT1) { FENCE_ASYNC(); fillb(ngs); }
            }
            mbar_wait(sb + (uint32_t)(gs & 1) * 8, (uint32_t)((gs >> 1) & 1));

            const uint32_t dA  = sb + 1024 + (uint32_t)(gs & 1) * G1_STG_B;
            const uint32_t dB1 = dA + 32768;
            const uint32_t dB2 = dA + 65536;

            uint32_t af[2][4][4], bf1[2][4][2], bf2[2][4][2];

            auto ldfr = [&](int ks, int pb) {
                const int kk = ks & 3;
                const uint32_t blk = (uint32_t)(ks >> 2) * 16384;
#pragma unroll
                for (int i = 0; i < 4; i++) {
                    int row = wr * 64 + i * 16 + rA;
                    uint32_t ad = dA + blk + (uint32_t)row * 128
                                + (uint32_t)((kk * 32 + cA) ^ ((row & 7) << 4));
                    ldm_x4(af[pb][i], ad);
                }
#pragma unroll
                for (int jp = 0; jp < 2; jp++) {
                    int n = wc * 32 + jp * 16 + rB;
                    uint32_t off = blk + (uint32_t)n * 128
                                 + (uint32_t)((kk * 32 + cB) ^ ((n & 7) << 4));
                    ldm_x4(&bf1[pb][jp * 2][0], dB1 + off);
                    ldm_x4(&bf2[pb][jp * 2][0], dB2 + off);
                }
            };

            ldfr(0, 0);
#pragma unroll
            for (int ks = 0; ks < 8; ks++) {
                const int cur = ks & 1;
                if (ks < 7) ldfr(ks + 1, cur ^ 1);
#pragma unroll
                for (int i = 0; i < 4; i++)
#pragma unroll
                    for (int j = 0; j < 4; j++) {
                        mma8(ah[i][j], af[cur][i], bf1[cur][j]);
                        mma8(ag[i][j], af[cur][i], bf2[cur][j]);
                    }
            }
        }

        // epilogue for this tile (TMA for next tile already streaming)
        const int e = tile >> 9, nt = (tile >> 4) & 31, mtt = tile & 15;
        const float* bp1 = bias1 + (size_t)e * HH + nt * 128;
        const float* bpg = biasg + (size_t)e * HH + nt * 128;
        const int s2 = nt * 4 + wc;
        float* blk = g_A2p + (((size_t)(e * 16 + mtt) * 128 + s2) << 12);
#pragma unroll
        for (int i = 0; i < 4; i++)
#pragma unroll
            for (int j = 0; j < 4; j++) {
                int cl = wc * 32 + j * 8 + 2 * tig;
                float bh0 = bp1[cl], bh1 = bp1[cl + 1];
                float bg0 = bpg[cl], bg1 = bpg[cl + 1];
                int c2 = j * 8 + 2 * tig;
#pragma unroll
                for (int half = 0; half < 2; half++) {
                    int rl = wr * 64 + i * 16 + gid + half * 8;
                    float h0 = ah[i][j][2 * half]     + bh0;
                    float h1 = ah[i][j][2 * half + 1] + bh1;
                    float g0 = ag[i][j][2 * half]     + bg0;
                    float g1 = ag[i][j][2 * half + 1] + bg1;
                    float2 v = make_float2(tf32f(h0 * my_silu(g0)), tf32f(h1 * my_silu(g1)));
                    *reinterpret_cast<float2*>(blk + (swz128((uint32_t)(rl * 128 + c2 * 4)) >> 2)) = v;
                }
            }
        // clear accumulators for next tile
#pragma unroll
        for (int i = 0; i < 4; i++)
#pragma unroll
            for (int j = 0; j < 4; j++)
#pragma unroll
                for (int k2 = 0; k2 < 4; k2++) { ah[i][j][k2] = 0.f; ag[i][j][k2] = 0.f; }
    }
}

// =================================================================================
// GEMM2 (PERSISTENT): out = og @ w2 + b2.  CTA 128x128, 256 thr, Kc=32,
// 128 stages/tile, 3-stage ring that never drains, occupancy 2.
// =================================================================================
#define G2_STG_B 32768
#define G2_SMEM (1024 + 3 * G2_STG_B)
#define NT2 (EE * 16 * 8)       // 1024 tiles

__global__ void __launch_bounds__(256, 2)
gemm2_kernel(const float* __restrict__ bias2, float* __restrict__ out) {
    extern __shared__ float sm[];
    const uint32_t sb = smem_u32(sm);
    const int tid = threadIdx.x, wid = tid >> 5, lane = tid & 31;
    const int gid = lane >> 2, tig = lane & 3;
    const int wr = wid >> 2, wc = wid & 3;
    const int t0 = blockIdx.x, gstride = gridDim.x;

    const int mq = lane >> 3, lr = lane & 7;
    const int rA = (mq & 1) * 8 + lr,  cA = (mq >> 1) * 16;
    const int rB = (mq >> 1) * 8 + lr, cB = (mq & 1) * 16;

    float acc[4][4][4] = {};

    auto fillb = [&](int gsx) {                 // gsx = local tile * 128 + stage
        const int lt = gsx >> 7, s = gsx & 127;
        const int tile = t0 + lt * gstride;
        const int e = tile >> 7, nt = (tile >> 4) & 7, mtt = tile & 15;
        const float* aS = g_A2p + (((size_t)(e * 16 + mtt) * 128) << 12);
        const float* bS = g_B2p + (((size_t)(e * 8  + nt) * 128) << 12);
        int b = gsx - (gsx / 3) * 3;
        const uint32_t mb = sb + (uint32_t)b * 8;
        const uint32_t dst = sb + 1024 + (uint32_t)b * G2_STG_B;
        mbar_expect_tx(mb, G2_STG_B);
        bulk_g2s(dst,         aS + ((size_t)s << 12), 16384, mb);
        bulk_g2s(dst + 16384, bS + ((size_t)s << 12), 16384, mb);
    };

    if (tid == 0) {
#pragma unroll
        for (int b = 0; b < 3; b++) mbar_init(sb + b * 8, 1);
        FENCE_ASYNC();
        fillb(0); fillb(1);
    }

    int gs = 0, cb = 0, cph = 0;
#pragma unroll 1
    for (int tile = t0; tile < NT2; tile += gstride) {
#pragma unroll 1
        for (int s = 0; s < 128; s++, gs++) {
            __syncthreads();
            if (tid == 0) {
                int ngs = gs + 2;
                if (t0 + (ngs >> 7) * gstride < NT2) { FENCE_ASYNC(); fillb(ngs); }
            }
            mbar_wait(sb + (uint32_t)cb * 8, (uint32_t)cph);

            const uint32_t dA = sb + 1024 + (uint32_t)cb * G2_STG_B;
            const uint32_t dB = dA + 16384;
            if (++cb == 3) { cb = 0; cph ^= 1; }

#pragma unroll
            for (int ks = 0; ks < 4; ks++) {
                uint32_t af[4][4], bf[4][2];
#pragma unroll
                for (int i = 0; i < 4; i++) {
                    int row = wr * 64 + i * 16 + rA;
                    uint32_t ad = dA + (uint32_t)row * 128
                                + (uint32_t)((ks * 32 + cA) ^ ((row & 7) << 4));
                    ldm_x4(af[i], ad);
                }
#pragma unroll
                for (int jp = 0; jp < 2; jp++) {
                    int n = wc * 32 + jp * 16 + rB;
                    uint32_t ad = dB + (uint32_t)n * 128
                                + (uint32_t)((ks * 32 + cB) ^ ((n & 7) << 4));
                    ldm_x4(&bf[jp * 2][0], ad);
                }
#pragma unroll
                for (int i = 0; i < 4; i++)
#pragma unroll
                    for (int j = 0; j < 4; j++)
                        mma8(acc[i][j], af[i], bf[j]);
            }
        }

        const int e = tile >> 7, nt = (tile >> 4) & 7, mtt = tile & 15;
        const int m0 = mtt * 128 + wr * 64;
        const int n0 = nt * 128 + wc * 32;
        const float* bp2 = bias2 + (size_t)e * DD;
#pragma unroll
        for (int i = 0; i < 4; i++)
#pragma unroll
            for (int j = 0; j < 4; j++) {
                int col = n0 + j * 8 + 2 * tig;
                float b0 = bp2[col], b1 = bp2[col + 1];
#pragma unroll
                for (int half = 0; half < 2; half++) {
                    int row = m0 + i * 16 + gid + half * 8;
                    float2 v = make_float2(acc[i][j][2 * half] + b0, acc[i][j][2 * half + 1] + b1);
                    *reinterpret_cast<float2*>(out + ((size_t)e * TT + row) * DD + col) = v;
                }
            }
#pragma unroll
        for (int i = 0; i < 4; i++)
#pragma unroll
            for (int j = 0; j < 4; j++)
#pragma unroll
                for (int k2 = 0; k2 < 4; k2++) acc[i][j][k2] = 0.f;
    }
}

// ---------------- launch ---------------------------------------------------------
extern "C" void kernel_launch(void* const* d_in, const int* in_sizes, int n_in,
                              void* d_out, int out_size) {
    const float* x  = (const float*)d_in[0];
    const float* w1 = (const float*)d_in[1];
    const float* b1 = (const float*)d_in[2];
    const float* wg = (const float*)d_in[3];
    const float* bg = (const float*)d_in[4];
    const float* w2 = (const float*)d_in[5];
    const float* b2 = (const float*)d_in[6];
    float* out = (float*)d_out;

    cudaFuncSetAttribute(gemm1_kernel, cudaFuncAttributeMaxDynamicSharedMemorySize, G1_SMEM);
    cudaFuncSetAttribute(gemm2_kernel, cudaFuncAttributeMaxDynamicSharedMemorySize, G2_SMEM);

    int smc = 0;
    if (cudaDeviceGetAttribute(&smc, cudaDevAttrMultiProcessorCount, 0) != cudaSuccess || smc <= 0)
        smc = 148;

    float *dB1p, *dBgp, *dB2p;
    cudaGetSymbolAddress((void**)&dB1p, g_B1p);
    cudaGetSymbolAddress((void**)&dBgp, g_Bgp);
    cudaGetSymbolAddress((void**)&dB2p, g_B2p);

    pack_x_kernel<<<(EE * TT * DD) / (256 * 4), 256>>>(x);
    transpose_pack_kernel<<<dim3(HH / 128, DD / 32, EE), 256>>>(w1, dB1p, DD, HH);
    transpose_pack_kernel<<<dim3(HH / 128, DD / 32, EE), 256>>>(wg, dBgp, DD, HH);
    transpose_pack_kernel<<<dim3(DD / 128, HH / 32, EE), 256>>>(w2, dB2p, HH, DD);

    gemm1_kernel<<<smc, 256, G1_SMEM>>>(b1, bg);          // persistent, 4096 tiles
    gemm2_kernel<<<2 * smc, 256, G2_SMEM>>>(b2, out);     // persistent, 1024 tiles
}

// round 10
// speedup vs baseline: 2.3999x; 1.6905x over previous
#include <cuda_runtime.h>
#include <cuda_fp16.h>
#include <cstdint>

#define EE 8
#define TT 2048
#define DD 1024
#define HH 4096

// ---------------- packed half scratch (pre-swizzled 16KB [128 x 64h] blocks) ---
__device__ __align__(1024) __half g_A1p[(size_t)EE * TT * DD]; // x      [e][mt][16 blk]
__device__ __align__(1024) __half g_B1p[(size_t)EE * HH * DD]; // w1^T   [e][nt32][16 blk]
__device__ __align__(1024) __half g_Bgp[(size_t)EE * HH * DD]; // wg^T
__device__ __align__(1024) __half g_B2p[(size_t)EE * DD * HH]; // w2^T   [e][nt8][64 blk]
__device__ __align__(1024) __half g_A2p[(size_t)EE * TT * HH]; // og     [e][mt][64 blk]

// ---------------- helpers ------------------------------------------------------
__device__ __forceinline__ uint32_t smem_u32(const void* p) {
    uint32_t a;
    asm("{ .reg .u64 t; cvta.to.shared.u64 t, %1; cvt.u32.u64 %0, t; }" : "=r"(a) : "l"(p));
    return a;
}
__device__ __forceinline__ uint32_t swz128(uint32_t o) { return o ^ ((o >> 3) & 0x70); }

__device__ __forceinline__ void mbar_init(uint32_t m, uint32_t c) {
    asm volatile("mbarrier.init.shared.b64 [%0], %1;" :: "r"(m), "r"(c) : "memory");
}
__device__ __forceinline__ void mbar_expect_tx(uint32_t m, uint32_t bytes) {
    asm volatile("mbarrier.arrive.expect_tx.shared.b64 _, [%0], %1;"
                 :: "r"(m), "r"(bytes) : "memory");
}
__device__ __forceinline__ void mbar_wait(uint32_t m, uint32_t parity) {
    asm volatile(
        "{\n\t.reg .pred P;\n"
        "LW_%=:\n\t"
        "mbarrier.try_wait.parity.acquire.cta.shared::cta.b64 P, [%0], %1, 0x989680;\n\t"
        "@P bra.uni LD_%=;\n\t"
        "bra.uni LW_%=;\n"
        "LD_%=:\n\t}"
        :: "r"(m), "r"(parity) : "memory");
}
__device__ __forceinline__ void bulk_g2s(uint32_t dst, const void* src,
                                         uint32_t bytes, uint32_t mbar) {
    asm volatile(
        "cp.async.bulk.shared::cluster.global.mbarrier::complete_tx::bytes "
        "[%0], [%1], %2, [%3];"
        :: "r"(dst), "l"(src), "r"(bytes), "r"(mbar) : "memory");
}
#define FENCE_ASYNC() asm volatile("fence.proxy.async.shared::cta;" ::: "memory")

__device__ __forceinline__ void ldm_x4(uint32_t* r, uint32_t addr) {
    asm volatile("ldmatrix.sync.aligned.m8n8.x4.shared.b16 {%0,%1,%2,%3}, [%4];"
                 : "=r"(r[0]), "=r"(r[1]), "=r"(r[2]), "=r"(r[3]) : "r"(addr));
}
// f16 m16n8k16, f32 accumulate
__device__ __forceinline__ void mma16(float* c, const uint32_t* a, const uint32_t* b) {
    asm volatile(
        "mma.sync.aligned.m16n8k16.row.col.f32.f16.f16.f32 "
        "{%0,%1,%2,%3}, {%4,%5,%6,%7}, {%8,%9}, {%0,%1,%2,%3};"
        : "+f"(c[0]), "+f"(c[1]), "+f"(c[2]), "+f"(c[3])
        : "r"(a[0]), "r"(a[1]), "r"(a[2]), "r"(a[3]), "r"(b[0]), "r"(b[1]));
}
__device__ __forceinline__ float my_silu(float g) { return g / (1.0f + __expf(-g)); }

__device__ __forceinline__ uint32_t h2u(__half2 h) {
    return *reinterpret_cast<uint32_t*>(&h);
}

// ---------------- prep: pack x to half blocks ----------------------------------
__global__ void pack_x_kernel(const float* __restrict__ x) {
    size_t idx = ((size_t)blockIdx.x * blockDim.x + threadIdx.x) * 4;
    float4 v = *reinterpret_cast<const float4*>(x + idx);
    int d = (int)(idx & (DD - 1));
    int t = (int)((idx / DD) & (TT - 1));
    int e = (int)(idx / ((size_t)TT * DD));
    int mt = t >> 7, r = t & 127, bd = d >> 6, c = d & 63;
    char* blk = (char*)(g_A1p + (((size_t)(e * 16 + mt) * 16 + bd) << 13));
    uint2 u;
    u.x = h2u(__floats2half2_rn(v.x, v.y));
    u.y = h2u(__floats2half2_rn(v.z, v.w));
    *reinterpret_cast<uint2*>(blk + swz128((uint32_t)(r * 128 + c * 2))) = u;
}

// ---------------- prep: transpose f32 -> packed half blocks --------------------
// input tile: 64 k-rows x 128 n-cols  ==  one output block [128 n x 64 k-halves]
__global__ void transpose_pack_kernel(const float* __restrict__ in, __half* __restrict__ out,
                                      int R, int C) {
    __shared__ __half tsm[64][136];
    const int e = blockIdx.z;
    const float* ip = in + (size_t)e * R * C;
    const int c0 = blockIdx.x * 128, r0 = blockIdx.y * 64;
    const int tid = threadIdx.x;
    const int lrow = tid >> 5, lc4 = tid & 31;
#pragma unroll
    for (int it = 0; it < 8; it++) {
        int r = lrow + 8 * it;
        float4 v = *reinterpret_cast<const float4*>(ip + (size_t)(r0 + r) * C + c0 + lc4 * 4);
        uint2 u;
        u.x = h2u(__floats2half2_rn(v.x, v.y));
        u.y = h2u(__floats2half2_rn(v.z, v.w));
        *reinterpret_cast<uint2*>(&tsm[r][lc4 * 4]) = u;
    }
    __syncthreads();
    const int NT = C >> 7, NKB = R >> 6;
    const int nt = blockIdx.x, kb = blockIdx.y;
    char* bp = (char*)(out + (((size_t)(e * NT + nt) * NKB + kb) << 13));
    const int kc = tid & 7, nlb = tid >> 3;
#pragma unroll
    for (int it = 0; it < 4; it++) {
        int nl = nlb + 32 * it;
        uint4 u;
        u.x = h2u(__halves2half2(tsm[kc * 8 + 0][nl], tsm[kc * 8 + 1][nl]));
        u.y = h2u(__halves2half2(tsm[kc * 8 + 2][nl], tsm[kc * 8 + 3][nl]));
        u.z = h2u(__halves2half2(tsm[kc * 8 + 4][nl], tsm[kc * 8 + 5][nl]));
        u.w = h2u(__halves2half2(tsm[kc * 8 + 6][nl], tsm[kc * 8 + 7][nl]));
        *reinterpret_cast<uint4*>(bp + swz128((uint32_t)(nl * 128 + kc * 16))) = u;
    }
}

// =================================================================================
// GEMM1 fused (persistent): h = x@w1+b1 ; g = silu(x@wg+bg) ; og_packed = h16(h*g)
// CTA 128x128 dual-plane, 256 thr (8 warps 2x4, warp 64x32). f16 m16n8k16.
// Kc=128 -> 8 stages/tile; 2-stage ring (96KB/stage) that never drains.
// =================================================================================
#define G1_STG_B 98304
#define G1_SMEM (1024 + 2 * G1_STG_B)
#define NT1 (EE * 16 * 32)

__global__ void __launch_bounds__(256, 1)
gemm1_kernel(const float* __restrict__ bias1, const float* __restrict__ biasg) {
    extern __shared__ float sm[];
    const uint32_t sb = smem_u32(sm);
    const int tid = threadIdx.x, wid = tid >> 5, lane = tid & 31;
    const int gid = lane >> 2, tig = lane & 3;
    const int wr = wid >> 2, wc = wid & 3;
    const int t0 = blockIdx.x, gstride = gridDim.x;

    const int mq = lane >> 3, lr = lane & 7;
    const int rA = (mq & 1) * 8 + lr,  cA = (mq >> 1) * 16;
    const int rB = (mq >> 1) * 8 + lr, cB = (mq & 1) * 16;

    float ah[4][4][4] = {}, ag[4][4][4] = {};

    auto fillb = [&](int gsx) {                       // gsx = local tile*8 + stage
        const int lt = gsx >> 3, s = gsx & 7;
        const int tile = t0 + lt * gstride;
        const int e = tile >> 9, nt = (tile >> 4) & 31, mtt = tile & 15;
        const __half* aS  = g_A1p + (((size_t)(e * 16 + mtt) * 16 + 2 * s) << 13);
        const __half* b1S = g_B1p + (((size_t)(e * 32 + nt) * 16 + 2 * s) << 13);
        const __half* bgS = g_Bgp + (((size_t)(e * 32 + nt) * 16 + 2 * s) << 13);
        const int b = gsx & 1;
        const uint32_t mb = sb + (uint32_t)b * 8;
        const uint32_t dst = sb + 1024 + (uint32_t)b * G1_STG_B;
        mbar_expect_tx(mb, G1_STG_B);
        bulk_g2s(dst,          aS,  32768, mb);
        bulk_g2s(dst + 32768,  b1S, 32768, mb);
        bulk_g2s(dst + 65536,  bgS, 32768, mb);
    };

    if (tid == 0) {
        mbar_init(sb, 1); mbar_init(sb + 8, 1);
        FENCE_ASYNC();
        fillb(0);
    }

    int gs = 0;
#pragma unroll 1
    for (int tile = t0; tile < NT1; tile += gstride) {
#pragma unroll 1
        for (int s = 0; s < 8; s++, gs++) {
            __syncthreads();
            if (tid == 0) {
                int ngs = gs + 1;
                if (t0 + (ngs >> 3) * gstride < NT1) { FENCE_ASYNC(); fillb(ngs); }
            }
            mbar_wait(sb + (uint32_t)(gs & 1) * 8, (uint32_t)((gs >> 1) & 1));

            const uint32_t dA  = sb + 1024 + (uint32_t)(gs & 1) * G1_STG_B;
            const uint32_t dB1 = dA + 32768;
            const uint32_t dB2 = dA + 65536;

            uint32_t af[2][4][4], bf1[2][4][2], bf2[2][4][2];

            auto ldfr = [&](int ks, int pb) {
                const int kk = ks & 3;
                const uint32_t blk = (uint32_t)(ks >> 2) * 16384;
#pragma unroll
                for (int i = 0; i < 4; i++) {
                    int row = wr * 64 + i * 16 + rA;
                    uint32_t ad = dA + blk + (uint32_t)row * 128
                                + (uint32_t)((kk * 32 + cA) ^ ((row & 7) << 4));
                    ldm_x4(af[pb][i], ad);
                }
#pragma unroll
                for (int jp = 0; jp < 2; jp++) {
                    int n = wc * 32 + jp * 16 + rB;
                    uint32_t off = blk + (uint32_t)n * 128
                                 + (uint32_t)((kk * 32 + cB) ^ ((n & 7) << 4));
                    ldm_x4(&bf1[pb][jp * 2][0], dB1 + off);
                    ldm_x4(&bf2[pb][jp * 2][0], dB2 + off);
                }
            };

            ldfr(0, 0);
#pragma unroll
            for (int ks = 0; ks < 8; ks++) {
                const int cur = ks & 1;
                if (ks < 7) ldfr(ks + 1, cur ^ 1);
#pragma unroll
                for (int i = 0; i < 4; i++)
#pragma unroll
                    for (int j = 0; j < 4; j++) {
                        mma16(ah[i][j], af[cur][i], bf1[cur][j]);
                        mma16(ag[i][j], af[cur][i], bf2[cur][j]);
                    }
            }
        }

        // epilogue: og = h16((h+b1)*silu(g+bg)) -> packed half blocks for GEMM2
        const int e = tile >> 9, nt = (tile >> 4) & 31, mtt = tile & 15;
        const float* bp1 = bias1 + (size_t)e * HH + nt * 128;
        const float* bpg = biasg + (size_t)e * HH + nt * 128;
        const int b2 = nt * 2 + (wc >> 1);            // og k-block (64 halves each)
        char* blk = (char*)(g_A2p + (((size_t)(e * 16 + mtt) * 64 + b2) << 13));
#pragma unroll
        for (int i = 0; i < 4; i++)
#pragma unroll
            for (int j = 0; j < 4; j++) {
                int cl = wc * 32 + j * 8 + 2 * tig;   // col within 128-tile
                float bh0 = bp1[cl], bh1 = bp1[cl + 1];
                float bg0 = bpg[cl], bg1 = bpg[cl + 1];
                int kh = (wc & 1) * 32 + j * 8 + 2 * tig;  // k-half within block
#pragma unroll
                for (int half = 0; half < 2; half++) {
                    int rl = wr * 64 + i * 16 + gid + half * 8;
                    float h0 = ah[i][j][2 * half]     + bh0;
                    float h1 = ah[i][j][2 * half + 1] + bh1;
                    float g0 = ag[i][j][2 * half]     + bg0;
                    float g1 = ag[i][j][2 * half + 1] + bg1;
                    uint32_t u = h2u(__floats2half2_rn(h0 * my_silu(g0), h1 * my_silu(g1)));
                    *reinterpret_cast<uint32_t*>(
                        blk + swz128((uint32_t)(rl * 128 + kh * 2))) = u;
                }
            }
#pragma unroll
        for (int i = 0; i < 4; i++)
#pragma unroll
            for (int j = 0; j < 4; j++)
#pragma unroll
                for (int k2 = 0; k2 < 4; k2++) { ah[i][j][k2] = 0.f; ag[i][j][k2] = 0.f; }
    }
}

// =================================================================================
// GEMM2 (persistent): out = og @ w2 + b2.  CTA 128x128, 256 thr, f16 m16n8k16,
// Kc=64 -> 64 stages/tile, 3-stage ring (32KB/stage), occupancy 2.
// =================================================================================
#define G2_STG_B 32768
#define G2_SMEM (1024 + 3 * G2_STG_B)
#define NT2 (EE * 16 * 8)

__global__ void __launch_bounds__(256, 2)
gemm2_kernel(const float* __restrict__ bias2, float* __restrict__ out) {
    extern __shared__ float sm[];
    const uint32_t sb = smem_u32(sm);
    const int tid = threadIdx.x, wid = tid >> 5, lane = tid & 31;
    const int gid = lane >> 2, tig = lane & 3;
    const int wr = wid >> 2, wc = wid & 3;
    const int t0 = blockIdx.x, gstride = gridDim.x;

    const int mq = lane >> 3, lr = lane & 7;
    const int rA = (mq & 1) * 8 + lr,  cA = (mq >> 1) * 16;
    const int rB = (mq >> 1) * 8 + lr, cB = (mq & 1) * 16;

    float acc[4][4][4] = {};

    auto fillb = [&](int gsx) {                       // gsx = local tile*64 + stage
        const int lt = gsx >> 6, s = gsx & 63;
        const int tile = t0 + lt * gstride;
        const int e = tile >> 7, nt = (tile >> 4) & 7, mtt = tile & 15;
        const __half* aS = g_A2p + (((size_t)(e * 16 + mtt) * 64 + s) << 13);
        const __half* bS = g_B2p + (((size_t)(e * 8  + nt) * 64 + s) << 13);
        int b = gsx - (gsx / 3) * 3;
        const uint32_t mb = sb + (uint32_t)b * 8;
        const uint32_t dst = sb + 1024 + (uint32_t)b * G2_STG_B;
        mbar_expect_tx(mb, G2_STG_B);
        bulk_g2s(dst,         aS, 16384, mb);
        bulk_g2s(dst + 16384, bS, 16384, mb);
    };

    if (tid == 0) {
#pragma unroll
        for (int b = 0; b < 3; b++) mbar_init(sb + b * 8, 1);
        FENCE_ASYNC();
        fillb(0); fillb(1);
    }

    int gs = 0, cb = 0, cph = 0;
#pragma unroll 1
    for (int tile = t0; tile < NT2; tile += gstride) {
#pragma unroll 1
        for (int s = 0; s < 64; s++, gs++) {
            __syncthreads();
            if (tid == 0) {
                int ngs = gs + 2;
                if (t0 + (ngs >> 6) * gstride < NT2) { FENCE_ASYNC(); fillb(ngs); }
            }
            mbar_wait(sb + (uint32_t)cb * 8, (uint32_t)cph);

            const uint32_t dA = sb + 1024 + (uint32_t)cb * G2_STG_B;
            const uint32_t dB = dA + 16384;
            if (++cb == 3) { cb = 0; cph ^= 1; }

#pragma unroll
            for (int ks = 0; ks < 4; ks++) {
                uint32_t af[4][4], bf[4][2];
#pragma unroll
                for (int i = 0; i < 4; i++) {
                    int row = wr * 64 + i * 16 + rA;
                    uint32_t ad = dA + (uint32_t)row * 128
                                + (uint32_t)((ks * 32 + cA) ^ ((row & 7) << 4));
                    ldm_x4(af[i], ad);
                }
#pragma unroll
                for (int jp = 0; jp < 2; jp++) {
                    int n = wc * 32 + jp * 16 + rB;
                    uint32_t ad = dB + (uint32_t)n * 128
                                + (uint32_t)((ks * 32 + cB) ^ ((n & 7) << 4));
                    ldm_x4(&bf[jp * 2][0], ad);
                }
#pragma unroll
                for (int i = 0; i < 4; i++)
#pragma unroll
                    for (int j = 0; j < 4; j++)
                        mma16(acc[i][j], af[i], bf[j]);
            }
        }

        const int e = tile >> 7, nt = (tile >> 4) & 7, mtt = tile & 15;
        const int m0 = mtt * 128 + wr * 64;
        const int n0 = nt * 128 + wc * 32;
        const float* bp2 = bias2 + (size_t)e * DD;
#pragma unroll
        for (int i = 0; i < 4; i++)
#pragma unroll
            for (int j = 0; j < 4; j++) {
                int col = n0 + j * 8 + 2 * tig;
                float b0 = bp2[col], b1 = bp2[col + 1];
#pragma unroll
                for (int half = 0; half < 2; half++) {
                    int row = m0 + i * 16 + gid + half * 8;
                    float2 v = make_float2(acc[i][j][2 * half] + b0, acc[i][j][2 * half + 1] + b1);
                    *reinterpret_cast<float2*>(out + ((size_t)e * TT + row) * DD + col) = v;
                }
            }
#pragma unroll
        for (int i = 0; i < 4; i++)
#pragma unroll
            for (int j = 0; j < 4; j++)
#pragma unroll
                for (int k2 = 0; k2 < 4; k2++) acc[i][j][k2] = 0.f;
    }
}

// ---------------- launch ---------------------------------------------------------
extern "C" void kernel_launch(void* const* d_in, const int* in_sizes, int n_in,
                              void* d_out, int out_size) {
    const float* x  = (const float*)d_in[0];
    const float* w1 = (const float*)d_in[1];
    const float* b1 = (const float*)d_in[2];
    const float* wg = (const float*)d_in[3];
    const float* bg = (const float*)d_in[4];
    const float* w2 = (const float*)d_in[5];
    const float* b2 = (const float*)d_in[6];
    float* out = (float*)d_out;

    cudaFuncSetAttribute(gemm1_kernel, cudaFuncAttributeMaxDynamicSharedMemorySize, G1_SMEM);
    cudaFuncSetAttribute(gemm2_kernel, cudaFuncAttributeMaxDynamicSharedMemorySize, G2_SMEM);

    int smc = 0;
    if (cudaDeviceGetAttribute(&smc, cudaDevAttrMultiProcessorCount, 0) != cudaSuccess || smc <= 0)
        smc = 148;

    __half *dB1p, *dBgp, *dB2p;
    cudaGetSymbolAddress((void**)&dB1p, g_B1p);
    cudaGetSymbolAddress((void**)&dBgp, g_Bgp);
    cudaGetSymbolAddress((void**)&dB2p, g_B2p);

    pack_x_kernel<<<(EE * TT * DD) / (256 * 4), 256>>>(x);
    transpose_pack_kernel<<<dim3(HH / 128, DD / 64, EE), 256>>>(w1, dB1p, DD, HH);
    transpose_pack_kernel<<<dim3(HH / 128, DD / 64, EE), 256>>>(wg, dBgp, DD, HH);
    transpose_pack_kernel<<<dim3(DD / 128, HH / 64, EE), 256>>>(w2, dB2p, HH, DD);

    gemm1_kernel<<<smc, 256, G1_SMEM>>>(b1, bg);          // persistent, 4096 tiles
    gemm2_kernel<<<2 * smc, 256, G2_SMEM>>>(b2, out);     // persistent, 1024 tiles
}

// round 11
// speedup vs baseline: 2.5431x; 1.0597x over previous
#include <cuda_runtime.h>
#include <cuda_fp16.h>
#include <cstdint>

#define EE 8
#define TT 2048
#define DD 1024
#define HH 4096

// ---------------- packed half scratch (pre-swizzled 16KB [128 x 64h] blocks) ---
__device__ __align__(1024) __half g_A1p[(size_t)EE * TT * DD]; // x      [e][mt][16 blk]
__device__ __align__(1024) __half g_B1p[(size_t)EE * HH * DD]; // w1^T   [e][nt32][16 blk]
__device__ __align__(1024) __half g_Bgp[(size_t)EE * HH * DD]; // wg^T
__device__ __align__(1024) __half g_B2p[(size_t)EE * DD * HH]; // w2^T   [e][nt8][64 blk]
__device__ __align__(1024) __half g_A2p[(size_t)EE * TT * HH]; // og     [e][mt][64 blk]

// ---------------- helpers ------------------------------------------------------
__device__ __forceinline__ uint32_t smem_u32(const void* p) {
    uint32_t a;
    asm("{ .reg .u64 t; cvta.to.shared.u64 t, %1; cvt.u32.u64 %0, t; }" : "=r"(a) : "l"(p));
    return a;
}
__device__ __forceinline__ uint32_t swz128(uint32_t o) { return o ^ ((o >> 3) & 0x70); }

__device__ __forceinline__ void mbar_init(uint32_t m, uint32_t c) {
    asm volatile("mbarrier.init.shared.b64 [%0], %1;" :: "r"(m), "r"(c) : "memory");
}
__device__ __forceinline__ void mbar_expect_tx(uint32_t m, uint32_t bytes) {
    asm volatile("mbarrier.arrive.expect_tx.shared.b64 _, [%0], %1;"
                 :: "r"(m), "r"(bytes) : "memory");
}
__device__ __forceinline__ void mbar_wait(uint32_t m, uint32_t parity) {
    asm volatile(
        "{\n\t.reg .pred P;\n"
        "LW_%=:\n\t"
        "mbarrier.try_wait.parity.acquire.cta.shared::cta.b64 P, [%0], %1, 0x989680;\n\t"
        "@P bra.uni LD_%=;\n\t"
        "bra.uni LW_%=;\n"
        "LD_%=:\n\t}"
        :: "r"(m), "r"(parity) : "memory");
}
__device__ __forceinline__ void bulk_g2s(uint32_t dst, const void* src,
                                         uint32_t bytes, uint32_t mbar) {
    asm volatile(
        "cp.async.bulk.shared::cluster.global.mbarrier::complete_tx::bytes "
        "[%0], [%1], %2, [%3];"
        :: "r"(dst), "l"(src), "r"(bytes), "r"(mbar) : "memory");
}
#define FENCE_ASYNC() asm volatile("fence.proxy.async.shared::cta;" ::: "memory")

__device__ __forceinline__ void ldm_x4(uint32_t* r, uint32_t addr) {
    asm volatile("ldmatrix.sync.aligned.m8n8.x4.shared.b16 {%0,%1,%2,%3}, [%4];"
                 : "=r"(r[0]), "=r"(r[1]), "=r"(r[2]), "=r"(r[3]) : "r"(addr));
}
__device__ __forceinline__ void mma16(float* c, const uint32_t* a, const uint32_t* b) {
    asm volatile(
        "mma.sync.aligned.m16n8k16.row.col.f32.f16.f16.f32 "
        "{%0,%1,%2,%3}, {%4,%5,%6,%7}, {%8,%9}, {%0,%1,%2,%3};"
        : "+f"(c[0]), "+f"(c[1]), "+f"(c[2]), "+f"(c[3])
        : "r"(a[0]), "r"(a[1]), "r"(a[2]), "r"(a[3]), "r"(b[0]), "r"(b[1]));
}
__device__ __forceinline__ float my_silu(float g) { return g / (1.0f + __expf(-g)); }
__device__ __forceinline__ uint32_t h2u(__half2 h) { return *reinterpret_cast<uint32_t*>(&h); }

// =================================================================================
// FUSED PREP: one launch.
//   blocks [0, 16384)           : pack x -> g_A1p
//   blocks [16384, 16384+4096)  : transpose w1 -> g_B1p
//   next 4096                   : transpose wg -> g_Bgp
//   next 4096                   : transpose w2 -> g_B2p
// Transpose tile: 64 k-rows x 128 n-cols f32 -> one 16KB packed half block.
// smem layout [n][k] (stride 66 halves): k-paired half2 scatter on write (<=4-way),
// conflict-free gather on read (bank = (nl + 4*kc) mod 32, all distinct per warp).
// =================================================================================
#define PK_NX 16384
#define PK_NW 4096

__global__ void __launch_bounds__(256, 1)
prep_kernel(const float* __restrict__ x,  const float* __restrict__ w1,
            const float* __restrict__ wg, const float* __restrict__ w2) {
    const int tid = threadIdx.x;
    int b = blockIdx.x;

    if (b < PK_NX) {                                   // ---- pack x ----
        size_t idx = ((size_t)b * 256 + tid) * 4;
        float4 v = *reinterpret_cast<const float4*>(x + idx);
        int d = (int)(idx & (DD - 1));
        int t = (int)((idx / DD) & (TT - 1));
        int e = (int)(idx / ((size_t)TT * DD));
        int mt = t >> 7, r = t & 127, bd = d >> 6, c = d & 63;
        char* blk = (char*)(g_A1p + (((size_t)(e * 16 + mt) * 16 + bd) << 13));
        uint2 u;
        u.x = h2u(__floats2half2_rn(v.x, v.y));
        u.y = h2u(__floats2half2_rn(v.z, v.w));
        *reinterpret_cast<uint2*>(blk + swz128((uint32_t)(r * 128 + c * 2))) = u;
        return;
    }

    // ---- weight transpose ----
    b -= PK_NX;
    const float* in; __half* out; int R, C;
    if (b < PK_NW)            { in = w1; out = g_B1p; R = DD; C = HH; }
    else if (b < 2 * PK_NW)   { b -= PK_NW;     in = wg; out = g_Bgp; R = DD; C = HH; }
    else                      { b -= 2 * PK_NW; in = w2; out = g_B2p; R = HH; C = DD; }

    const int NTc = C >> 7, NKB = R >> 6;
    const int nt = b % NTc;
    const int kb = (b / NTc) % NKB;
    const int e  = b / (NTc * NKB);

    __shared__ __half tsm[128 * 66];                   // [n 0..127][k 0..63], stride 66
    const float* ip = in + (size_t)e * R * C + (size_t)(kb * 64) * C + nt * 128;

    const int warp = tid >> 5, cl = tid & 31;
#pragma unroll
    for (int it = 0; it < 4; it++) {                    // 32 k-pairs over 8 warps
        int kr = (warp + 8 * it) * 2;
        float4 v0 = *reinterpret_cast<const float4*>(ip + (size_t)kr * C + 4 * cl);
        float4 v1 = *reinterpret_cast<const float4*>(ip + (size_t)(kr + 1) * C + 4 * cl);
        const float* f0 = &v0.x;
        const float* f1 = &v1.x;
#pragma unroll
        for (int j = 0; j < 4; j++) {
            __half2 h = __floats2half2_rn(f0[j], f1[j]);   // (k, k+1) pair for column n
            *reinterpret_cast<__half2*>(&tsm[(4 * cl + j) * 66 + kr]) = h;
        }
    }
    __syncthreads();

    char* bp = (char*)(out + (((size_t)(e * NTc + nt) * NKB + kb) << 13));
    const int kc = tid & 7, nlb = tid >> 3;
#pragma unroll
    for (int it = 0; it < 4; it++) {
        int nl = nlb + 32 * it;
        const uint32_t* rowp = reinterpret_cast<const uint32_t*>(&tsm[nl * 66 + kc * 8]);
        uint4 u;
        u.x = rowp[0]; u.y = rowp[1]; u.z = rowp[2]; u.w = rowp[3];
        *reinterpret_cast<uint4*>(bp + swz128((uint32_t)(nl * 128 + kc * 16))) = u;
    }
}

// =================================================================================
// GEMM1 fused (persistent): h = x@w1+b1 ; g = silu(x@wg+bg) ; og_packed = h16(h*g)
// CTA 128x128 dual-plane, 256 thr (8 warps 2x4, warp 64x32). f16 m16n8k16.
// Kc=128 -> 8 stages/tile; 2-stage ring (96KB/stage) that never drains.
// =================================================================================
#define G1_STG_B 98304
#define G1_SMEM (1024 + 2 * G1_STG_B)
#define NT1 (EE * 16 * 32)

__global__ void __launch_bounds__(256, 1)
gemm1_kernel(const float* __restrict__ bias1, const float* __restrict__ biasg) {
    extern __shared__ float sm[];
    const uint32_t sb = smem_u32(sm);
    const int tid = threadIdx.x, wid = tid >> 5, lane = tid & 31;
    const int gid = lane >> 2, tig = lane & 3;
    const int wr = wid >> 2, wc = wid & 3;
    const int t0 = blockIdx.x, gstride = gridDim.x;

    const int mq = lane >> 3, lr = lane & 7;
    const int rA = (mq & 1) * 8 + lr,  cA = (mq >> 1) * 16;
    const int rB = (mq >> 1) * 8 + lr, cB = (mq & 1) * 16;

    float ah[4][4][4] = {}, ag[4][4][4] = {};

    auto fillb = [&](int gsx) {                       // gsx = local tile*8 + stage
        const int lt = gsx >> 3, s = gsx & 7;
        const int tile = t0 + lt * gstride;
        const int e = tile >> 9, nt = (tile >> 4) & 31, mtt = tile & 15;
        const __half* aS  = g_A1p + (((size_t)(e * 16 + mtt) * 16 + 2 * s) << 13);
        const __half* b1S = g_B1p + (((size_t)(e * 32 + nt) * 16 + 2 * s) << 13);
        const __half* bgS = g_Bgp + (((size_t)(e * 32 + nt) * 16 + 2 * s) << 13);
        const int b = gsx & 1;
        const uint32_t mb = sb + (uint32_t)b * 8;
        const uint32_t dst = sb + 1024 + (uint32_t)b * G1_STG_B;
        mbar_expect_tx(mb, G1_STG_B);
        bulk_g2s(dst,          aS,  32768, mb);
        bulk_g2s(dst + 32768,  b1S, 32768, mb);
        bulk_g2s(dst + 65536,  bgS, 32768, mb);
    };

    if (tid == 0) {
        mbar_init(sb, 1); mbar_init(sb + 8, 1);
        FENCE_ASYNC();
        fillb(0);
    }

    int gs = 0;
#pragma unroll 1
    for (int tile = t0; tile < NT1; tile += gstride) {
#pragma unroll 1
        for (int s = 0; s < 8; s++, gs++) {
            __syncthreads();
            if (tid == 0) {
                int ngs = gs + 1;
                if (t0 + (ngs >> 3) * gstride < NT1) fillb(ngs);
            }
            mbar_wait(sb + (uint32_t)(gs & 1) * 8, (uint32_t)((gs >> 1) & 1));

            const uint32_t dA  = sb + 1024 + (uint32_t)(gs & 1) * G1_STG_B;
            const uint32_t dB1 = dA + 32768;
            const uint32_t dB2 = dA + 65536;

            uint32_t af[2][4][4], bf1[2][4][2], bf2[2][4][2];

            auto ldfr = [&](int ks, int pb) {
                const int kk = ks & 3;
                const uint32_t blk = (uint32_t)(ks >> 2) * 16384;
#pragma unroll
                for (int i = 0; i < 4; i++) {
                    int row = wr * 64 + i * 16 + rA;
                    uint32_t ad = dA + blk + (uint32_t)row * 128
                                + (uint32_t)((kk * 32 + cA) ^ ((row & 7) << 4));
                    ldm_x4(af[pb][i], ad);
                }
#pragma unroll
                for (int jp = 0; jp < 2; jp++) {
                    int n = wc * 32 + jp * 16 + rB;
                    uint32_t off = blk + (uint32_t)n * 128
                                 + (uint32_t)((kk * 32 + cB) ^ ((n & 7) << 4));
                    ldm_x4(&bf1[pb][jp * 2][0], dB1 + off);
                    ldm_x4(&bf2[pb][jp * 2][0], dB2 + off);
                }
            };

            ldfr(0, 0);
#pragma unroll
            for (int ks = 0; ks < 8; ks++) {
                const int cur = ks & 1;
                if (ks < 7) ldfr(ks + 1, cur ^ 1);
#pragma unroll
                for (int i = 0; i < 4; i++)
#pragma unroll
                    for (int j = 0; j < 4; j++) {
                        mma16(ah[i][j], af[cur][i], bf1[cur][j]);
                        mma16(ag[i][j], af[cur][i], bf2[cur][j]);
                    }
            }
        }

        // epilogue: og = h16((h+b1)*silu(g+bg)) -> packed half blocks for GEMM2
        const int e = tile >> 9, nt = (tile >> 4) & 31, mtt = tile & 15;
        const float* bp1 = bias1 + (size_t)e * HH + nt * 128;
        const float* bpg = biasg + (size_t)e * HH + nt * 128;
        const int b2 = nt * 2 + (wc >> 1);
        char* blk = (char*)(g_A2p + (((size_t)(e * 16 + mtt) * 64 + b2) << 13));
#pragma unroll
        for (int i = 0; i < 4; i++)
#pragma unroll
            for (int j = 0; j < 4; j++) {
                int cl = wc * 32 + j * 8 + 2 * tig;
                float bh0 = bp1[cl], bh1 = bp1[cl + 1];
                float bg0 = bpg[cl], bg1 = bpg[cl + 1];
                int kh = (wc & 1) * 32 + j * 8 + 2 * tig;
#pragma unroll
                for (int half = 0; half < 2; half++) {
                    int rl = wr * 64 + i * 16 + gid + half * 8;
                    float h0 = ah[i][j][2 * half]     + bh0;
                    float h1 = ah[i][j][2 * half + 1] + bh1;
                    float g0 = ag[i][j][2 * half]     + bg0;
                    float g1 = ag[i][j][2 * half + 1] + bg1;
                    uint32_t u = h2u(__floats2half2_rn(h0 * my_silu(g0), h1 * my_silu(g1)));
                    *reinterpret_cast<uint32_t*>(
                        blk + swz128((uint32_t)(rl * 128 + kh * 2))) = u;
                }
            }
#pragma unroll
        for (int i = 0; i < 4; i++)
#pragma unroll
            for (int j = 0; j < 4; j++)
#pragma unroll
                for (int k2 = 0; k2 < 4; k2++) { ah[i][j][k2] = 0.f; ag[i][j][k2] = 0.f; }
    }
}

// =================================================================================
// GEMM2 (persistent): out = og @ w2 + b2.  CTA 128x128, 256 thr, f16 m16n8k16,
// Kc=64 -> 64 stages/tile, 3-stage ring (32KB/stage), occupancy 2.
// =================================================================================
#define G2_STG_B 32768
#define G2_SMEM (1024 + 3 * G2_STG_B)
#define NT2 (EE * 16 * 8)

__global__ void __launch_bounds__(256, 2)
gemm2_kernel(const float* __restrict__ bias2, float* __restrict__ out) {
    extern __shared__ float sm[];
    const uint32_t sb = smem_u32(sm);
    const int tid = threadIdx.x, wid = tid >> 5, lane = tid & 31;
    const int gid = lane >> 2, tig = lane & 3;
    const int wr = wid >> 2, wc = wid & 3;
    const int t0 = blockIdx.x, gstride = gridDim.x;

    const int mq = lane >> 3, lr = lane & 7;
    const int rA = (mq & 1) * 8 + lr,  cA = (mq >> 1) * 16;
    const int rB = (mq >> 1) * 8 + lr, cB = (mq & 1) * 16;

    float acc[4][4][4] = {};

    auto fillb = [&](int gsx) {                       // gsx = local tile*64 + stage
        const int lt = gsx >> 6, s = gsx & 63;
        const int tile = t0 + lt * gstride;
        const int e = tile >> 7, nt = (tile >> 4) & 7, mtt = tile & 15;
        const __half* aS = g_A2p + (((size_t)(e * 16 + mtt) * 64 + s) << 13);
        const __half* bS = g_B2p + (((size_t)(e * 8  + nt) * 64 + s) << 13);
        int b = gsx - (gsx / 3) * 3;
        const uint32_t mb = sb + (uint32_t)b * 8;
        const uint32_t dst = sb + 1024 + (uint32_t)b * G2_STG_B;
        mbar_expect_tx(mb, G2_STG_B);
        bulk_g2s(dst,         aS, 16384, mb);
        bulk_g2s(dst + 16384, bS, 16384, mb);
    };

    if (tid == 0) {
#pragma unroll
        for (int b = 0; b < 3; b++) mbar_init(sb + b * 8, 1);
        FENCE_ASYNC();
        fillb(0); fillb(1);
    }

    int gs = 0, cb = 0, cph = 0;
#pragma unroll 1
    for (int tile = t0; tile < NT2; tile += gstride) {
#pragma unroll 1
        for (int s = 0; s < 64; s++, gs++) {
            __syncthreads();
            if (tid == 0) {
                int ngs = gs + 2;
                if (t0 + (ngs >> 6) * gstride < NT2) fillb(ngs);
            }
            mbar_wait(sb + (uint32_t)cb * 8, (uint32_t)cph);

            const uint32_t dA = sb + 1024 + (uint32_t)cb * G2_STG_B;
            const uint32_t dB = dA + 16384;
            if (++cb == 3) { cb = 0; cph ^= 1; }

#pragma unroll
            for (int ks = 0; ks < 4; ks++) {
                uint32_t af[4][4], bf[4][2];
#pragma unroll
                for (int i = 0; i < 4; i++) {
                    int row = wr * 64 + i * 16 + rA;
                    uint32_t ad = dA + (uint32_t)row * 128
                                + (uint32_t)((ks * 32 + cA) ^ ((row & 7) << 4));
                    ldm_x4(af[i], ad);
                }
#pragma unroll
                for (int jp = 0; jp < 2; jp++) {
                    int n = wc * 32 + jp * 16 + rB;
                    uint32_t ad = dB + (uint32_t)n * 128
                                + (uint32_t)((ks * 32 + cB) ^ ((n & 7) << 4));
                    ldm_x4(&bf[jp * 2][0], ad);
                }
#pragma unroll
                for (int i = 0; i < 4; i++)
#pragma unroll
                    for (int j = 0; j < 4; j++)
                        mma16(acc[i][j], af[i], bf[j]);
            }
        }

        const int e = tile >> 7, nt = (tile >> 4) & 7, mtt = tile & 15;
        const int m0 = mtt * 128 + wr * 64;
        const int n0 = nt * 128 + wc * 32;
        const float* bp2 = bias2 + (size_t)e * DD;
#pragma unroll
        for (int i = 0; i < 4; i++)
#pragma unroll
            for (int j = 0; j < 4; j++) {
                int col = n0 + j * 8 + 2 * tig;
                float b0 = bp2[col], b1 = bp2[col + 1];
#pragma unroll
                for (int half = 0; half < 2; half++) {
                    int row = m0 + i * 16 + gid + half * 8;
                    float2 v = make_float2(acc[i][j][2 * half] + b0, acc[i][j][2 * half + 1] + b1);
                    *reinterpret_cast<float2*>(out + ((size_t)e * TT + row) * DD + col) = v;
                }
            }
#pragma unroll
        for (int i = 0; i < 4; i++)
#pragma unroll
            for (int j = 0; j < 4; j++)
#pragma unroll
                for (int k2 = 0; k2 < 4; k2++) acc[i][j][k2] = 0.f;
    }
}

// ---------------- launch ---------------------------------------------------------
extern "C" void kernel_launch(void* const* d_in, const int* in_sizes, int n_in,
                              void* d_out, int out_size) {
    const float* x  = (const float*)d_in[0];
    const float* w1 = (const float*)d_in[1];
    const float* b1 = (const float*)d_in[2];
    const float* wg = (const float*)d_in[3];
    const float* bg = (const float*)d_in[4];
    const float* w2 = (const float*)d_in[5];
    const float* b2 = (const float*)d_in[6];
    float* out = (float*)d_out;

    cudaFuncSetAttribute(gemm1_kernel, cudaFuncAttributeMaxDynamicSharedMemorySize, G1_SMEM);
    cudaFuncSetAttribute(gemm2_kernel, cudaFuncAttributeMaxDynamicSharedMemorySize, G2_SMEM);

    int smc = 0;
    if (cudaDeviceGetAttribute(&smc, cudaDevAttrMultiProcessorCount, 0) != cudaSuccess || smc <= 0)
        smc = 148;

    prep_kernel<<<PK_NX + 3 * PK_NW, 256>>>(x, w1, wg, w2);
    gemm1_kernel<<<smc, 256, G1_SMEM>>>(b1, bg);          // persistent, 4096 tiles
    gemm2_kernel<<<2 * smc, 256, G2_SMEM>>>(b2, out);     // persistent, 1024 tiles
}

// round 12
// speedup vs baseline: 2.6040x; 1.0239x over previous
#include <cuda_runtime.h>
#include <cuda_fp16.h>
#include <cstdint>

#define EE 8
#define TT 2048
#define DD 1024
#define HH 4096

// ---------------- packed half scratch (pre-swizzled 16KB [128 x 64h] blocks) ---
__device__ __align__(1024) __half g_A1p[(size_t)EE * TT * DD];
__device__ __align__(1024) __half g_B1p[(size_t)EE * HH * DD];
__device__ __align__(1024) __half g_Bgp[(size_t)EE * HH * DD];
__device__ __align__(1024) __half g_B2p[(size_t)EE * DD * HH];
__device__ __align__(1024) __half g_A2p[(size_t)EE * TT * HH];

__device__ int g_ctr1, g_ctr2;       // dynamic tile counters (reset by prep)

// ---------------- helpers ------------------------------------------------------
__device__ __forceinline__ uint32_t smem_u32(const void* p) {
    uint32_t a;
    asm("{ .reg .u64 t; cvta.to.shared.u64 t, %1; cvt.u32.u64 %0, t; }" : "=r"(a) : "l"(p));
    return a;
}
__device__ __forceinline__ uint32_t swz128(uint32_t o) { return o ^ ((o >> 3) & 0x70); }

__device__ __forceinline__ void mbar_init(uint32_t m, uint32_t c) {
    asm volatile("mbarrier.init.shared.b64 [%0], %1;" :: "r"(m), "r"(c) : "memory");
}
__device__ __forceinline__ void mbar_expect_tx(uint32_t m, uint32_t bytes) {
    asm volatile("mbarrier.arrive.expect_tx.shared.b64 _, [%0], %1;"
                 :: "r"(m), "r"(bytes) : "memory");
}
__device__ __forceinline__ void mbar_arrive(uint32_t m) {
    asm volatile("mbarrier.arrive.shared.b64 _, [%0];" :: "r"(m) : "memory");
}
__device__ __forceinline__ void mbar_wait(uint32_t m, uint32_t parity) {
    asm volatile(
        "{\n\t.reg .pred P;\n"
        "LW_%=:\n\t"
        "mbarrier.try_wait.parity.acquire.cta.shared::cta.b64 P, [%0], %1, 0x989680;\n\t"
        "@P bra.uni LD_%=;\n\t"
        "bra.uni LW_%=;\n"
        "LD_%=:\n\t}"
        :: "r"(m), "r"(parity) : "memory");
}
__device__ __forceinline__ void bulk_g2s(uint32_t dst, const void* src,
                                         uint32_t bytes, uint32_t mbar) {
    asm volatile(
        "cp.async.bulk.shared::cluster.global.mbarrier::complete_tx::bytes "
        "[%0], [%1], %2, [%3];"
        :: "r"(dst), "l"(src), "r"(bytes), "r"(mbar) : "memory");
}
#define FENCE_ASYNC() asm volatile("fence.proxy.async.shared::cta;" ::: "memory")

__device__ __forceinline__ void ldm_x4(uint32_t* r, uint32_t addr) {
    asm volatile("ldmatrix.sync.aligned.m8n8.x4.shared.b16 {%0,%1,%2,%3}, [%4];"
                 : "=r"(r[0]), "=r"(r[1]), "=r"(r[2]), "=r"(r[3]) : "r"(addr));
}
__device__ __forceinline__ void mma16(float* c, const uint32_t* a, const uint32_t* b) {
    asm volatile(
        "mma.sync.aligned.m16n8k16.row.col.f32.f16.f16.f32 "
        "{%0,%1,%2,%3}, {%4,%5,%6,%7}, {%8,%9}, {%0,%1,%2,%3};"
        : "+f"(c[0]), "+f"(c[1]), "+f"(c[2]), "+f"(c[3])
        : "r"(a[0]), "r"(a[1]), "r"(a[2]), "r"(a[3]), "r"(b[0]), "r"(b[1]));
}
__device__ __forceinline__ float my_silu(float g) { return g / (1.0f + __expf(-g)); }
__device__ __forceinline__ uint32_t h2u(__half2 h) { return *reinterpret_cast<uint32_t*>(&h); }

// =================================================================================
// FUSED PREP (unchanged layout work) + counter reset
// =================================================================================
#define PK_NX 16384
#define PK_NW 4096

__global__ void __launch_bounds__(256, 1)
prep_kernel(const float* __restrict__ x,  const float* __restrict__ w1,
            const float* __restrict__ wg, const float* __restrict__ w2) {
    const int tid = threadIdx.x;
    int b = blockIdx.x;

    if (b == 0 && tid == 0) { g_ctr1 = 0; g_ctr2 = 0; }

    if (b < PK_NX) {                                   // ---- pack x ----
        size_t idx = ((size_t)b * 256 + tid) * 4;
        float4 v = *reinterpret_cast<const float4*>(x + idx);
        int d = (int)(idx & (DD - 1));
        int t = (int)((idx / DD) & (TT - 1));
        int e = (int)(idx / ((size_t)TT * DD));
        int mt = t >> 7, r = t & 127, bd = d >> 6, c = d & 63;
        char* blk = (char*)(g_A1p + (((size_t)(e * 16 + mt) * 16 + bd) << 13));
        uint2 u;
        u.x = h2u(__floats2half2_rn(v.x, v.y));
        u.y = h2u(__floats2half2_rn(v.z, v.w));
        *reinterpret_cast<uint2*>(blk + swz128((uint32_t)(r * 128 + c * 2))) = u;
        return;
    }

    b -= PK_NX;
    const float* in; __half* out; int R, C;
    if (b < PK_NW)            { in = w1; out = g_B1p; R = DD; C = HH; }
    else if (b < 2 * PK_NW)   { b -= PK_NW;     in = wg; out = g_Bgp; R = DD; C = HH; }
    else                      { b -= 2 * PK_NW; in = w2; out = g_B2p; R = HH; C = DD; }

    const int NTc = C >> 7, NKB = R >> 6;
    const int nt = b % NTc;
    const int kb = (b / NTc) % NKB;
    const int e  = b / (NTc * NKB);

    __shared__ __half tsm[128 * 66];
    const float* ip = in + (size_t)e * R * C + (size_t)(kb * 64) * C + nt * 128;

    const int warp = tid >> 5, cl = tid & 31;
#pragma unroll
    for (int it = 0; it < 4; it++) {
        int kr = (warp + 8 * it) * 2;
        float4 v0 = *reinterpret_cast<const float4*>(ip + (size_t)kr * C + 4 * cl);
        float4 v1 = *reinterpret_cast<const float4*>(ip + (size_t)(kr + 1) * C + 4 * cl);
        const float* f0 = &v0.x;
        const float* f1 = &v1.x;
#pragma unroll
        for (int j = 0; j < 4; j++) {
            __half2 h = __floats2half2_rn(f0[j], f1[j]);
            *reinterpret_cast<__half2*>(&tsm[(4 * cl + j) * 66 + kr]) = h;
        }
    }
    __syncthreads();

    char* bp = (char*)(out + (((size_t)(e * NTc + nt) * NKB + kb) << 13));
    const int kc = tid & 7, nlb = tid >> 3;
#pragma unroll
    for (int it = 0; it < 4; it++) {
        int nl = nlb + 32 * it;
        const uint32_t* rowp = reinterpret_cast<const uint32_t*>(&tsm[nl * 66 + kc * 8]);
        uint4 u;
        u.x = rowp[0]; u.y = rowp[1]; u.z = rowp[2]; u.w = rowp[3];
        *reinterpret_cast<uint4*>(bp + swz128((uint32_t)(nl * 128 + kc * 16))) = u;
    }
}

// =================================================================================
// GEMM1 fused (persistent + dynamic tiles + split barriers)
// CTA 128x128 dual-plane, 256 thr, f16 m16n8k16, Kc=128, 2-stage ring (96KB/stage).
// mbars: full[2] @ sb+0,8 (count 1); empty[2] @ sb+16,24 (count 256).
// =================================================================================
#define G1_STG_B 98304
#define G1_SMEM (1024 + 2 * G1_STG_B)
#define NT1 (EE * 16 * 32)

__global__ void __launch_bounds__(256, 1)
gemm1_kernel(const float* __restrict__ bias1, const float* __restrict__ biasg) {
    extern __shared__ float sm[];
    __shared__ int sm_next;
    const uint32_t sb = smem_u32(sm);
    const int tid = threadIdx.x, wid = tid >> 5, lane = tid & 31;
    const int gid = lane >> 2, tig = lane & 3;
    const int wr = wid >> 2, wc = wid & 3;

    const int mq = lane >> 3, lr = lane & 7;
    const int rA = (mq & 1) * 8 + lr,  cA = (mq >> 1) * 16;
    const int rB = (mq >> 1) * 8 + lr, cB = (mq & 1) * 16;

    float ah[4][4][4] = {}, ag[4][4][4] = {};

    auto fill = [&](int tile_, int stg, int fb) {
        const int e = tile_ >> 9, nt = (tile_ >> 4) & 31, mtt = tile_ & 15;
        const __half* aS  = g_A1p + (((size_t)(e * 16 + mtt) * 16 + 2 * stg) << 13);
        const __half* b1S = g_B1p + (((size_t)(e * 32 + nt) * 16 + 2 * stg) << 13);
        const __half* bgS = g_Bgp + (((size_t)(e * 32 + nt) * 16 + 2 * stg) << 13);
        const uint32_t mb = sb + (uint32_t)fb * 8;
        const uint32_t dst = sb + 1024 + (uint32_t)fb * G1_STG_B;
        mbar_expect_tx(mb, G1_STG_B);
        bulk_g2s(dst,          aS,  32768, mb);
        bulk_g2s(dst + 32768,  b1S, 32768, mb);
        bulk_g2s(dst + 65536,  bgS, 32768, mb);
    };

    if (tid == 0) {
        mbar_init(sb, 1);       mbar_init(sb + 8, 1);
        mbar_init(sb + 16, 256); mbar_init(sb + 24, 256);
        sm_next = atomicAdd(&g_ctr1, 1);
        FENCE_ASYNC();
    }
    __syncthreads();
    int tile = sm_next;
    __syncthreads();                                  // all read before tid0 rewrites

    int pnext = NT1;                                  // producer-only state (tid0)
    if (tid == 0 && tile < NT1) {
        mbar_wait(sb + 16, 1);                        // fresh: passes
        fill(tile, 0, 0);
    }

    int gs = 0;
#pragma unroll 1
    while (tile < NT1) {
#pragma unroll 1
        for (int s = 0; s < 8; s++, gs++) {
            if (tid == 0) {
                if (s == 0) { pnext = atomicAdd(&g_ctr1, 1); sm_next = pnext; }
                int ft = (s == 7) ? pnext : tile;
                if (ft < NT1) {
                    int fgs = gs + 1, fb = fgs & 1;
                    mbar_wait(sb + 16 + (uint32_t)fb * 8, ((fgs >> 1) & 1) ^ 1);
                    fill(ft, (s + 1) & 7, fb);
                }
            }
            const int cbuf = gs & 1;
            mbar_wait(sb + (uint32_t)cbuf * 8, (gs >> 1) & 1);

            const uint32_t dA  = sb + 1024 + (uint32_t)cbuf * G1_STG_B;
            const uint32_t dB1 = dA + 32768;
            const uint32_t dB2 = dA + 65536;

            uint32_t af[2][4][4], bf1[2][4][2], bf2[2][4][2];

            auto ldfr = [&](int ks, int pb) {
                const int kk = ks & 3;
                const uint32_t blk = (uint32_t)(ks >> 2) * 16384;
#pragma unroll
                for (int i = 0; i < 4; i++) {
                    int row = wr * 64 + i * 16 + rA;
                    uint32_t ad = dA + blk + (uint32_t)row * 128
                                + (uint32_t)((kk * 32 + cA) ^ ((row & 7) << 4));
                    ldm_x4(af[pb][i], ad);
                }
#pragma unroll
                for (int jp = 0; jp < 2; jp++) {
                    int n = wc * 32 + jp * 16 + rB;
                    uint32_t off = blk + (uint32_t)n * 128
                                 + (uint32_t)((kk * 32 + cB) ^ ((n & 7) << 4));
                    ldm_x4(&bf1[pb][jp * 2][0], dB1 + off);
                    ldm_x4(&bf2[pb][jp * 2][0], dB2 + off);
                }
            };

            ldfr(0, 0);
#pragma unroll
            for (int ks = 0; ks < 8; ks++) {
                const int cur = ks & 1;
                if (ks < 7) ldfr(ks + 1, cur ^ 1);
#pragma unroll
                for (int i = 0; i < 4; i++)
#pragma unroll
                    for (int j = 0; j < 4; j++) {
                        mma16(ah[i][j], af[cur][i], bf1[cur][j]);
                        mma16(ag[i][j], af[cur][i], bf2[cur][j]);
                    }
            }
            mbar_arrive(sb + 16 + (uint32_t)cbuf * 8);   // buffer consumed
        }

        // epilogue: og = h16((h+b1)*silu(g+bg)) -> packed half blocks for GEMM2
        const int e = tile >> 9, nt = (tile >> 4) & 31, mtt = tile & 15;
        const float* bp1 = bias1 + (size_t)e * HH + nt * 128;
        const float* bpg = biasg + (size_t)e * HH + nt * 128;
        const int b2 = nt * 2 + (wc >> 1);
        char* blk = (char*)(g_A2p + (((size_t)(e * 16 + mtt) * 64 + b2) << 13));
#pragma unroll
        for (int i = 0; i < 4; i++)
#pragma unroll
            for (int j = 0; j < 4; j++) {
                int cl = wc * 32 + j * 8 + 2 * tig;
                float bh0 = bp1[cl], bh1 = bp1[cl + 1];
                float bg0 = bpg[cl], bg1 = bpg[cl + 1];
                int kh = (wc & 1) * 32 + j * 8 + 2 * tig;
#pragma unroll
                for (int half = 0; half < 2; half++) {
                    int rl = wr * 64 + i * 16 + gid + half * 8;
                    float h0 = ah[i][j][2 * half]     + bh0;
                    float h1 = ah[i][j][2 * half + 1] + bh1;
                    float g0 = ag[i][j][2 * half]     + bg0;
                    float g1 = ag[i][j][2 * half + 1] + bg1;
                    uint32_t u = h2u(__floats2half2_rn(h0 * my_silu(g0), h1 * my_silu(g1)));
                    *reinterpret_cast<uint32_t*>(
                        blk + swz128((uint32_t)(rl * 128 + kh * 2))) = u;
                }
            }
#pragma unroll
        for (int i = 0; i < 4; i++)
#pragma unroll
            for (int j = 0; j < 4; j++)
#pragma unroll
                for (int k2 = 0; k2 < 4; k2++) { ah[i][j][k2] = 0.f; ag[i][j][k2] = 0.f; }

        __syncthreads();
        tile = sm_next;
        __syncthreads();
    }
}

// =================================================================================
// GEMM2 (persistent + dynamic tiles + split barriers)
// CTA 128x128, 256 thr, f16 m16n8k16, Kc=64 -> 64 stages/tile, 3-ring, occ 2.
// mbars: full[3] @ sb+0,8,16 (count 1); empty[3] @ sb+24,32,40 (count 256).
// =================================================================================
#define G2_STG_B 32768
#define G2_SMEM (1024 + 3 * G2_STG_B)
#define NT2 (EE * 16 * 8)

__global__ void __launch_bounds__(256, 2)
gemm2_kernel(const float* __restrict__ bias2, float* __restrict__ out) {
    extern __shared__ float sm[];
    __shared__ int sm_next;
    const uint32_t sb = smem_u32(sm);
    const int tid = threadIdx.x, wid = tid >> 5, lane = tid & 31;
    const int gid = lane >> 2, tig = lane & 3;
    const int wr = wid >> 2, wc = wid & 3;

    const int mq = lane >> 3, lr = lane & 7;
    const int rA = (mq & 1) * 8 + lr,  cA = (mq >> 1) * 16;
    const int rB = (mq >> 1) * 8 + lr, cB = (mq & 1) * 16;

    float acc[4][4][4] = {};

    auto fill = [&](int tile_, int stg, int fb) {
        const int e = tile_ >> 7, nt = (tile_ >> 4) & 7, mtt = tile_ & 15;
        const __half* aS = g_A2p + (((size_t)(e * 16 + mtt) * 64 + stg) << 13);
        const __half* bS = g_B2p + (((size_t)(e * 8  + nt) * 64 + stg) << 13);
        const uint32_t mb = sb + (uint32_t)fb * 8;
        const uint32_t dst = sb + 1024 + (uint32_t)fb * G2_STG_B;
        mbar_expect_tx(mb, G2_STG_B);
        bulk_g2s(dst,         aS, 16384, mb);
        bulk_g2s(dst + 16384, bS, 16384, mb);
    };

    if (tid == 0) {
#pragma unroll
        for (int b = 0; b < 3; b++) { mbar_init(sb + b * 8, 1); mbar_init(sb + 24 + b * 8, 256); }
        sm_next = atomicAdd(&g_ctr2, 1);
        FENCE_ASYNC();
    }
    __syncthreads();
    int tile = sm_next;
    __syncthreads();

    int pnext = NT2;
    if (tid == 0 && tile < NT2) {
        mbar_wait(sb + 24, 1); fill(tile, 0, 0);      // fresh: passes
        mbar_wait(sb + 32, 1); fill(tile, 1, 1);
    }

    int gs = 0, cb = 0, cph = 0;
#pragma unroll 1
    while (tile < NT2) {
#pragma unroll 1
        for (int s = 0; s < 64; s++, gs++) {
            if (tid == 0) {
                if (s == 0) { pnext = atomicAdd(&g_ctr2, 1); sm_next = pnext; }
                int fs = s + 2;
                int ft = (fs >= 64) ? pnext : tile;
                if (ft < NT2) {
                    int fgs = gs + 2;
                    int fj = fgs / 3, fb = fgs - 3 * fj;
                    mbar_wait(sb + 24 + (uint32_t)fb * 8, (uint32_t)((fj & 1) ^ 1));
                    fill(ft, fs & 63, fb);
                }
            }
            const int cbuf = cb;
            mbar_wait(sb + (uint32_t)cbuf * 8, (uint32_t)cph);
            if (++cb == 3) { cb = 0; cph ^= 1; }

            const uint32_t dA = sb + 1024 + (uint32_t)cbuf * G2_STG_B;
            const uint32_t dB = dA + 16384;

#pragma unroll
            for (int ks = 0; ks < 4; ks++) {
                uint32_t af[4][4], bf[4][2];
#pragma unroll
                for (int i = 0; i < 4; i++) {
                    int row = wr * 64 + i * 16 + rA;
                    uint32_t ad = dA + (uint32_t)row * 128
                                + (uint32_t)((ks * 32 + cA) ^ ((row & 7) << 4));
                    ldm_x4(af[i], ad);
                }
#pragma unroll
                for (int jp = 0; jp < 2; jp++) {
                    int n = wc * 32 + jp * 16 + rB;
                    uint32_t ad = dB + (uint32_t)n * 128
                                + (uint32_t)((ks * 32 + cB) ^ ((n & 7) << 4));
                    ldm_x4(&bf[jp * 2][0], ad);
                }
#pragma unroll
                for (int i = 0; i < 4; i++)
#pragma unroll
                    for (int j = 0; j < 4; j++)
                        mma16(acc[i][j], af[i], bf[j]);
            }
            mbar_arrive(sb + 24 + (uint32_t)cbuf * 8);
        }

        const int e = tile >> 7, nt = (tile >> 4) & 7, mtt = tile & 15;
        const int m0 = mtt * 128 + wr * 64;
        const int n0 = nt * 128 + wc * 32;
        const float* bp2 = bias2 + (size_t)e * DD;
#pragma unroll
        for (int i = 0; i < 4; i++)
#pragma unroll
            for (int j = 0; j < 4; j++) {
                int col = n0 + j * 8 + 2 * tig;
                float b0 = bp2[col], b1 = bp2[col + 1];
#pragma unroll
                for (int half = 0; half < 2; half++) {
                    int row = m0 + i * 16 + gid + half * 8;
                    float2 v = make_float2(acc[i][j][2 * half] + b0, acc[i][j][2 * half + 1] + b1);
                    *reinterpret_cast<float2*>(out + ((size_t)e * TT + row) * DD + col) = v;
                }
            }
#pragma unroll
        for (int i = 0; i < 4; i++)
#pragma unroll
            for (int j = 0; j < 4; j++)
#pragma unroll
                for (int k2 = 0; k2 < 4; k2++) acc[i][j][k2] = 0.f;

        __syncthreads();
        tile = sm_next;
        __syncthreads();
    }
}

// ---------------- launch ---------------------------------------------------------
extern "C" void kernel_launch(void* const* d_in, const int* in_sizes, int n_in,
                              void* d_out, int out_size) {
    const float* x  = (const float*)d_in[0];
    const float* w1 = (const float*)d_in[1];
    const float* b1 = (const float*)d_in[2];
    const float* wg = (const float*)d_in[3];
    const float* bg = (const float*)d_in[4];
    const float* w2 = (const float*)d_in[5];
    const float* b2 = (const float*)d_in[6];
    float* out = (float*)d_out;

    cudaFuncSetAttribute(gemm1_kernel, cudaFuncAttributeMaxDynamicSharedMemorySize, G1_SMEM);
    cudaFuncSetAttribute(gemm2_kernel, cudaFuncAttributeMaxDynamicSharedMemorySize, G2_SMEM);

    int smc = 0;
    if (cudaDeviceGetAttribute(&smc, cudaDevAttrMultiProcessorCount, 0) != cudaSuccess || smc <= 0)
        smc = 148;

    prep_kernel<<<PK_NX + 3 * PK_NW, 256>>>(x, w1, wg, w2);
    gemm1_kernel<<<smc, 256, G1_SMEM>>>(b1, bg);          // persistent, dynamic tiles
    gemm2_kernel<<<2 * smc, 256, G2_SMEM>>>(b2, out);     // persistent, dynamic tiles
}

// round 13
// speedup vs baseline: 2.6066x; 1.0010x over previous
#include <cuda_runtime.h>
#include <cuda_fp16.h>
#include <cstdint>

#define EE 8
#define TT 2048
#define DD 1024
#define HH 4096

// ---------------- packed half scratch (pre-swizzled 16KB [128 x 64h] blocks) ---
__device__ __align__(1024) __half g_A1p[(size_t)EE * TT * DD];
__device__ __align__(1024) __half g_B1p[(size_t)EE * HH * DD];
__device__ __align__(1024) __half g_Bgp[(size_t)EE * HH * DD];
__device__ __align__(1024) __half g_B2p[(size_t)EE * DD * HH];
__device__ __align__(1024) __half g_A2p[(size_t)EE * TT * HH];

__device__ int g_ctr1, g_ctr2;       // dynamic tile counters (reset by prep)

// ---------------- helpers ------------------------------------------------------
__device__ __forceinline__ uint32_t smem_u32(const void* p) {
    uint32_t a;
    asm("{ .reg .u64 t; cvta.to.shared.u64 t, %1; cvt.u32.u64 %0, t; }" : "=r"(a) : "l"(p));
    return a;
}
__device__ __forceinline__ uint32_t swz128(uint32_t o) { return o ^ ((o >> 3) & 0x70); }

__device__ __forceinline__ void mbar_init(uint32_t m, uint32_t c) {
    asm volatile("mbarrier.init.shared.b64 [%0], %1;" :: "r"(m), "r"(c) : "memory");
}
__device__ __forceinline__ void mbar_expect_tx(uint32_t m, uint32_t bytes) {
    asm volatile("mbarrier.arrive.expect_tx.shared.b64 _, [%0], %1;"
                 :: "r"(m), "r"(bytes) : "memory");
}
__device__ __forceinline__ void mbar_arrive(uint32_t m) {
    asm volatile("mbarrier.arrive.shared.b64 _, [%0];" :: "r"(m) : "memory");
}
__device__ __forceinline__ void mbar_wait(uint32_t m, uint32_t parity) {
    asm volatile(
        "{\n\t.reg .pred P;\n"
        "LW_%=:\n\t"
        "mbarrier.try_wait.parity.acquire.cta.shared::cta.b64 P, [%0], %1, 0x989680;\n\t"
        "@P bra.uni LD_%=;\n\t"
        "bra.uni LW_%=;\n"
        "LD_%=:\n\t}"
        :: "r"(m), "r"(parity) : "memory");
}
__device__ __forceinline__ void bulk_g2s(uint32_t dst, const void* src,
                                         uint32_t bytes, uint32_t mbar) {
    asm volatile(
        "cp.async.bulk.shared::cluster.global.mbarrier::complete_tx::bytes "
        "[%0], [%1], %2, [%3];"
        :: "r"(dst), "l"(src), "r"(bytes), "r"(mbar) : "memory");
}
#define FENCE_ASYNC() asm volatile("fence.proxy.async.shared::cta;" ::: "memory")

__device__ __forceinline__ void ldm_x4(uint32_t* r, uint32_t addr) {
    asm volatile("ldmatrix.sync.aligned.m8n8.x4.shared.b16 {%0,%1,%2,%3}, [%4];"
                 : "=r"(r[0]), "=r"(r[1]), "=r"(r[2]), "=r"(r[3]) : "r"(addr));
}
__device__ __forceinline__ void mma16(float* c, const uint32_t* a, const uint32_t* b) {
    asm volatile(
        "mma.sync.aligned.m16n8k16.row.col.f32.f16.f16.f32 "
        "{%0,%1,%2,%3}, {%4,%5,%6,%7}, {%8,%9}, {%0,%1,%2,%3};"
        : "+f"(c[0]), "+f"(c[1]), "+f"(c[2]), "+f"(c[3])
        : "r"(a[0]), "r"(a[1]), "r"(a[2]), "r"(a[3]), "r"(b[0]), "r"(b[1]));
}
__device__ __forceinline__ float my_silu(float g) { return g / (1.0f + __expf(-g)); }
__device__ __forceinline__ uint32_t h2u(__half2 h) { return *reinterpret_cast<uint32_t*>(&h); }

// =================================================================================
// FUSED PREP + counter reset (unchanged — 80% DRAM, at its compulsory roofline)
// =================================================================================
#define PK_NX 16384
#define PK_NW 4096

__global__ void __launch_bounds__(256, 1)
prep_kernel(const float* __restrict__ x,  const float* __restrict__ w1,
            const float* __restrict__ wg, const float* __restrict__ w2) {
    const int tid = threadIdx.x;
    int b = blockIdx.x;

    if (b == 0 && tid == 0) { g_ctr1 = 0; g_ctr2 = 0; }

    if (b < PK_NX) {                                   // ---- pack x ----
        size_t idx = ((size_t)b * 256 + tid) * 4;
        float4 v = *reinterpret_cast<const float4*>(x + idx);
        int d = (int)(idx & (DD - 1));
        int t = (int)((idx / DD) & (TT - 1));
        int e = (int)(idx / ((size_t)TT * DD));
        int mt = t >> 7, r = t & 127, bd = d >> 6, c = d & 63;
        char* blk = (char*)(g_A1p + (((size_t)(e * 16 + mt) * 16 + bd) << 13));
        uint2 u;
        u.x = h2u(__floats2half2_rn(v.x, v.y));
        u.y = h2u(__floats2half2_rn(v.z, v.w));
        *reinterpret_cast<uint2*>(blk + swz128((uint32_t)(r * 128 + c * 2))) = u;
        return;
    }

    b -= PK_NX;
    const float* in; __half* out; int R, C;
    if (b < PK_NW)            { in = w1; out = g_B1p; R = DD; C = HH; }
    else if (b < 2 * PK_NW)   { b -= PK_NW;     in = wg; out = g_Bgp; R = DD; C = HH; }
    else                      { b -= 2 * PK_NW; in = w2; out = g_B2p; R = HH; C = DD; }

    const int NTc = C >> 7, NKB = R >> 6;
    const int nt = b % NTc;
    const int kb = (b / NTc) % NKB;
    const int e  = b / (NTc * NKB);

    __shared__ __half tsm[128 * 66];
    const float* ip = in + (size_t)e * R * C + (size_t)(kb * 64) * C + nt * 128;

    const int warp = tid >> 5, cl = tid & 31;
#pragma unroll
    for (int it = 0; it < 4; it++) {
        int kr = (warp + 8 * it) * 2;
        float4 v0 = *reinterpret_cast<const float4*>(ip + (size_t)kr * C + 4 * cl);
        float4 v1 = *reinterpret_cast<const float4*>(ip + (size_t)(kr + 1) * C + 4 * cl);
        const float* f0 = &v0.x;
        const float* f1 = &v1.x;
#pragma unroll
        for (int j = 0; j < 4; j++) {
            __half2 h = __floats2half2_rn(f0[j], f1[j]);
            *reinterpret_cast<__half2*>(&tsm[(4 * cl + j) * 66 + kr]) = h;
        }
    }
    __syncthreads();

    char* bp = (char*)(out + (((size_t)(e * NTc + nt) * NKB + kb) << 13));
    const int kc = tid & 7, nlb = tid >> 3;
#pragma unroll
    for (int it = 0; it < 4; it++) {
        int nl = nlb + 32 * it;
        const uint32_t* rowp = reinterpret_cast<const uint32_t*>(&tsm[nl * 66 + kc * 8]);
        uint4 u;
        u.x = rowp[0]; u.y = rowp[1]; u.z = rowp[2]; u.w = rowp[3];
        *reinterpret_cast<uint4*>(bp + swz128((uint32_t)(nl * 128 + kc * 16))) = u;
    }
}

// =================================================================================
// GEMM1 fused (persistent + dynamic tiles + split barriers + PROXY-FENCED release)
// CTA 128x128 dual-plane, 256 thr, f16 m16n8k16, Kc=128, 2-stage ring (96KB/stage).
// mbars: full[2] @ sb+0,8 (count 1); empty[2] @ sb+16,24 (count 256).
// Consumer release: fence.proxy.async BEFORE empty-arrive (orders generic ldmatrix
// reads ahead of the next async-proxy TMA overwrite of the buffer).
// =================================================================================
#define G1_STG_B 98304
#define G1_SMEM (1024 + 2 * G1_STG_B)
#define NT1 (EE * 16 * 32)

__global__ void __launch_bounds__(256, 1)
gemm1_kernel(const float* __restrict__ bias1, const float* __restrict__ biasg) {
    extern __shared__ float sm[];
    __shared__ int sm_next;
    const uint32_t sb = smem_u32(sm);
    const int tid = threadIdx.x, wid = tid >> 5, lane = tid & 31;
    const int gid = lane >> 2, tig = lane & 3;
    const int wr = wid >> 2, wc = wid & 3;

    const int mq = lane >> 3, lr = lane & 7;
    const int rA = (mq & 1) * 8 + lr,  cA = (mq >> 1) * 16;
    const int rB = (mq >> 1) * 8 + lr, cB = (mq & 1) * 16;

    float ah[4][4][4] = {}, ag[4][4][4] = {};

    auto fill = [&](int tile_, int stg, int fb) {
        const int e = tile_ >> 9, nt = (tile_ >> 4) & 31, mtt = tile_ & 15;
        const __half* aS  = g_A1p + (((size_t)(e * 16 + mtt) * 16 + 2 * stg) << 13);
        const __half* b1S = g_B1p + (((size_t)(e * 32 + nt) * 16 + 2 * stg) << 13);
        const __half* bgS = g_Bgp + (((size_t)(e * 32 + nt) * 16 + 2 * stg) << 13);
        const uint32_t mb = sb + (uint32_t)fb * 8;
        const uint32_t dst = sb + 1024 + (uint32_t)fb * G1_STG_B;
        mbar_expect_tx(mb, G1_STG_B);
        bulk_g2s(dst,          aS,  32768, mb);
        bulk_g2s(dst + 32768,  b1S, 32768, mb);
        bulk_g2s(dst + 65536,  bgS, 32768, mb);
    };

    if (tid == 0) {
        mbar_init(sb, 1);       mbar_init(sb + 8, 1);
        mbar_init(sb + 16, 256); mbar_init(sb + 24, 256);
        sm_next = atomicAdd(&g_ctr1, 1);
        FENCE_ASYNC();
    }
    __syncthreads();
    int tile = sm_next;
    __syncthreads();                                  // all read before tid0 rewrites

    int pnext = NT1;                                  // producer-only state (tid0)
    if (tid == 0 && tile < NT1) {
        mbar_wait(sb + 16, 1);                        // fresh: passes
        fill(tile, 0, 0);
    }

    int gs = 0;
#pragma unroll 1
    while (tile < NT1) {
#pragma unroll 1
        for (int s = 0; s < 8; s++, gs++) {
            if (tid == 0) {
                if (s == 0) { pnext = atomicAdd(&g_ctr1, 1); sm_next = pnext; }
                int ft = (s == 7) ? pnext : tile;
                if (ft < NT1) {
                    int fgs = gs + 1, fb = fgs & 1;
                    mbar_wait(sb + 16 + (uint32_t)fb * 8, ((fgs >> 1) & 1) ^ 1);
                    fill(ft, (s + 1) & 7, fb);
                }
            }
            const int cbuf = gs & 1;
            mbar_wait(sb + (uint32_t)cbuf * 8, (gs >> 1) & 1);

            const uint32_t dA  = sb + 1024 + (uint32_t)cbuf * G1_STG_B;
            const uint32_t dB1 = dA + 32768;
            const uint32_t dB2 = dA + 65536;

            uint32_t af[2][4][4], bf1[2][4][2], bf2[2][4][2];

            auto ldfr = [&](int ks, int pb) {
                const int kk = ks & 3;
                const uint32_t blk = (uint32_t)(ks >> 2) * 16384;
#pragma unroll
                for (int i = 0; i < 4; i++) {
                    int row = wr * 64 + i * 16 + rA;
                    uint32_t ad = dA + blk + (uint32_t)row * 128
                                + (uint32_t)((kk * 32 + cA) ^ ((row & 7) << 4));
                    ldm_x4(af[pb][i], ad);
                }
#pragma unroll
                for (int jp = 0; jp < 2; jp++) {
                    int n = wc * 32 + jp * 16 + rB;
                    uint32_t off = blk + (uint32_t)n * 128
                                 + (uint32_t)((kk * 32 + cB) ^ ((n & 7) << 4));
                    ldm_x4(&bf1[pb][jp * 2][0], dB1 + off);
                    ldm_x4(&bf2[pb][jp * 2][0], dB2 + off);
                }
            };

            ldfr(0, 0);
#pragma unroll
            for (int ks = 0; ks < 8; ks++) {
                const int cur = ks & 1;
                if (ks < 7) ldfr(ks + 1, cur ^ 1);
#pragma unroll
                for (int i = 0; i < 4; i++)
#pragma unroll
                    for (int j = 0; j < 4; j++) {
                        mma16(ah[i][j], af[cur][i], bf1[cur][j]);
                        mma16(ag[i][j], af[cur][i], bf2[cur][j]);
                    }
            }
            FENCE_ASYNC();                               // order reads before next TMA
            mbar_arrive(sb + 16 + (uint32_t)cbuf * 8);   // buffer consumed
        }

        // epilogue: og = h16((h+b1)*silu(g+bg)) -> packed half blocks for GEMM2
        const int e = tile >> 9, nt = (tile >> 4) & 31, mtt = tile & 15;
        const float* bp1 = bias1 + (size_t)e * HH + nt * 128;
        const float* bpg = biasg + (size_t)e * HH + nt * 128;
        const int b2 = nt * 2 + (wc >> 1);
        char* blk = (char*)(g_A2p + (((size_t)(e * 16 + mtt) * 64 + b2) << 13));
#pragma unroll
        for (int i = 0; i < 4; i++)
#pragma unroll
            for (int j = 0; j < 4; j++) {
                int cl = wc * 32 + j * 8 + 2 * tig;
                float bh0 = bp1[cl], bh1 = bp1[cl + 1];
                float bg0 = bpg[cl], bg1 = bpg[cl + 1];
                int kh = (wc & 1) * 32 + j * 8 + 2 * tig;
#pragma unroll
                for (int half = 0; half < 2; half++) {
                    int rl = wr * 64 + i * 16 + gid + half * 8;
                    float h0 = ah[i][j][2 * half]     + bh0;
                    float h1 = ah[i][j][2 * half + 1] + bh1;
                    float g0 = ag[i][j][2 * half]     + bg0;
                    float g1 = ag[i][j][2 * half + 1] + bg1;
                    uint32_t u = h2u(__floats2half2_rn(h0 * my_silu(g0), h1 * my_silu(g1)));
                    *reinterpret_cast<uint32_t*>(
                        blk + swz128((uint32_t)(rl * 128 + kh * 2))) = u;
                }
            }
#pragma unroll
        for (int i = 0; i < 4; i++)
#pragma unroll
            for (int j = 0; j < 4; j++)
#pragma unroll
                for (int k2 = 0; k2 < 4; k2++) { ah[i][j][k2] = 0.f; ag[i][j][k2] = 0.f; }

        __syncthreads();
        tile = sm_next;
        __syncthreads();
    }
}

// =================================================================================
// GEMM2 (persistent + dynamic tiles + split barriers + PROXY-FENCED release)
// CTA 128x128, 256 thr, f16 m16n8k16, Kc=64 -> 64 stages/tile, 3-ring, occ 2.
// mbars: full[3] @ sb+0,8,16 (count 1); empty[3] @ sb+24,32,40 (count 256).
// =================================================================================
#define G2_STG_B 32768
#define G2_SMEM (1024 + 3 * G2_STG_B)
#define NT2 (EE * 16 * 8)

__global__ void __launch_bounds__(256, 2)
gemm2_kernel(const float* __restrict__ bias2, float* __restrict__ out) {
    extern __shared__ float sm[];
    __shared__ int sm_next;
    const uint32_t sb = smem_u32(sm);
    const int tid = threadIdx.x, wid = tid >> 5, lane = tid & 31;
    const int gid = lane >> 2, tig = lane & 3;
    const int wr = wid >> 2, wc = wid & 3;

    const int mq = lane >> 3, lr = lane & 7;
    const int rA = (mq & 1) * 8 + lr,  cA = (mq >> 1) * 16;
    const int rB = (mq >> 1) * 8 + lr, cB = (mq & 1) * 16;

    float acc[4][4][4] = {};

    auto fill = [&](int tile_, int stg, int fb) {
        const int e = tile_ >> 7, nt = (tile_ >> 4) & 7, mtt = tile_ & 15;
        const __half* aS = g_A2p + (((size_t)(e * 16 + mtt) * 64 + stg) << 13);
        const __half* bS = g_B2p + (((size_t)(e * 8  + nt) * 64 + stg) << 13);
        const uint32_t mb = sb + (uint32_t)fb * 8;
        const uint32_t dst = sb + 1024 + (uint32_t)fb * G2_STG_B;
        mbar_expect_tx(mb, G2_STG_B);
        bulk_g2s(dst,         aS, 16384, mb);
        bulk_g2s(dst + 16384, bS, 16384, mb);
    };

    if (tid == 0) {
#pragma unroll
        for (int b = 0; b < 3; b++) { mbar_init(sb + b * 8, 1); mbar_init(sb + 24 + b * 8, 256); }
        sm_next = atomicAdd(&g_ctr2, 1);
        FENCE_ASYNC();
    }
    __syncthreads();
    int tile = sm_next;
    __syncthreads();

    int pnext = NT2;
    if (tid == 0 && tile < NT2) {
        mbar_wait(sb + 24, 1); fill(tile, 0, 0);      // fresh: passes
        mbar_wait(sb + 32, 1); fill(tile, 1, 1);
    }

    int gs = 0, cb = 0, cph = 0;
#pragma unroll 1
    while (tile < NT2) {
#pragma unroll 1
        for (int s = 0; s < 64; s++, gs++) {
            if (tid == 0) {
                if (s == 0) { pnext = atomicAdd(&g_ctr2, 1); sm_next = pnext; }
                int fs = s + 2;
                int ft = (fs >= 64) ? pnext : tile;
                if (ft < NT2) {
                    int fgs = gs + 2;
                    int fj = fgs / 3, fb = fgs - 3 * fj;
                    mbar_wait(sb + 24 + (uint32_t)fb * 8, (uint32_t)((fj & 1) ^ 1));
                    fill(ft, fs & 63, fb);
                }
            }
            const int cbuf = cb;
            mbar_wait(sb + (uint32_t)cbuf * 8, (uint32_t)cph);
            if (++cb == 3) { cb = 0; cph ^= 1; }

            const uint32_t dA = sb + 1024 + (uint32_t)cbuf * G2_STG_B;
            const uint32_t dB = dA + 16384;

#pragma unroll
            for (int ks = 0; ks < 4; ks++) {
                uint32_t af[4][4], bf[4][2];
#pragma unroll
                for (int i = 0; i < 4; i++) {
                    int row = wr * 64 + i * 16 + rA;
                    uint32_t ad = dA + (uint32_t)row * 128
                                + (uint32_t)((ks * 32 + cA) ^ ((row & 7) << 4));
                    ldm_x4(af[i], ad);
                }
#pragma unroll
                for (int jp = 0; jp < 2; jp++) {
                    int n = wc * 32 + jp * 16 + rB;
                    uint32_t ad = dB + (uint32_t)n * 128
                                + (uint32_t)((ks * 32 + cB) ^ ((n & 7) << 4));
                    ldm_x4(&bf[jp * 2][0], ad);
                }
#pragma unroll
                for (int i = 0; i < 4; i++)
#pragma unroll
                    for (int j = 0; j < 4; j++)
                        mma16(acc[i][j], af[i], bf[j]);
            }
            FENCE_ASYNC();                               // order reads before next TMA
            mbar_arrive(sb + 24 + (uint32_t)cbuf * 8);
        }

        const int e = tile >> 7, nt = (tile >> 4) & 7, mtt = tile & 15;
        const int m0 = mtt * 128 + wr * 64;
        const int n0 = nt * 128 + wc * 32;
        const float* bp2 = bias2 + (size_t)e * DD;
#pragma unroll
        for (int i = 0; i < 4; i++)
#pragma unroll
            for (int j = 0; j < 4; j++) {
                int col = n0 + j * 8 + 2 * tig;
                float b0 = bp2[col], b1 = bp2[col + 1];
#pragma unroll
                for (int half = 0; half < 2; half++) {
                    int row = m0 + i * 16 + gid + half * 8;
                    float2 v = make_float2(acc[i][j][2 * half] + b0, acc[i][j][2 * half + 1] + b1);
                    *reinterpret_cast<float2*>(out + ((size_t)e * TT + row) * DD + col) = v;
                }
            }
#pragma unroll
        for (int i = 0; i < 4; i++)
#pragma unroll
            for (int j = 0; j < 4; j++)
#pragma unroll
                for (int k2 = 0; k2 < 4; k2++) acc[i][j][k2] = 0.f;

        __syncthreads();
        tile = sm_next;
        __syncthreads();
    }
}

// ---------------- launch ---------------------------------------------------------
extern "C" void kernel_launch(void* const* d_in, const int* in_sizes, int n_in,
                              void* d_out, int out_size) {
    const float* x  = (const float*)d_in[0];
    const float* w1 = (const float*)d_in[1];
    const float* b1 = (const float*)d_in[2];
    const float* wg = (const float*)d_in[3];
    const float* bg = (const float*)d_in[4];
    const float* w2 = (const float*)d_in[5];
    const float* b2 = (const float*)d_in[6];
    float* out = (float*)d_out;

    cudaFuncSetAttribute(gemm1_kernel, cudaFuncAttributeMaxDynamicSharedMemorySize, G1_SMEM);
    cudaFuncSetAttribute(gemm2_kernel, cudaFuncAttributeMaxDynamicSharedMemorySize, G2_SMEM);

    int smc = 0;
    if (cudaDeviceGetAttribute(&smc, cudaDevAttrMultiProcessorCount, 0) != cudaSuccess || smc <= 0)
        smc = 148;

    prep_kernel<<<PK_NX + 3 * PK_NW, 256>>>(x, w1, wg, w2);
    gemm1_kernel<<<smc, 256, G1_SMEM>>>(b1, bg);          // persistent, dynamic tiles
    gemm2_kernel<<<2 * smc, 256, G2_SMEM>>>(b2, out);     // persistent, dynamic tiles
}

// round 14
// speedup vs baseline: 2.6185x; 1.0046x over previous
#include <cuda_runtime.h>
#include <cuda_fp16.h>
#include <cstdint>

#define EE 8
#define TT 2048
#define DD 1024
#define HH 4096

// ---------------- packed half scratch (pre-swizzled 16KB [128 x 64h] blocks) ---
__device__ __align__(1024) __half g_A1p[(size_t)EE * TT * DD];
__device__ __align__(1024) __half g_B1p[(size_t)EE * HH * DD];
__device__ __align__(1024) __half g_Bgp[(size_t)EE * HH * DD];
__device__ __align__(1024) __half g_B2p[(size_t)EE * DD * HH];
__device__ __align__(1024) __half g_A2p[(size_t)EE * TT * HH];

__device__ int g_ctr1, g_ctr2;       // dynamic tile counters (reset by prep_a)

// ---------------- helpers ------------------------------------------------------
__device__ __forceinline__ uint32_t smem_u32(const void* p) {
    uint32_t a;
    asm("{ .reg .u64 t; cvta.to.shared.u64 t, %1; cvt.u32.u64 %0, t; }" : "=r"(a) : "l"(p));
    return a;
}
__device__ __forceinline__ uint32_t swz128(uint32_t o) { return o ^ ((o >> 3) & 0x70); }

__device__ __forceinline__ void mbar_init(uint32_t m, uint32_t c) {
    asm volatile("mbarrier.init.shared.b64 [%0], %1;" :: "r"(m), "r"(c) : "memory");
}
__device__ __forceinline__ void mbar_expect_tx(uint32_t m, uint32_t bytes) {
    asm volatile("mbarrier.arrive.expect_tx.shared.b64 _, [%0], %1;"
                 :: "r"(m), "r"(bytes) : "memory");
}
__device__ __forceinline__ void mbar_arrive(uint32_t m) {
    asm volatile("mbarrier.arrive.shared.b64 _, [%0];" :: "r"(m) : "memory");
}
__device__ __forceinline__ void mbar_wait(uint32_t m, uint32_t parity) {
    asm volatile(
        "{\n\t.reg .pred P;\n"
        "LW_%=:\n\t"
        "mbarrier.try_wait.parity.acquire.cta.shared::cta.b64 P, [%0], %1, 0x989680;\n\t"
        "@P bra.uni LD_%=;\n\t"
        "bra.uni LW_%=;\n"
        "LD_%=:\n\t}"
        :: "r"(m), "r"(parity) : "memory");
}
__device__ __forceinline__ void bulk_g2s(uint32_t dst, const void* src,
                                         uint32_t bytes, uint32_t mbar) {
    asm volatile(
        "cp.async.bulk.shared::cluster.global.mbarrier::complete_tx::bytes "
        "[%0], [%1], %2, [%3];"
        :: "r"(dst), "l"(src), "r"(bytes), "r"(mbar) : "memory");
}
#define FENCE_ASYNC() asm volatile("fence.proxy.async.shared::cta;" ::: "memory")

__device__ __forceinline__ void ldm_x4(uint32_t* r, uint32_t addr) {
    asm volatile("ldmatrix.sync.aligned.m8n8.x4.shared.b16 {%0,%1,%2,%3}, [%4];"
                 : "=r"(r[0]), "=r"(r[1]), "=r"(r[2]), "=r"(r[3]) : "r"(addr));
}
__device__ __forceinline__ void mma16(float* c, const uint32_t* a, const uint32_t* b) {
    asm volatile(
        "mma.sync.aligned.m16n8k16.row.col.f32.f16.f16.f32 "
        "{%0,%1,%2,%3}, {%4,%5,%6,%7}, {%8,%9}, {%0,%1,%2,%3};"
        : "+f"(c[0]), "+f"(c[1]), "+f"(c[2]), "+f"(c[3])
        : "r"(a[0]), "r"(a[1]), "r"(a[2]), "r"(a[3]), "r"(b[0]), "r"(b[1]));
}
__device__ __forceinline__ float my_silu(float g) { return g / (1.0f + __expf(-g)); }
__device__ __forceinline__ uint32_t h2u(__half2 h) { return *reinterpret_cast<uint32_t*>(&h); }

// ---------------- shared transpose tile body ------------------------------------
// input tile: 64 k-rows x 128 n-cols f32 -> one 16KB packed half block.
__device__ __forceinline__ void transpose_tile(const float* __restrict__ in,
                                               __half* __restrict__ out,
                                               int R, int C, int b, int tid,
                                               __half* tsm /* 128*66 halves */) {
    const int NTc = C >> 7, NKB = R >> 6;
    const int nt = b % NTc;
    const int kb = (b / NTc) % NKB;
    const int e  = b / (NTc * NKB);

    const float* ip = in + (size_t)e * R * C + (size_t)(kb * 64) * C + nt * 128;

    const int warp = tid >> 5, cl = tid & 31;
#pragma unroll
    for (int it = 0; it < 4; it++) {
        int kr = (warp + 8 * it) * 2;
        float4 v0 = *reinterpret_cast<const float4*>(ip + (size_t)kr * C + 4 * cl);
        float4 v1 = *reinterpret_cast<const float4*>(ip + (size_t)(kr + 1) * C + 4 * cl);
        const float* f0 = &v0.x;
        const float* f1 = &v1.x;
#pragma unroll
        for (int j = 0; j < 4; j++) {
            __half2 h = __floats2half2_rn(f0[j], f1[j]);
            *reinterpret_cast<__half2*>(&tsm[(4 * cl + j) * 66 + kr]) = h;
        }
    }
    __syncthreads();

    char* bp = (char*)(out + (((size_t)(e * NTc + nt) * NKB + kb) << 13));
    const int kc = tid & 7, nlb = tid >> 3;
#pragma unroll
    for (int it = 0; it < 4; it++) {
        int nl = nlb + 32 * it;
        const uint32_t* rowp = reinterpret_cast<const uint32_t*>(&tsm[nl * 66 + kc * 8]);
        uint4 u;
        u.x = rowp[0]; u.y = rowp[1]; u.z = rowp[2]; u.w = rowp[3];
        *reinterpret_cast<uint4*>(bp + swz128((uint32_t)(nl * 128 + kc * 16))) = u;
    }
}

// =================================================================================
// PREP A (critical path): pack x + transpose w1, wg + counter reset
// =================================================================================
#define PK_NX 16384
#define PK_NW 4096

__global__ void __launch_bounds__(256, 6)
prep_a_kernel(const float* __restrict__ x, const float* __restrict__ w1,
              const float* __restrict__ wg) {
    const int tid = threadIdx.x;
    int b = blockIdx.x;

    if (b == 0 && tid == 0) { g_ctr1 = 0; g_ctr2 = 0; }

    if (b < PK_NX) {                                   // ---- pack x ----
        size_t idx = ((size_t)b * 256 + tid) * 4;
        float4 v = *reinterpret_cast<const float4*>(x + idx);
        int d = (int)(idx & (DD - 1));
        int t = (int)((idx / DD) & (TT - 1));
        int e = (int)(idx / ((size_t)TT * DD));
        int mt = t >> 7, r = t & 127, bd = d >> 6, c = d & 63;
        char* blk = (char*)(g_A1p + (((size_t)(e * 16 + mt) * 16 + bd) << 13));
        uint2 u;
        u.x = h2u(__floats2half2_rn(v.x, v.y));
        u.y = h2u(__floats2half2_rn(v.z, v.w));
        *reinterpret_cast<uint2*>(blk + swz128((uint32_t)(r * 128 + c * 2))) = u;
        return;
    }

    __shared__ __half tsm[128 * 66];
    b -= PK_NX;
    if (b < PK_NW) transpose_tile(w1, g_B1p, DD, HH, b, tid, tsm);
    else           transpose_tile(wg, g_Bgp, DD, HH, b - PK_NW, tid, tsm);
}

// =================================================================================
// PREP B (overlapped with GEMM1): transpose w2
// =================================================================================
__global__ void __launch_bounds__(256, 6)
prep_b_kernel(const float* __restrict__ w2) {
    __shared__ __half tsm[128 * 66];
    transpose_tile(w2, g_B2p, HH, DD, blockIdx.x, threadIdx.x, tsm);
}

// =================================================================================
// GEMM1 fused (persistent + dynamic tiles + split barriers + proxy-fenced release)
// CTA 128x128 dual-plane, 256 thr, f16 m16n8k16, Kc=128, 2-stage ring (96KB/stage).
// =================================================================================
#define G1_STG_B 98304
#define G1_SMEM (1024 + 2 * G1_STG_B)
#define NT1 (EE * 16 * 32)

__global__ void __launch_bounds__(256, 1)
gemm1_kernel(const float* __restrict__ bias1, const float* __restrict__ biasg) {
    extern __shared__ float sm[];
    __shared__ int sm_next;
    const uint32_t sb = smem_u32(sm);
    const int tid = threadIdx.x, wid = tid >> 5, lane = tid & 31;
    const int gid = lane >> 2, tig = lane & 3;
    const int wr = wid >> 2, wc = wid & 3;

    const int mq = lane >> 3, lr = lane & 7;
    const int rA = (mq & 1) * 8 + lr,  cA = (mq >> 1) * 16;
    const int rB = (mq >> 1) * 8 + lr, cB = (mq & 1) * 16;

    float ah[4][4][4] = {}, ag[4][4][4] = {};

    auto fill = [&](int tile_, int stg, int fb) {
        const int e = tile_ >> 9, nt = (tile_ >> 4) & 31, mtt = tile_ & 15;
        const __half* aS  = g_A1p + (((size_t)(e * 16 + mtt) * 16 + 2 * stg) << 13);
        const __half* b1S = g_B1p + (((size_t)(e * 32 + nt) * 16 + 2 * stg) << 13);
        const __half* bgS = g_Bgp + (((size_t)(e * 32 + nt) * 16 + 2 * stg) << 13);
        const uint32_t mb = sb + (uint32_t)fb * 8;
        const uint32_t dst = sb + 1024 + (uint32_t)fb * G1_STG_B;
        mbar_expect_tx(mb, G1_STG_B);
        bulk_g2s(dst,          aS,  32768, mb);
        bulk_g2s(dst + 32768,  b1S, 32768, mb);
        bulk_g2s(dst + 65536,  bgS, 32768, mb);
    };

    if (tid == 0) {
        mbar_init(sb, 1);       mbar_init(sb + 8, 1);
        mbar_init(sb + 16, 256); mbar_init(sb + 24, 256);
        sm_next = atomicAdd(&g_ctr1, 1);
        FENCE_ASYNC();
    }
    __syncthreads();
    int tile = sm_next;
    __syncthreads();                                  // all read before tid0 rewrites

    int pnext = NT1;                                  // producer-only state (tid0)
    if (tid == 0 && tile < NT1) {
        mbar_wait(sb + 16, 1);                        // fresh: passes
        fill(tile, 0, 0);
    }

    int gs = 0;
#pragma unroll 1
    while (tile < NT1) {
#pragma unroll 1
        for (int s = 0; s < 8; s++, gs++) {
            if (tid == 0) {
                if (s == 0) { pnext = atomicAdd(&g_ctr1, 1); sm_next = pnext; }
                int ft = (s == 7) ? pnext : tile;
                if (ft < NT1) {
                    int fgs = gs + 1, fb = fgs & 1;
                    mbar_wait(sb + 16 + (uint32_t)fb * 8, ((fgs >> 1) & 1) ^ 1);
                    fill(ft, (s + 1) & 7, fb);
                }
            }
            const int cbuf = gs & 1;
            mbar_wait(sb + (uint32_t)cbuf * 8, (gs >> 1) & 1);

            const uint32_t dA  = sb + 1024 + (uint32_t)cbuf * G1_STG_B;
            const uint32_t dB1 = dA + 32768;
            const uint32_t dB2 = dA + 65536;

            uint32_t af[2][4][4], bf1[2][4][2], bf2[2][4][2];

            auto ldfr = [&](int ks, int pb) {
                const int kk = ks & 3;
                const uint32_t blk = (uint32_t)(ks >> 2) * 16384;
#pragma unroll
                for (int i = 0; i < 4; i++) {
                    int row = wr * 64 + i * 16 + rA;
                    uint32_t ad = dA + blk + (uint32_t)row * 128
                                + (uint32_t)((kk * 32 + cA) ^ ((row & 7) << 4));
                    ldm_x4(af[pb][i], ad);
                }
#pragma unroll
                for (int jp = 0; jp < 2; jp++) {
                    int n = wc * 32 + jp * 16 + rB;
                    uint32_t off = blk + (uint32_t)n * 128
                                 + (uint32_t)((kk * 32 + cB) ^ ((n & 7) << 4));
                    ldm_x4(&bf1[pb][jp * 2][0], dB1 + off);
                    ldm_x4(&bf2[pb][jp * 2][0], dB2 + off);
                }
            };

            ldfr(0, 0);
#pragma unroll
            for (int ks = 0; ks < 8; ks++) {
                const int cur = ks & 1;
                if (ks < 7) ldfr(ks + 1, cur ^ 1);
#pragma unroll
                for (int i = 0; i < 4; i++)
#pragma unroll
                    for (int j = 0; j < 4; j++) {
                        mma16(ah[i][j], af[cur][i], bf1[cur][j]);
                        mma16(ag[i][j], af[cur][i], bf2[cur][j]);
                    }
            }
            FENCE_ASYNC();                               // order reads before next TMA
            mbar_arrive(sb + 16 + (uint32_t)cbuf * 8);   // buffer consumed
        }

        // epilogue: og = h16((h+b1)*silu(g+bg)) -> packed half blocks for GEMM2
        const int e = tile >> 9, nt = (tile >> 4) & 31, mtt = tile & 15;
        const float* bp1 = bias1 + (size_t)e * HH + nt * 128;
        const float* bpg = biasg + (size_t)e * HH + nt * 128;
        const int b2 = nt * 2 + (wc >> 1);
        char* blk = (char*)(g_A2p + (((size_t)(e * 16 + mtt) * 64 + b2) << 13));
#pragma unroll
        for (int i = 0; i < 4; i++)
#pragma unroll
            for (int j = 0; j < 4; j++) {
                int cl = wc * 32 + j * 8 + 2 * tig;
                float bh0 = bp1[cl], bh1 = bp1[cl + 1];
                float bg0 = bpg[cl], bg1 = bpg[cl + 1];
                int kh = (wc & 1) * 32 + j * 8 + 2 * tig;
#pragma unroll
                for (int half = 0; half < 2; half++) {
                    int rl = wr * 64 + i * 16 + gid + half * 8;
                    float h0 = ah[i][j][2 * half]     + bh0;
                    float h1 = ah[i][j][2 * half + 1] + bh1;
                    float g0 = ag[i][j][2 * half]     + bg0;
                    float g1 = ag[i][j][2 * half + 1] + bg1;
                    uint32_t u = h2u(__floats2half2_rn(h0 * my_silu(g0), h1 * my_silu(g1)));
                    *reinterpret_cast<uint32_t*>(
                        blk + swz128((uint32_t)(rl * 128 + kh * 2))) = u;
                }
            }
#pragma unroll
        for (int i = 0; i < 4; i++)
#pragma unroll
            for (int j = 0; j < 4; j++)
#pragma unroll
                for (int k2 = 0; k2 < 4; k2++) { ah[i][j][k2] = 0.f; ag[i][j][k2] = 0.f; }

        __syncthreads();
        tile = sm_next;
        __syncthreads();
    }
}

// =================================================================================
// GEMM2 (persistent + dynamic tiles + split barriers + proxy-fenced release)
// CTA 128x128, 256 thr, f16 m16n8k16, Kc=64 -> 64 stages/tile, 3-ring, occ 2.
// =================================================================================
#define G2_STG_B 32768
#define G2_SMEM (1024 + 3 * G2_STG_B)
#define NT2 (EE * 16 * 8)

__global__ void __launch_bounds__(256, 2)
gemm2_kernel(const float* __restrict__ bias2, float* __restrict__ out) {
    extern __shared__ float sm[];
    __shared__ int sm_next;
    const uint32_t sb = smem_u32(sm);
    const int tid = threadIdx.x, wid = tid >> 5, lane = tid & 31;
    const int gid = lane >> 2, tig = lane & 3;
    const int wr = wid >> 2, wc = wid & 3;

    const int mq = lane >> 3, lr = lane & 7;
    const int rA = (mq & 1) * 8 + lr,  cA = (mq >> 1) * 16;
    const int rB = (mq >> 1) * 8 + lr, cB = (mq & 1) * 16;

    float acc[4][4][4] = {};

    auto fill = [&](int tile_, int stg, int fb) {
        const int e = tile_ >> 7, nt = (tile_ >> 4) & 7, mtt = tile_ & 15;
        const __half* aS = g_A2p + (((size_t)(e * 16 + mtt) * 64 + stg) << 13);
        const __half* bS = g_B2p + (((size_t)(e * 8  + nt) * 64 + stg) << 13);
        const uint32_t mb = sb + (uint32_t)fb * 8;
        const uint32_t dst = sb + 1024 + (uint32_t)fb * G2_STG_B;
        mbar_expect_tx(mb, G2_STG_B);
        bulk_g2s(dst,         aS, 16384, mb);
        bulk_g2s(dst + 16384, bS, 16384, mb);
    };

    if (tid == 0) {
#pragma unroll
        for (int b = 0; b < 3; b++) { mbar_init(sb + b * 8, 1); mbar_init(sb + 24 + b * 8, 256); }
        sm_next = atomicAdd(&g_ctr2, 1);
        FENCE_ASYNC();
    }
    __syncthreads();
    int tile = sm_next;
    __syncthreads();

    int pnext = NT2;
    if (tid == 0 && tile < NT2) {
        mbar_wait(sb + 24, 1); fill(tile, 0, 0);      // fresh: passes
        mbar_wait(sb + 32, 1); fill(tile, 1, 1);
    }

    int gs = 0, cb = 0, cph = 0;
#pragma unroll 1
    while (tile < NT2) {
#pragma unroll 1
        for (int s = 0; s < 64; s++, gs++) {
            if (tid == 0) {
                if (s == 0) { pnext = atomicAdd(&g_ctr2, 1); sm_next = pnext; }
                int fs = s + 2;
                int ft = (fs >= 64) ? pnext : tile;
                if (ft < NT2) {
                    int fgs = gs + 2;
                    int fj = fgs / 3, fb = fgs - 3 * fj;
                    mbar_wait(sb + 24 + (uint32_t)fb * 8, (uint32_t)((fj & 1) ^ 1));
                    fill(ft, fs & 63, fb);
                }
            }
            const int cbuf = cb;
            mbar_wait(sb + (uint32_t)cbuf * 8, (uint32_t)cph);
            if (++cb == 3) { cb = 0; cph ^= 1; }

            const uint32_t dA = sb + 1024 + (uint32_t)cbuf * G2_STG_B;
            const uint32_t dB = dA + 16384;

#pragma unroll
            for (int ks = 0; ks < 4; ks++) {
                uint32_t af[4][4], bf[4][2];
#pragma unroll
                for (int i = 0; i < 4; i++) {
                    int row = wr * 64 + i * 16 + rA;
                    uint32_t ad = dA + (uint32_t)row * 128
                                + (uint32_t)((ks * 32 + cA) ^ ((row & 7) << 4));
                    ldm_x4(af[i], ad);
                }
#pragma unroll
                for (int jp = 0; jp < 2; jp++) {
                    int n = wc * 32 + jp * 16 + rB;
                    uint32_t ad = dB + (uint32_t)n * 128
                                + (uint32_t)((ks * 32 + cB) ^ ((n & 7) << 4));
                    ldm_x4(&bf[jp * 2][0], ad);
                }
#pragma unroll
                for (int i = 0; i < 4; i++)
#pragma unroll
                    for (int j = 0; j < 4; j++)
                        mma16(acc[i][j], af[i], bf[j]);
            }
            FENCE_ASYNC();                               // order reads before next TMA
            mbar_arrive(sb + 24 + (uint32_t)cbuf * 8);
        }

        const int e = tile >> 7, nt = (tile >> 4) & 7, mtt = tile & 15;
        const int m0 = mtt * 128 + wr * 64;
        const int n0 = nt * 128 + wc * 32;
        const float* bp2 = bias2 + (size_t)e * DD;
#pragma unroll
        for (int i = 0; i < 4; i++)
#pragma unroll
            for (int j = 0; j < 4; j++) {
                int col = n0 + j * 8 + 2 * tig;
                float b0 = bp2[col], b1 = bp2[col + 1];
#pragma unroll
                for (int half = 0; half < 2; half++) {
                    int row = m0 + i * 16 + gid + half * 8;
                    float2 v = make_float2(acc[i][j][2 * half] + b0, acc[i][j][2 * half + 1] + b1);
                    *reinterpret_cast<float2*>(out + ((size_t)e * TT + row) * DD + col) = v;
                }
            }
#pragma unroll
        for (int i = 0; i < 4; i++)
#pragma unroll
            for (int j = 0; j < 4; j++)
#pragma unroll
                for (int k2 = 0; k2 < 4; k2++) acc[i][j][k2] = 0.f;

        __syncthreads();
        tile = sm_next;
        __syncthreads();
    }
}

// ---------------- launch ---------------------------------------------------------
extern "C" void kernel_launch(void* const* d_in, const int* in_sizes, int n_in,
                              void* d_out, int out_size) {
    const float* x  = (const float*)d_in[0];
    const float* w1 = (const float*)d_in[1];
    const float* b1 = (const float*)d_in[2];
    const float* wg = (const float*)d_in[3];
    const float* bg = (const float*)d_in[4];
    const float* w2 = (const float*)d_in[5];
    const float* b2 = (const float*)d_in[6];
    float* out = (float*)d_out;

    cudaFuncSetAttribute(gemm1_kernel, cudaFuncAttributeMaxDynamicSharedMemorySize, G1_SMEM);
    cudaFuncSetAttribute(gemm2_kernel, cudaFuncAttributeMaxDynamicSharedMemorySize, G2_SMEM);

    int smc = 0;
    if (cudaDeviceGetAttribute(&smc, cudaDevAttrMultiProcessorCount, 0) != cudaSuccess || smc <= 0)
        smc = 148;

    // side stream + fork/join events (host resources, created once on the
    // first — non-captured — call; capture-legal cross-stream dependency pattern)
    static cudaStream_t s_side = nullptr;
    static cudaEvent_t ev_fork = nullptr, ev_join = nullptr;
    if (s_side == nullptr) {
        cudaStreamCreateWithFlags(&s_side, cudaStreamNonBlocking);
        cudaEventCreateWithFlags(&ev_fork, cudaEventDisableTiming);
        cudaEventCreateWithFlags(&ev_join, cudaEventDisableTiming);
    }

    // critical path: pack x + transpose w1/wg
    prep_a_kernel<<<PK_NX + 2 * PK_NW, 256>>>(x, w1, wg);

    // fork: w2 transpose runs on the side stream, overlapped with GEMM1
    cudaEventRecord(ev_fork, 0);
    cudaStreamWaitEvent(s_side, ev_fork, 0);
    prep_b_kernel<<<PK_NW, 256, 0, s_side>>>(w2);

    gemm1_kernel<<<smc, 256, G1_SMEM>>>(b1, bg);          // persistent, dynamic tiles

    // join: GEMM2 needs both og (stream 0) and w2^T (side stream)
    cudaEventRecord(ev_join, s_side);
    cudaStreamWaitEvent(0, ev_join, 0);
    gemm2_kernel<<<2 * smc, 256, G2_SMEM>>>(b2, out);     // persistent, dynamic tiles
}